// round 8
// baseline (speedup 1.0000x reference)
#include <cuda_runtime.h>
#include <math.h>
#include <stdint.h>

// ---------------------------------------------------------------------------
// Problem constants
// ---------------------------------------------------------------------------
#define Bq   8
#define Tq   1024
#define Dm   1024
#define Hh   16
#define Ll   8
#define Vv   8192
#define HD   64
#define BT   (Bq*Tq)
#define DD   (Dm*Dm)

// element offsets into weight slice arrays (int8, same layout as f32 weights)
#define OFF_WQ  0L
#define OFF_WK  (8L*DD)
#define OFF_WV  (16L*DD)
#define OFF_WO  (24L*DD)
#define OFF_W1  (32L*DD)
#define OFF_W2  (48L*DD)
#define OFF_HW  (64L*DD)
#define WTOT    (72L*DD)
// scale row offsets
#define SROW_WQ 0
#define SROW_WK 8192
#define SROW_WV 16384
#define SROW_WO 24576
#define SROW_W1 32768
#define SROW_W2 49152
#define SROW_HW 57344
#define SROWS   65536

// ---------------------------------------------------------------------------
// Scratch (static device globals)
// ---------------------------------------------------------------------------
__device__ float  g_x[BT * Dm];          // residual stream (f32)
__device__ float  g_qkv[3L * BT * Dm];   // q | k | v (f32)
__device__ float  g_f[BT * 2 * Dm];      // f32 scratch (attn out / gelu out)
__device__ int8_t g_a0[BT * 2 * Dm];     // activation hi slice
__device__ int8_t g_a1[BT * 2 * Dm];     // activation lo slice
__device__ float  g_as[BT];              // activation row scales
__device__ int8_t g_w0[WTOT];            // weight hi slice
__device__ int8_t g_w1[WTOT];            // weight lo slice
__device__ float  g_ws[SROWS];           // weight row scales

// ---------------------------------------------------------------------------
// Helpers
// ---------------------------------------------------------------------------
__device__ __forceinline__ uint32_t smem_u32(const void* p) {
    uint32_t a;
    asm("{ .reg .u64 t; cvta.to.shared.u64 t, %1; cvt.u32.u64 %0, t; }"
        : "=r"(a) : "l"(p));
    return a;
}
__device__ __forceinline__ void cpa16(uint32_t dst, const void* src) {
    asm volatile("cp.async.cg.shared.global [%0], [%1], 16;" :: "r"(dst), "l"(src));
}
__device__ __forceinline__ void ldm_x4(uint32_t& r0, uint32_t& r1,
                                       uint32_t& r2, uint32_t& r3, uint32_t addr) {
    asm volatile("ldmatrix.sync.aligned.m8n8.x4.shared.b16 {%0,%1,%2,%3}, [%4];"
                 : "=r"(r0), "=r"(r1), "=r"(r2), "=r"(r3) : "r"(addr));
}
// int8 IMMA: m16n8k32 s8*s8 -> s32, exact accumulation
__device__ __forceinline__ void imma(int* d,
                                     uint32_t a0, uint32_t a1, uint32_t a2, uint32_t a3,
                                     uint32_t b0, uint32_t b1) {
    asm volatile(
        "mma.sync.aligned.m16n8k32.row.col.s32.s8.s8.s32 "
        "{%0,%1,%2,%3}, {%4,%5,%6,%7}, {%8,%9}, {%0,%1,%2,%3};"
        : "+r"(d[0]), "+r"(d[1]), "+r"(d[2]), "+r"(d[3])
        : "r"(a0), "r"(a1), "r"(a2), "r"(a3), "r"(b0), "r"(b1));
}
// split q (|q| <= 16320) into hi/lo int8: q ~= 128*h + l
__device__ __forceinline__ void q2(float q, int& h, int& l) {
    float a0f = rintf(q * 0.0078125f);                 // /128
    a0f = fminf(fmaxf(a0f, -127.f), 127.f);
    float a1f = rintf(q - 128.f * a0f);
    a1f = fminf(fmaxf(a1f, -128.f), 127.f);
    h = (int)a0f; l = (int)a1f;
}

// ---------------------------------------------------------------------------
// Row quantizer: X[row][0..W) f32 -> hi/lo int8 slices + per-row scale.
// Used for weights (once) and activations (per layer). One block per row.
// ---------------------------------------------------------------------------
__global__ __launch_bounds__(256) void quant_rows(
    const float* __restrict__ X, int W,
    int8_t* __restrict__ A0, int8_t* __restrict__ A1, float* __restrict__ S)
{
    long row = blockIdx.x;
    const float* x = X + row * W;
    int tid = threadIdx.x;

    float m = 0.f;
    for (int i = tid * 4; i < W; i += 1024) {
        float4 v = *(const float4*)(x + i);
        m = fmaxf(m, fmaxf(fmaxf(fabsf(v.x), fabsf(v.y)),
                           fmaxf(fabsf(v.z), fabsf(v.w))));
    }
    __shared__ float rm[8];
    __shared__ float rmax_s;
    #pragma unroll
    for (int o = 16; o; o >>= 1) m = fmaxf(m, __shfl_xor_sync(~0u, m, o));
    if ((tid & 31) == 0) rm[tid >> 5] = m;
    __syncthreads();
    if (tid < 32) {
        float mm = (tid < 8) ? rm[tid] : 0.f;
        #pragma unroll
        for (int o = 4; o; o >>= 1) mm = fmaxf(mm, __shfl_xor_sync(~0u, mm, o));
        if (tid == 0) { rmax_s = mm; S[row] = mm * (1.f / 16320.f); }
    }
    __syncthreads();
    float rmax = rmax_s;
    float inv = rmax > 0.f ? 16320.f / rmax : 0.f;

    for (int i = tid * 4; i < W; i += 1024) {
        float4 v = *(const float4*)(x + i);
        int h0, l0, h1, l1, h2, l2, h3, l3;
        q2(v.x * inv, h0, l0); q2(v.y * inv, h1, l1);
        q2(v.z * inv, h2, l2); q2(v.w * inv, h3, l3);
        *(char4*)(A0 + row * W + i) = make_char4((char)h0, (char)h1, (char)h2, (char)h3);
        *(char4*)(A1 + row * W + i) = make_char4((char)l0, (char)l1, (char)l2, (char)l3);
    }
}

// ---------------------------------------------------------------------------
// Embedding
// ---------------------------------------------------------------------------
__global__ __launch_bounds__(256) void embed_kernel(
    const int* __restrict__ idx, const int* __restrict__ ts,
    const float* __restrict__ tok, const float* __restrict__ pos,
    const float* __restrict__ gpos, float* __restrict__ x)
{
    long i = (long)blockIdx.x * 256 + threadIdx.x;
    int d = (int)(i % Dm);
    long bt = i / Dm;
    int t = (int)(bt % Tq);
    int b = (int)(bt / Tq);
    int tokid = idx[b * Tq + t];
    int tstep = ts[b];
    x[i] = tok[(long)tokid * Dm + d] + gpos[(long)tstep * Dm + d] + pos[(long)t * Dm + d];
}

// ---------------------------------------------------------------------------
// LayerNorm fused with int8 hi/lo quantization (row-local)
// ---------------------------------------------------------------------------
__global__ __launch_bounds__(256) void ln_quant(
    const float* __restrict__ X, const float* __restrict__ w,
    const float* __restrict__ b,
    int8_t* __restrict__ A0, int8_t* __restrict__ A1, float* __restrict__ S)
{
    int row = blockIdx.x;
    const float* x = X + (long)row * Dm;
    int tid = threadIdx.x;

    int i = tid * 4;
    float4 v = *(const float4*)(x + i);
    float s  = v.x + v.y + v.z + v.w;
    float ss = v.x*v.x + v.y*v.y + v.z*v.z + v.w*v.w;

    __shared__ float rs[8], rss[8];
    #pragma unroll
    for (int m = 16; m; m >>= 1) {
        s  += __shfl_xor_sync(0xffffffffu, s,  m);
        ss += __shfl_xor_sync(0xffffffffu, ss, m);
    }
    int wid = tid >> 5, lane = tid & 31;
    if (lane == 0) { rs[wid] = s; rss[wid] = ss; }
    __syncthreads();
    if (wid == 0) {
        s  = (lane < 8) ? rs[lane]  : 0.f;
        ss = (lane < 8) ? rss[lane] : 0.f;
        #pragma unroll
        for (int m = 4; m; m >>= 1) {
            s  += __shfl_xor_sync(0xffffffffu, s,  m);
            ss += __shfl_xor_sync(0xffffffffu, ss, m);
        }
        if (lane == 0) { rs[0] = s; rss[0] = ss; }
    }
    __syncthreads();
    float mean = rs[0] * (1.0f / Dm);
    float var  = rss[0] * (1.0f / Dm) - mean * mean;
    float rstd = rsqrtf(var + 1e-5f);

    float4 wv = *(const float4*)(w + i);
    float4 bv = *(const float4*)(b + i);
    float o0 = (v.x - mean) * rstd * wv.x + bv.x;
    float o1 = (v.y - mean) * rstd * wv.y + bv.y;
    float o2 = (v.z - mean) * rstd * wv.z + bv.z;
    float o3 = (v.w - mean) * rstd * wv.w + bv.w;

    // row max of |o|
    float am = fmaxf(fmaxf(fabsf(o0), fabsf(o1)), fmaxf(fabsf(o2), fabsf(o3)));
    __shared__ float rm[8];
    __shared__ float rmax_s;
    #pragma unroll
    for (int m = 16; m; m >>= 1) am = fmaxf(am, __shfl_xor_sync(~0u, am, m));
    if (lane == 0) rm[wid] = am;
    __syncthreads();
    if (wid == 0) {
        float mm = (lane < 8) ? rm[lane] : 0.f;
        #pragma unroll
        for (int m = 4; m; m >>= 1) mm = fmaxf(mm, __shfl_xor_sync(~0u, mm, m));
        if (lane == 0) { rmax_s = mm; S[row] = mm * (1.f / 16320.f); }
    }
    __syncthreads();
    float rmax = rmax_s;
    float inv = rmax > 0.f ? 16320.f / rmax : 0.f;

    int h0, l0, h1, l1, h2, l2, h3, l3;
    q2(o0 * inv, h0, l0); q2(o1 * inv, h1, l1);
    q2(o2 * inv, h2, l2); q2(o3 * inv, h3, l3);
    long base = (long)row * Dm + i;
    *(char4*)(A0 + base) = make_char4((char)h0, (char)h1, (char)h2, (char)h3);
    *(char4*)(A1 + base) = make_char4((char)l0, (char)l1, (char)l2, (char)l3);
}

// ---------------------------------------------------------------------------
// INT8 IMMA GEMM (2-slice Ozaki split, 3 IMMA terms).
// C[m,n] = sA[m]*sB[n]*(16384*acc_hh + 128*acc_cross) (+bias)(+res | gelu).
// CTA 128x64 (MxN), warp tile 32x32 (8 warps 4m x 2n), k-step 64 int8,
// cp.async double buffer.  smem: 2 stages x (2*A[128x80] + 2*B[64x80]) = 60KB.
// ---------------------------------------------------------------------------
#define EPI_NONE 0
#define EPI_ADD  1
#define EPI_GELU 2
#define EPI_QKV  3

#define PKB   80
#define A_T   (128*PKB)
#define B_T   (64*PKB)
#define STGB  (2*A_T + 2*B_T)
#define GSMEM (2*STGB)

template<int EPI>
__global__ __launch_bounds__(256, 2) void gemm_i8(
    const int8_t* __restrict__ Aa0, const int8_t* __restrict__ Aa1,
    const float* __restrict__ sA,
    const int8_t* __restrict__ Ba0, const int8_t* __restrict__ Ba1,
    const float* __restrict__ sB, long bStride, int sStride,
    const float* __restrict__ b0p, const float* __restrict__ b1p,
    const float* __restrict__ b2p, const float* __restrict__ res,
    float* __restrict__ C, int M, int N, int K)
{
    extern __shared__ __align__(16) char gsm[];
    const uint32_t sbase = smem_u32(gsm);

    const int tid = threadIdx.x, lane = tid & 31, warp = tid >> 5;
    const int g = lane >> 2, t = lane & 3, l7 = lane & 7;
    const int wm = warp >> 1, wn = warp & 1;
    const int m0 = blockIdx.y * 128, n0 = blockIdx.x * 64;

    int ch[2][4][4], cx[2][4][4];
    #pragma unroll
    for (int a = 0; a < 2; a++)
        #pragma unroll
        for (int b = 0; b < 4; b++)
            #pragma unroll
            for (int c = 0; c < 4; c++) { ch[a][b][c] = 0; cx[a][b][c] = 0; }

    const int S = K >> 6;

    auto issue = [&](int k0, int buf) {
        #pragma unroll
        for (int j = 0; j < 6; j++) {
            int c = tid + 256 * j;
            const int8_t* src;
            uint32_t dst;
            if (c < 1024) {
                int sl = c >> 9, r = (c >> 2) & 127, q = c & 3;
                src = (sl ? Aa1 : Aa0) + (long)(m0 + r) * K + k0 + q * 16;
                dst = (uint32_t)(buf * STGB + sl * A_T + r * PKB + q * 16);
            } else {
                int c2 = c - 1024;
                int sl = c2 >> 8, r = (c2 >> 2) & 63, q = c2 & 3;
                long roff;
                if (EPI == EPI_QKV) {
                    int rg = n0 + r;
                    roff = (long)(rg >> 10) * bStride + (long)(rg & 1023) * K;
                } else {
                    roff = (long)(n0 + r) * K;
                }
                src = (sl ? Ba1 : Ba0) + roff + k0 + q * 16;
                dst = (uint32_t)(buf * STGB + 2 * A_T + sl * B_T + r * PKB + q * 16);
            }
            cpa16(sbase + dst, src);
        }
        asm volatile("cp.async.commit_group;" ::: "memory");
    };

    issue(0, 0);

    for (int s = 0; s < S; s++) {
        asm volatile("cp.async.wait_group 0;" ::: "memory");
        __syncthreads();
        if (s + 1 < S) issue((s + 1) << 6, (s + 1) & 1);

        uint32_t sb  = sbase + (uint32_t)((s & 1) * STGB);
        uint32_t A0s = sb, A1s = sb + A_T;
        uint32_t B0s = sb + 2u * A_T, B1s = B0s + B_T;

        #pragma unroll
        for (int kk = 0; kk < 2; kk++) {
            // B fragments: 4 n-frags x 2 slices (b16 view of int8 pairs)
            uint32_t bb0[4][2], bb1[4][2];
            #pragma unroll
            for (int p = 0; p < 2; p++) {
                int row = wn * 32 + p * 16 + l7 + ((lane & 16) >> 1);
                int kc  = kk * 16 + (lane & 8);              // b16 units
                uint32_t off = (uint32_t)(row * PKB + kc * 2);
                ldm_x4(bb0[2*p][0], bb0[2*p][1], bb0[2*p+1][0], bb0[2*p+1][1], B0s + off);
                ldm_x4(bb1[2*p][0], bb1[2*p][1], bb1[2*p+1][0], bb1[2*p+1][1], B1s + off);
            }
            #pragma unroll
            for (int mi = 0; mi < 2; mi++) {
                int row = wm * 32 + mi * 16 + l7 + (lane & 8);
                int kc  = kk * 16 + ((lane & 16) >> 1);
                uint32_t off = (uint32_t)(row * PKB + kc * 2);
                uint32_t a00, a01, a02, a03, a10, a11, a12, a13;
                ldm_x4(a00, a01, a02, a03, A0s + off);
                ldm_x4(a10, a11, a12, a13, A1s + off);
                #pragma unroll
                for (int ni = 0; ni < 4; ni++) {
                    imma(ch[mi][ni], a00, a01, a02, a03, bb0[ni][0], bb0[ni][1]);
                    imma(cx[mi][ni], a00, a01, a02, a03, bb1[ni][0], bb1[ni][1]);
                    imma(cx[mi][ni], a10, a11, a12, a13, bb0[ni][0], bb0[ni][1]);
                }
            }
        }
    }

    // --- epilogue ---
    const float* bias = b0p;
    const float* sBp = sB;
    float* Cd = C;
    int csub = 0, Nw = N;
    if (EPI == EPI_QKV) {
        int sel = n0 >> 10;
        bias = (sel == 0) ? b0p : (sel == 1) ? b1p : b2p;
        Cd = C + (long)sel * BT * Dm;
        sBp = sB + sel * sStride;
        csub = sel << 10;
        Nw = Dm;
    }

    #pragma unroll
    for (int mi = 0; mi < 2; mi++) {
        int r0 = m0 + wm * 32 + mi * 16 + g;
        float sa0 = sA[r0], sa1 = sA[r0 + 8];
        #pragma unroll
        for (int ni = 0; ni < 4; ni++) {
            int cc = n0 + wn * 32 + ni * 8 + 2 * t;
            int ccl = cc - csub;
            float sb0v = sBp[ccl], sb1v = sBp[ccl + 1];
            float b0v = bias ? bias[ccl] : 0.f;
            float b1v = bias ? bias[ccl + 1] : 0.f;
            int* h = ch[mi][ni]; int* xx = cx[mi][ni];
            float v0 = sa0 * sb0v * (16384.f * (float)h[0] + 128.f * (float)xx[0]) + b0v;
            float v1 = sa0 * sb1v * (16384.f * (float)h[1] + 128.f * (float)xx[1]) + b1v;
            float v2 = sa1 * sb0v * (16384.f * (float)h[2] + 128.f * (float)xx[2]) + b0v;
            float v3 = sa1 * sb1v * (16384.f * (float)h[3] + 128.f * (float)xx[3]) + b1v;
            long i0 = (long)r0 * Nw + ccl;
            long i1 = (long)(r0 + 8) * Nw + ccl;
            if (EPI == EPI_ADD) {
                v0 += res[i0]; v1 += res[i0 + 1];
                v2 += res[i1]; v3 += res[i1 + 1];
            }
            if (EPI == EPI_GELU) {
                v0 = 0.5f * v0 * (1.f + erff(v0 * 0.70710678118654752f));
                v1 = 0.5f * v1 * (1.f + erff(v1 * 0.70710678118654752f));
                v2 = 0.5f * v2 * (1.f + erff(v2 * 0.70710678118654752f));
                v3 = 0.5f * v3 * (1.f + erff(v3 * 0.70710678118654752f));
            }
            *(float2*)(Cd + i0) = make_float2(v0, v1);
            *(float2*)(Cd + i1) = make_float2(v2, v3);
        }
    }
}

// ---------------------------------------------------------------------------
// Flash attention (fp32, causal) -> f32 output
// ---------------------------------------------------------------------------
#define APAD 68
#define ATT_SMEM_FLOATS (4 * 64 * APAD)

__global__ __launch_bounds__(256) void attn_kernel(
    const float* __restrict__ Q, const float* __restrict__ K,
    const float* __restrict__ V, float* __restrict__ Y)
{
    extern __shared__ float smem[];
    float (*Qs)[APAD]  = (float (*)[APAD])(smem);
    float (*Kst)[APAD] = (float (*)[APAD])(smem + 64 * APAD);
    float (*Vs)[APAD]  = (float (*)[APAD])(smem + 2 * 64 * APAD);
    float (*Ps)[APAD]  = (float (*)[APAD])(smem + 3 * 64 * APAD);

    const int qt = blockIdx.x, h = blockIdx.y, b = blockIdx.z;
    const int tid = threadIdx.x;
    const int tx = tid & 15;
    const int ty = tid >> 4;

    const long baseq = ((long)(b * Tq + qt * 64)) * Dm + h * HD;

    for (int i = tid; i < 64 * 16; i += 256) {
        int r = i >> 4, c4 = (i & 15) << 2;
        float4 v = *(const float4*)(Q + baseq + (long)r * Dm + c4);
        Qs[r][c4] = v.x; Qs[r][c4 + 1] = v.y; Qs[r][c4 + 2] = v.z; Qs[r][c4 + 3] = v.w;
    }

    float m_i[4], l_i[4], o[4][4];
    #pragma unroll
    for (int i = 0; i < 4; i++) {
        m_i[i] = -1e30f; l_i[i] = 0.f;
        #pragma unroll
        for (int j = 0; j < 4; j++) o[i][j] = 0.f;
    }

    for (int kt = 0; kt <= qt; kt++) {
        const long basek = ((long)(b * Tq + kt * 64)) * Dm + h * HD;
        for (int i = tid; i < 64 * 16; i += 256) {
            int r = i >> 4, c4 = (i & 15) << 2;
            float4 kv = *(const float4*)(K + basek + (long)r * Dm + c4);
            Kst[c4][r] = kv.x; Kst[c4 + 1][r] = kv.y; Kst[c4 + 2][r] = kv.z; Kst[c4 + 3][r] = kv.w;
            float4 vv = *(const float4*)(V + basek + (long)r * Dm + c4);
            Vs[r][c4] = vv.x; Vs[r][c4 + 1] = vv.y; Vs[r][c4 + 2] = vv.z; Vs[r][c4 + 3] = vv.w;
        }
        __syncthreads();

        float s[4][4];
        #pragma unroll
        for (int i = 0; i < 4; i++)
            #pragma unroll
            for (int j = 0; j < 4; j++) s[i][j] = 0.f;

        #pragma unroll 8
        for (int kk = 0; kk < 64; kk++) {
            float a0 = Qs[4 * ty + 0][kk];
            float a1 = Qs[4 * ty + 1][kk];
            float a2 = Qs[4 * ty + 2][kk];
            float a3 = Qs[4 * ty + 3][kk];
            float4 bb = *(const float4*)&Kst[kk][4 * tx];
            s[0][0] = fmaf(a0, bb.x, s[0][0]); s[0][1] = fmaf(a0, bb.y, s[0][1]);
            s[0][2] = fmaf(a0, bb.z, s[0][2]); s[0][3] = fmaf(a0, bb.w, s[0][3]);
            s[1][0] = fmaf(a1, bb.x, s[1][0]); s[1][1] = fmaf(a1, bb.y, s[1][1]);
            s[1][2] = fmaf(a1, bb.z, s[1][2]); s[1][3] = fmaf(a1, bb.w, s[1][3]);
            s[2][0] = fmaf(a2, bb.x, s[2][0]); s[2][1] = fmaf(a2, bb.y, s[2][1]);
            s[2][2] = fmaf(a2, bb.z, s[2][2]); s[2][3] = fmaf(a2, bb.w, s[2][3]);
            s[3][0] = fmaf(a3, bb.x, s[3][0]); s[3][1] = fmaf(a3, bb.y, s[3][1]);
            s[3][2] = fmaf(a3, bb.z, s[3][2]); s[3][3] = fmaf(a3, bb.w, s[3][3]);
        }

        const float scale = 0.125f;
        #pragma unroll
        for (int i = 0; i < 4; i++)
            #pragma unroll
            for (int j = 0; j < 4; j++) s[i][j] *= scale;

        if (kt == qt) {
            #pragma unroll
            for (int i = 0; i < 4; i++)
                #pragma unroll
                for (int j = 0; j < 4; j++)
                    if (4 * tx + j > 4 * ty + i) s[i][j] = -1e30f;
        }

        #pragma unroll
        for (int i = 0; i < 4; i++) {
            float rmax = fmaxf(fmaxf(s[i][0], s[i][1]), fmaxf(s[i][2], s[i][3]));
            #pragma unroll
            for (int m = 8; m; m >>= 1)
                rmax = fmaxf(rmax, __shfl_xor_sync(0xffffffffu, rmax, m));
            float mnew  = fmaxf(m_i[i], rmax);
            float alpha = expf(m_i[i] - mnew);
            m_i[i] = mnew;
            float rsum = 0.f;
            #pragma unroll
            for (int j = 0; j < 4; j++) {
                float p = expf(s[i][j] - mnew);
                s[i][j] = p;
                rsum += p;
            }
            #pragma unroll
            for (int m = 8; m; m >>= 1)
                rsum += __shfl_xor_sync(0xffffffffu, rsum, m);
            l_i[i] = l_i[i] * alpha + rsum;
            #pragma unroll
            for (int j = 0; j < 4; j++) o[i][j] *= alpha;
        }

        #pragma unroll
        for (int i = 0; i < 4; i++)
            #pragma unroll
            for (int j = 0; j < 4; j++)
                Ps[4 * ty + i][4 * tx + j] = s[i][j];
        __syncthreads();

        #pragma unroll 8
        for (int kk = 0; kk < 64; kk++) {
            float a0 = Ps[4 * ty + 0][kk];
            float a1 = Ps[4 * ty + 1][kk];
            float a2 = Ps[4 * ty + 2][kk];
            float a3 = Ps[4 * ty + 3][kk];
            float4 bb = *(const float4*)&Vs[kk][4 * tx];
            o[0][0] = fmaf(a0, bb.x, o[0][0]); o[0][1] = fmaf(a0, bb.y, o[0][1]);
            o[0][2] = fmaf(a0, bb.z, o[0][2]); o[0][3] = fmaf(a0, bb.w, o[0][3]);
            o[1][0] = fmaf(a1, bb.x, o[1][0]); o[1][1] = fmaf(a1, bb.y, o[1][1]);
            o[1][2] = fmaf(a1, bb.z, o[1][2]); o[1][3] = fmaf(a1, bb.w, o[1][3]);
            o[2][0] = fmaf(a2, bb.x, o[2][0]); o[2][1] = fmaf(a2, bb.y, o[2][1]);
            o[2][2] = fmaf(a2, bb.z, o[2][2]); o[2][3] = fmaf(a2, bb.w, o[2][3]);
            o[3][0] = fmaf(a3, bb.x, o[3][0]); o[3][1] = fmaf(a3, bb.y, o[3][1]);
            o[3][2] = fmaf(a3, bb.z, o[3][2]); o[3][3] = fmaf(a3, bb.w, o[3][3]);
        }
        __syncthreads();
    }

    #pragma unroll
    for (int i = 0; i < 4; i++) {
        float inv = 1.f / l_i[i];
        long orow = baseq + (long)(4 * ty + i) * Dm + 4 * tx;
        Y[orow + 0] = o[i][0] * inv;
        Y[orow + 1] = o[i][1] * inv;
        Y[orow + 2] = o[i][2] * inv;
        Y[orow + 3] = o[i][3] * inv;
    }
}

// ---------------------------------------------------------------------------
// Launcher
// ---------------------------------------------------------------------------
extern "C" void kernel_launch(void* const* d_in, const int* in_sizes, int n_in,
                              void* d_out, int out_size)
{
    const int*   idx  = (const int*)  d_in[0];
    const int*   ts   = (const int*)  d_in[1];
    const float* tok  = (const float*)d_in[2];
    const float* pos  = (const float*)d_in[3];
    const float* gpos = (const float*)d_in[4];
    const float* ln1w = (const float*)d_in[5];
    const float* ln1b = (const float*)d_in[6];
    const float* Wq   = (const float*)d_in[7];
    const float* bq   = (const float*)d_in[8];
    const float* Wk   = (const float*)d_in[9];
    const float* bk   = (const float*)d_in[10];
    const float* Wv   = (const float*)d_in[11];
    const float* bv   = (const float*)d_in[12];
    const float* Wo   = (const float*)d_in[13];
    const float* bo   = (const float*)d_in[14];
    const float* ln2w = (const float*)d_in[15];
    const float* ln2b = (const float*)d_in[16];
    const float* W1   = (const float*)d_in[17];
    const float* b1   = (const float*)d_in[18];
    const float* W2   = (const float*)d_in[19];
    const float* b2   = (const float*)d_in[20];
    const float* lnfw = (const float*)d_in[21];
    const float* lnfb = (const float*)d_in[22];
    const float* hw   = (const float*)d_in[23];
    float* out = (float*)d_out;

    float *x, *qkv, *f, *as, *ws;
    int8_t *a0, *a1, *w0, *w1;
    cudaGetSymbolAddress((void**)&x,   g_x);
    cudaGetSymbolAddress((void**)&qkv, g_qkv);
    cudaGetSymbolAddress((void**)&f,   g_f);
    cudaGetSymbolAddress((void**)&a0,  g_a0);
    cudaGetSymbolAddress((void**)&a1,  g_a1);
    cudaGetSymbolAddress((void**)&as,  g_as);
    cudaGetSymbolAddress((void**)&w0,  g_w0);
    cudaGetSymbolAddress((void**)&w1,  g_w1);
    cudaGetSymbolAddress((void**)&ws,  g_ws);

    cudaFuncSetAttribute(attn_kernel, cudaFuncAttributeMaxDynamicSharedMemorySize,
                         ATT_SMEM_FLOATS * (int)sizeof(float));
    cudaFuncSetAttribute(gemm_i8<EPI_NONE>, cudaFuncAttributeMaxDynamicSharedMemorySize, GSMEM);
    cudaFuncSetAttribute(gemm_i8<EPI_ADD>,  cudaFuncAttributeMaxDynamicSharedMemorySize, GSMEM);
    cudaFuncSetAttribute(gemm_i8<EPI_GELU>, cudaFuncAttributeMaxDynamicSharedMemorySize, GSMEM);
    cudaFuncSetAttribute(gemm_i8<EPI_QKV>,  cudaFuncAttributeMaxDynamicSharedMemorySize, GSMEM);

    // weight quantization (once per launch)
    quant_rows<<<8192, 256>>>(Wq, Dm,      w0 + OFF_WQ, w1 + OFF_WQ, ws + SROW_WQ);
    quant_rows<<<8192, 256>>>(Wk, Dm,      w0 + OFF_WK, w1 + OFF_WK, ws + SROW_WK);
    quant_rows<<<8192, 256>>>(Wv, Dm,      w0 + OFF_WV, w1 + OFF_WV, ws + SROW_WV);
    quant_rows<<<8192, 256>>>(Wo, Dm,      w0 + OFF_WO, w1 + OFF_WO, ws + SROW_WO);
    quant_rows<<<16384, 256>>>(W1, Dm,     w0 + OFF_W1, w1 + OFF_W1, ws + SROW_W1);
    quant_rows<<<8192, 256>>>(W2, 2 * Dm,  w0 + OFF_W2, w1 + OFF_W2, ws + SROW_W2);
    quant_rows<<<8192, 256>>>(hw, Dm,      w0 + OFF_HW, w1 + OFF_HW, ws + SROW_HW);

    embed_kernel<<<(BT * Dm) / 256, 256>>>(idx, ts, tok, pos, gpos, x);

    const dim3 gQKV(3 * Dm / 64, BT / 128);   // (48, 64)
    const dim3 gD(Dm / 64, BT / 128);         // (16, 64)
    const dim3 g2D(2 * Dm / 64, BT / 128);    // (32, 64)
    const dim3 gV(Vv / 64, BT / 128);         // (128, 64)

    float* qb = qkv;
    float* kb = qkv + (long)BT * Dm;
    float* vb = qkv + 2L * BT * Dm;

    for (int l = 0; l < Ll; l++) {
        ln_quant<<<BT, 256>>>(x, ln1w + (long)l * Dm, ln1b + (long)l * Dm, a0, a1, as);

        gemm_i8<EPI_QKV><<<gQKV, 256, GSMEM>>>(
            a0, a1, as,
            w0 + OFF_WQ + (long)l * DD, w1 + OFF_WQ + (long)l * DD,
            ws + SROW_WQ + l * Dm, 8L * DD, 8192,
            bq + (long)l * Dm, bk + (long)l * Dm, bv + (long)l * Dm,
            nullptr, qkv, BT, 3 * Dm, Dm);

        attn_kernel<<<dim3(Tq / 64, Hh, Bq), 256,
                      ATT_SMEM_FLOATS * sizeof(float)>>>(qb, kb, vb, f);

        quant_rows<<<BT, 256>>>(f, Dm, a0, a1, as);

        gemm_i8<EPI_ADD><<<gD, 256, GSMEM>>>(
            a0, a1, as,
            w0 + OFF_WO + (long)l * DD, w1 + OFF_WO + (long)l * DD,
            ws + SROW_WO + l * Dm, 0, 0,
            bo + (long)l * Dm, nullptr, nullptr,
            x, x, BT, Dm, Dm);

        ln_quant<<<BT, 256>>>(x, ln2w + (long)l * Dm, ln2b + (long)l * Dm, a0, a1, as);

        gemm_i8<EPI_GELU><<<g2D, 256, GSMEM>>>(
            a0, a1, as,
            w0 + OFF_W1 + (long)l * 2 * DD, w1 + OFF_W1 + (long)l * 2 * DD,
            ws + SROW_W1 + l * 2 * Dm, 0, 0,
            b1 + (long)l * 2 * Dm, nullptr, nullptr,
            nullptr, f, BT, 2 * Dm, Dm);

        quant_rows<<<BT, 256>>>(f, 2 * Dm, a0, a1, as);

        gemm_i8<EPI_ADD><<<gD, 256, GSMEM>>>(
            a0, a1, as,
            w0 + OFF_W2 + (long)l * 2 * DD, w1 + OFF_W2 + (long)l * 2 * DD,
            ws + SROW_W2 + l * Dm, 0, 0,
            b2 + (long)l * Dm, nullptr, nullptr,
            x, x, BT, Dm, 2 * Dm);
    }

    ln_quant<<<BT, 256>>>(x, lnfw, lnfb, a0, a1, as);
    gemm_i8<EPI_NONE><<<gV, 256, GSMEM>>>(
        a0, a1, as,
        w0 + OFF_HW, w1 + OFF_HW, ws + SROW_HW, 0, 0,
        nullptr, nullptr, nullptr,
        nullptr, out, BT, Vv, Dm);
}

// round 9
// speedup vs baseline: 1.9833x; 1.9833x over previous
#include <cuda_runtime.h>
#include <cuda_fp16.h>
#include <math.h>
#include <stdint.h>

// ---------------------------------------------------------------------------
// Problem constants
// ---------------------------------------------------------------------------
#define Bq   8
#define Tq   1024
#define Dm   1024
#define Hh   16
#define Ll   8
#define Vv   8192
#define HD   64
#define BT   (Bq*Tq)

// ---------------------------------------------------------------------------
// Scratch (static device globals)
// ---------------------------------------------------------------------------
__device__ float g_x[BT * Dm];           // residual stream (f32)
__device__ float g_qkv[3L * BT * Dm];    // q | k | v

__device__ __half g_pa_h[BT * Dm];       // pair buf A: LN out / attn out
__device__ __half g_pa_l[BT * Dm];
__device__ __half g_pb_h[BT * 2 * Dm];   // pair buf B: MLP hidden
__device__ __half g_pb_l[BT * 2 * Dm];

#define DD      (Dm*Dm)
#define OFF_WQ  0L
#define OFF_WK  (8L*DD)
#define OFF_WV  (16L*DD)
#define OFF_WO  (24L*DD)
#define OFF_W1  (32L*DD)
#define OFF_W2  (48L*DD)
#define OFF_HW  (64L*DD)
#define WTOT    (72L*DD)
__device__ __half g_wh[WTOT];
__device__ __half g_wl[WTOT];

// ---------------------------------------------------------------------------
// Helpers
// ---------------------------------------------------------------------------
__device__ __forceinline__ uint32_t smem_u32(const void* p) {
    uint32_t a;
    asm("{ .reg .u64 t; cvta.to.shared.u64 t, %1; cvt.u32.u64 %0, t; }"
        : "=r"(a) : "l"(p));
    return a;
}
__device__ __forceinline__ void cpa16(uint32_t dst, const void* src) {
    asm volatile("cp.async.cg.shared.global [%0], [%1], 16;" :: "r"(dst), "l"(src));
}
__device__ __forceinline__ void ldm_x4(uint32_t& r0, uint32_t& r1,
                                       uint32_t& r2, uint32_t& r3, uint32_t addr) {
    asm volatile("ldmatrix.sync.aligned.m8n8.x4.shared.b16 {%0,%1,%2,%3}, [%4];"
                 : "=r"(r0), "=r"(r1), "=r"(r2), "=r"(r3) : "r"(addr));
}
__device__ __forceinline__ void mma_f16(float& d0, float& d1, float& d2, float& d3,
                                        uint32_t a0, uint32_t a1, uint32_t a2, uint32_t a3,
                                        uint32_t b0, uint32_t b1) {
    asm volatile(
        "mma.sync.aligned.m16n8k16.row.col.f32.f16.f16.f32 "
        "{%0,%1,%2,%3}, {%4,%5,%6,%7}, {%8,%9}, {%0,%1,%2,%3};"
        : "+f"(d0), "+f"(d1), "+f"(d2), "+f"(d3)
        : "r"(a0), "r"(a1), "r"(a2), "r"(a3), "r"(b0), "r"(b1));
}
__device__ __forceinline__ void split16(float x, __half& hi, __half& lo) {
    hi = __float2half_rn(x);
    lo = __float2half_rn(x - __half2float(hi));
}

// --- packed f32x2 (sm_100+ baseline PTX feature, SASS FFMA2) ---
__device__ __forceinline__ unsigned long long pack2(float lo, float hi) {
    unsigned long long r;
    asm("mov.b64 %0, {%1, %2};" : "=l"(r) : "f"(lo), "f"(hi));
    return r;
}
__device__ __forceinline__ void unpack2(unsigned long long v, float& lo, float& hi) {
    asm("mov.b64 {%0, %1}, %2;" : "=f"(lo), "=f"(hi) : "l"(v));
}
#define FMA2(d, a, b) \
    asm("fma.rn.f32x2 %0, %1, %2, %0;" : "+l"(d) : "l"(a), "l"(b))
#define MUL2(d, a, b) \
    asm("mul.rn.f32x2 %0, %1, %2;" : "=l"(d) : "l"(a), "l"(b))

// ---------------------------------------------------------------------------
// Weight f32 -> f16 hi/lo pair conversion
// ---------------------------------------------------------------------------
__global__ __launch_bounds__(256) void cvt_pair(
    const float* __restrict__ s, __half* __restrict__ h,
    __half* __restrict__ l, long n)
{
    long i = ((long)blockIdx.x * 256 + threadIdx.x) * 4;
    if (i >= n) return;
    float4 v = *(const float4*)(s + i);
    __half h0, h1, h2, h3, l0, l1, l2, l3;
    split16(v.x, h0, l0); split16(v.y, h1, l1);
    split16(v.z, h2, l2); split16(v.w, h3, l3);
    *(__half2*)(h + i)     = __halves2half2(h0, h1);
    *(__half2*)(h + i + 2) = __halves2half2(h2, h3);
    *(__half2*)(l + i)     = __halves2half2(l0, l1);
    *(__half2*)(l + i + 2) = __halves2half2(l2, l3);
}

// ---------------------------------------------------------------------------
// Embedding
// ---------------------------------------------------------------------------
__global__ __launch_bounds__(256) void embed_kernel(
    const int* __restrict__ idx, const int* __restrict__ ts,
    const float* __restrict__ tok, const float* __restrict__ pos,
    const float* __restrict__ gpos, float* __restrict__ x)
{
    long i = (long)blockIdx.x * 256 + threadIdx.x;
    int d = (int)(i % Dm);
    long bt = i / Dm;
    int t = (int)(bt % Tq);
    int b = (int)(bt / Tq);
    int tokid = idx[b * Tq + t];
    int tstep = ts[b];
    x[i] = tok[(long)tokid * Dm + d] + gpos[(long)tstep * Dm + d] + pos[(long)t * Dm + d];
}

// ---------------------------------------------------------------------------
// LayerNorm -> f16 hi/lo pair output
// ---------------------------------------------------------------------------
__global__ __launch_bounds__(256) void layernorm_pair(
    const float* __restrict__ X, const float* __restrict__ w,
    const float* __restrict__ b, __half* __restrict__ Yh, __half* __restrict__ Yl)
{
    int row = blockIdx.x;
    const float* x = X + (long)row * Dm;
    int tid = threadIdx.x;

    int i = tid * 4;
    float4 v = *(const float4*)(x + i);
    float s  = v.x + v.y + v.z + v.w;
    float ss = v.x*v.x + v.y*v.y + v.z*v.z + v.w*v.w;

    __shared__ float rs[8], rss[8];
    #pragma unroll
    for (int m = 16; m; m >>= 1) {
        s  += __shfl_xor_sync(0xffffffffu, s,  m);
        ss += __shfl_xor_sync(0xffffffffu, ss, m);
    }
    int wid = tid >> 5, lane = tid & 31;
    if (lane == 0) { rs[wid] = s; rss[wid] = ss; }
    __syncthreads();
    if (wid == 0) {
        s  = (lane < 8) ? rs[lane]  : 0.f;
        ss = (lane < 8) ? rss[lane] : 0.f;
        #pragma unroll
        for (int m = 4; m; m >>= 1) {
            s  += __shfl_xor_sync(0xffffffffu, s,  m);
            ss += __shfl_xor_sync(0xffffffffu, ss, m);
        }
        if (lane == 0) { rs[0] = s; rss[0] = ss; }
    }
    __syncthreads();
    float mean = rs[0] * (1.0f / Dm);
    float var  = rss[0] * (1.0f / Dm) - mean * mean;
    float rstd = rsqrtf(var + 1e-5f);

    float4 wv = *(const float4*)(w + i);
    float4 bv = *(const float4*)(b + i);
    float o0 = (v.x - mean) * rstd * wv.x + bv.x;
    float o1 = (v.y - mean) * rstd * wv.y + bv.y;
    float o2 = (v.z - mean) * rstd * wv.z + bv.z;
    float o3 = (v.w - mean) * rstd * wv.w + bv.w;

    long base = (long)row * Dm + i;
    __half h0, h1, h2, h3, l0, l1, l2, l3;
    split16(o0, h0, l0); split16(o1, h1, l1);
    split16(o2, h2, l2); split16(o3, h3, l3);
    *(__half2*)(Yh + base)     = __halves2half2(h0, h1);
    *(__half2*)(Yh + base + 2) = __halves2half2(h2, h3);
    *(__half2*)(Yl + base)     = __halves2half2(l0, l1);
    *(__half2*)(Yl + base + 2) = __halves2half2(l2, l3);
}

// ---------------------------------------------------------------------------
// HMMA GEMM (3x f16 split), ldmatrix fragment loads. (R5 proven version)
// CTA 128x128, k-step 32, cp.async double buffer, 8 warps of 64x32.
// ---------------------------------------------------------------------------
#define EPI_NONE 0
#define EPI_ADD  1
#define EPI_GELU 2
#define EPI_QKV  3

#define PK      40
#define TILE_H  (128*PK)
#define STG_H   (4*TILE_H)
#define GEMM_SMEM (2*STG_H*2)

template<int EPI>
__global__ __launch_bounds__(256, 2) void gemm_hmma(
    const __half* __restrict__ Ah, const __half* __restrict__ Al,
    const __half* __restrict__ Bh, const __half* __restrict__ Bl,
    long bStride,
    const float* __restrict__ b0p, const float* __restrict__ b1p,
    const float* __restrict__ b2p, const float* __restrict__ res,
    float* __restrict__ C, __half* __restrict__ Ch, __half* __restrict__ Cl,
    int M, int N, int K)
{
    extern __shared__ __align__(16) __half gsm[];
    const uint32_t sbase = smem_u32(gsm);

    const int tid = threadIdx.x, lane = tid & 31, warp = tid >> 5;
    const int g = lane >> 2, t = lane & 3, l7 = lane & 7;
    const int wm = warp & 1, wn = warp >> 1;
    const int m0 = blockIdx.y * 128, n0 = blockIdx.x * 128;

    float acc[4][4][4];
    #pragma unroll
    for (int a = 0; a < 4; a++)
        #pragma unroll
        for (int b = 0; b < 4; b++)
            #pragma unroll
            for (int c = 0; c < 4; c++) acc[a][b][c] = 0.f;

    const int S = K >> 5;

    auto issue = [&](int k0, int buf) {
        #pragma unroll
        for (int j = 0; j < 8; j++) {
            int c = tid + 256 * j;
            int tile = c >> 9;
            int r = (c >> 2) & 127;
            int q = c & 3;
            const __half* src;
            if (tile == 0)      src = Ah + (long)(m0 + r) * K + k0 + q * 8;
            else if (tile == 1) src = Al + (long)(m0 + r) * K + k0 + q * 8;
            else {
                long roff;
                if (EPI == EPI_QKV) {
                    int rg = n0 + r;
                    roff = (long)(rg >> 10) * bStride + (long)(rg & 1023) * K;
                } else {
                    roff = (long)(n0 + r) * K;
                }
                src = (tile == 2 ? Bh : Bl) + roff + k0 + q * 8;
            }
            uint32_t dst = sbase + (uint32_t)(buf * STG_H + tile * TILE_H + r * PK + q * 8) * 2u;
            cpa16(dst, src);
        }
        asm volatile("cp.async.commit_group;" ::: "memory");
    };

    issue(0, 0);

    for (int s = 0; s < S; s++) {
        asm volatile("cp.async.wait_group 0;" ::: "memory");
        __syncthreads();
        if (s + 1 < S) issue((s + 1) << 5, (s + 1) & 1);

        uint32_t sb  = sbase + (uint32_t)((s & 1) * STG_H) * 2u;
        uint32_t A_h = sb;
        uint32_t A_l = sb + TILE_H * 2u;
        uint32_t B_h = sb + 2u * TILE_H * 2u;
        uint32_t B_l = sb + 3u * TILE_H * 2u;

        #pragma unroll
        for (int kk = 0; kk < 32; kk += 16) {
            uint32_t bh[4][2], bl[4][2];
            #pragma unroll
            for (int p = 0; p < 2; p++) {
                int row = wn * 32 + p * 16 + l7 + ((lane & 16) >> 1);
                int kc  = kk + (lane & 8);
                uint32_t off = (uint32_t)(row * PK + kc) * 2u;
                ldm_x4(bh[2*p][0], bh[2*p][1], bh[2*p+1][0], bh[2*p+1][1], B_h + off);
                ldm_x4(bl[2*p][0], bl[2*p][1], bl[2*p+1][0], bl[2*p+1][1], B_l + off);
            }
            #pragma unroll
            for (int mi = 0; mi < 4; mi++) {
                int row = wm * 64 + mi * 16 + l7 + (lane & 8);
                int kc  = kk + ((lane & 16) >> 1);
                uint32_t off = (uint32_t)(row * PK + kc) * 2u;
                uint32_t ah0, ah1, ah2, ah3, al0, al1, al2, al3;
                ldm_x4(ah0, ah1, ah2, ah3, A_h + off);
                ldm_x4(al0, al1, al2, al3, A_l + off);
                #pragma unroll
                for (int ni = 0; ni < 4; ni++) {
                    float* d = acc[mi][ni];
                    mma_f16(d[0], d[1], d[2], d[3], ah0, ah1, ah2, ah3, bh[ni][0], bh[ni][1]);
                    mma_f16(d[0], d[1], d[2], d[3], ah0, ah1, ah2, ah3, bl[ni][0], bl[ni][1]);
                    mma_f16(d[0], d[1], d[2], d[3], al0, al1, al2, al3, bh[ni][0], bh[ni][1]);
                }
            }
        }
    }

    // --- epilogue ---
    const float* bias = b0p;
    float* Cd = C;
    int csub = 0, Nw = N;
    if (EPI == EPI_QKV) {
        int sel = n0 >> 10;
        bias = (sel == 0) ? b0p : (sel == 1) ? b1p : b2p;
        Cd = C + (long)sel * BT * Dm;
        csub = sel << 10;
        Nw = Dm;
    }

    #pragma unroll
    for (int mi = 0; mi < 4; mi++) {
        int r0 = m0 + wm * 64 + mi * 16 + g;
        #pragma unroll
        for (int ni = 0; ni < 4; ni++) {
            int cc = n0 + wn * 32 + ni * 8 + 2 * t;
            float b0v = bias ? bias[cc - csub] : 0.f;
            float b1v = bias ? bias[cc - csub + 1] : 0.f;
            float v0 = acc[mi][ni][0] + b0v, v1 = acc[mi][ni][1] + b1v;
            float v2 = acc[mi][ni][2] + b0v, v3 = acc[mi][ni][3] + b1v;
            long i0 = (long)r0 * Nw + (cc - csub);
            long i1 = (long)(r0 + 8) * Nw + (cc - csub);
            if (EPI == EPI_ADD) {
                v0 += res[i0]; v1 += res[i0 + 1];
                v2 += res[i1]; v3 += res[i1 + 1];
            }
            if (EPI == EPI_GELU) {
                v0 = 0.5f * v0 * (1.f + erff(v0 * 0.70710678118654752f));
                v1 = 0.5f * v1 * (1.f + erff(v1 * 0.70710678118654752f));
                v2 = 0.5f * v2 * (1.f + erff(v2 * 0.70710678118654752f));
                v3 = 0.5f * v3 * (1.f + erff(v3 * 0.70710678118654752f));
                __half h0, h1, h2, h3, l0, l1, l2, l3;
                split16(v0, h0, l0); split16(v1, h1, l1);
                split16(v2, h2, l2); split16(v3, h3, l3);
                *(__half2*)(Ch + i0) = __halves2half2(h0, h1);
                *(__half2*)(Ch + i1) = __halves2half2(h2, h3);
                *(__half2*)(Cl + i0) = __halves2half2(l0, l1);
                *(__half2*)(Cl + i1) = __halves2half2(l2, l3);
            } else {
                *(float2*)(Cd + i0) = make_float2(v0, v1);
                *(float2*)(Cd + i1) = make_float2(v2, v3);
            }
        }
    }
}

// ---------------------------------------------------------------------------
// Flash attention (fp32, causal) with packed f32x2 FMA -> f16 hi/lo pairs
// ---------------------------------------------------------------------------
#define APAD 68
#define ATT_SMEM_FLOATS (4 * 64 * APAD)

__global__ __launch_bounds__(256) void attn_kernel(
    const float* __restrict__ Q, const float* __restrict__ K,
    const float* __restrict__ V, __half* __restrict__ Yh, __half* __restrict__ Yl)
{
    extern __shared__ float smem[];
    float (*Qs)[APAD]  = (float (*)[APAD])(smem);
    float (*Kst)[APAD] = (float (*)[APAD])(smem + 64 * APAD);
    float (*Vs)[APAD]  = (float (*)[APAD])(smem + 2 * 64 * APAD);
    float (*Ps)[APAD]  = (float (*)[APAD])(smem + 3 * 64 * APAD);

    const int qt = blockIdx.x, h = blockIdx.y, b = blockIdx.z;
    const int tid = threadIdx.x;
    const int tx = tid & 15;
    const int ty = tid >> 4;

    const long baseq = ((long)(b * Tq + qt * 64)) * Dm + h * HD;

    for (int i = tid; i < 64 * 16; i += 256) {
        int r = i >> 4, c4 = (i & 15) << 2;
        float4 v = *(const float4*)(Q + baseq + (long)r * Dm + c4);
        Qs[r][c4] = v.x; Qs[r][c4 + 1] = v.y; Qs[r][c4 + 2] = v.z; Qs[r][c4 + 3] = v.w;
    }

    float m_i[4], l_i[4];
    unsigned long long o2[4][2];
    #pragma unroll
    for (int i = 0; i < 4; i++) {
        m_i[i] = -1e30f; l_i[i] = 0.f;
        o2[i][0] = 0ull; o2[i][1] = 0ull;
    }

    for (int kt = 0; kt <= qt; kt++) {
        const long basek = ((long)(b * Tq + kt * 64)) * Dm + h * HD;
        for (int i = tid; i < 64 * 16; i += 256) {
            int r = i >> 4, c4 = (i & 15) << 2;
            float4 kv = *(const float4*)(K + basek + (long)r * Dm + c4);
            Kst[c4][r] = kv.x; Kst[c4 + 1][r] = kv.y; Kst[c4 + 2][r] = kv.z; Kst[c4 + 3][r] = kv.w;
            float4 vv = *(const float4*)(V + basek + (long)r * Dm + c4);
            Vs[r][c4] = vv.x; Vs[r][c4 + 1] = vv.y; Vs[r][c4 + 2] = vv.z; Vs[r][c4 + 3] = vv.w;
        }
        __syncthreads();

        // S = Q K^T  (packed f32x2: 8 FFMA2 per kk)
        unsigned long long s2[4][2];
        #pragma unroll
        for (int i = 0; i < 4; i++) { s2[i][0] = 0ull; s2[i][1] = 0ull; }

        #pragma unroll 8
        for (int kk = 0; kk < 64; kk++) {
            ulonglong2 bb = *(const ulonglong2*)&Kst[kk][4 * tx];
            #pragma unroll
            for (int i = 0; i < 4; i++) {
                float a = Qs[4 * ty + i][kk];
                unsigned long long ap = pack2(a, a);
                FMA2(s2[i][0], ap, bb.x);
                FMA2(s2[i][1], ap, bb.y);
            }
        }

        float s[4][4];
        #pragma unroll
        for (int i = 0; i < 4; i++) {
            unpack2(s2[i][0], s[i][0], s[i][1]);
            unpack2(s2[i][1], s[i][2], s[i][3]);
        }

        const float scale = 0.125f;
        #pragma unroll
        for (int i = 0; i < 4; i++)
            #pragma unroll
            for (int j = 0; j < 4; j++) s[i][j] *= scale;

        if (kt == qt) {
            #pragma unroll
            for (int i = 0; i < 4; i++)
                #pragma unroll
                for (int j = 0; j < 4; j++)
                    if (4 * tx + j > 4 * ty + i) s[i][j] = -1e30f;
        }

        #pragma unroll
        for (int i = 0; i < 4; i++) {
            float rmax = fmaxf(fmaxf(s[i][0], s[i][1]), fmaxf(s[i][2], s[i][3]));
            #pragma unroll
            for (int m = 8; m; m >>= 1)
                rmax = fmaxf(rmax, __shfl_xor_sync(0xffffffffu, rmax, m));
            float mnew  = fmaxf(m_i[i], rmax);
            float alpha = expf(m_i[i] - mnew);
            m_i[i] = mnew;
            float rsum = 0.f;
            #pragma unroll
            for (int j = 0; j < 4; j++) {
                float p = expf(s[i][j] - mnew);
                s[i][j] = p;
                rsum += p;
            }
            #pragma unroll
            for (int m = 8; m; m >>= 1)
                rsum += __shfl_xor_sync(0xffffffffu, rsum, m);
            l_i[i] = l_i[i] * alpha + rsum;
            unsigned long long apk = pack2(alpha, alpha);
            MUL2(o2[i][0], o2[i][0], apk);
            MUL2(o2[i][1], o2[i][1], apk);
        }

        #pragma unroll
        for (int i = 0; i < 4; i++)
            #pragma unroll
            for (int j = 0; j < 4; j++)
                Ps[4 * ty + i][4 * tx + j] = s[i][j];
        __syncthreads();

        // O += P V  (packed f32x2)
        #pragma unroll 8
        for (int kk = 0; kk < 64; kk++) {
            ulonglong2 bb = *(const ulonglong2*)&Vs[kk][4 * tx];
            #pragma unroll
            for (int i = 0; i < 4; i++) {
                float a = Ps[4 * ty + i][kk];
                unsigned long long ap = pack2(a, a);
                FMA2(o2[i][0], ap, bb.x);
                FMA2(o2[i][1], ap, bb.y);
            }
        }
        __syncthreads();
    }

    #pragma unroll
    for (int i = 0; i < 4; i++) {
        float inv = 1.f / l_i[i];
        float o0, o1, oo2, o3;
        unpack2(o2[i][0], o0, o1);
        unpack2(o2[i][1], oo2, o3);
        long orow = baseq + (long)(4 * ty + i) * Dm + 4 * tx;
        float vals[4] = {o0 * inv, o1 * inv, oo2 * inv, o3 * inv};
        #pragma unroll
        for (int j = 0; j < 4; j++) {
            __half hi, lo;
            split16(vals[j], hi, lo);
            Yh[orow + j] = hi;
            Yl[orow + j] = lo;
        }
    }
}

// ---------------------------------------------------------------------------
// Launcher
// ---------------------------------------------------------------------------
extern "C" void kernel_launch(void* const* d_in, const int* in_sizes, int n_in,
                              void* d_out, int out_size)
{
    const int*   idx  = (const int*)  d_in[0];
    const int*   ts   = (const int*)  d_in[1];
    const float* tok  = (const float*)d_in[2];
    const float* pos  = (const float*)d_in[3];
    const float* gpos = (const float*)d_in[4];
    const float* ln1w = (const float*)d_in[5];
    const float* ln1b = (const float*)d_in[6];
    const float* Wq   = (const float*)d_in[7];
    const float* bq   = (const float*)d_in[8];
    const float* Wk   = (const float*)d_in[9];
    const float* bk   = (const float*)d_in[10];
    const float* Wv   = (const float*)d_in[11];
    const float* bv   = (const float*)d_in[12];
    const float* Wo   = (const float*)d_in[13];
    const float* bo   = (const float*)d_in[14];
    const float* ln2w = (const float*)d_in[15];
    const float* ln2b = (const float*)d_in[16];
    const float* W1   = (const float*)d_in[17];
    const float* b1   = (const float*)d_in[18];
    const float* W2   = (const float*)d_in[19];
    const float* b2   = (const float*)d_in[20];
    const float* lnfw = (const float*)d_in[21];
    const float* lnfb = (const float*)d_in[22];
    const float* hw   = (const float*)d_in[23];
    float* out = (float*)d_out;

    float *x, *qkv;
    __half *pah, *pal, *pbh, *pbl, *wh, *wl;
    cudaGetSymbolAddress((void**)&x,   g_x);
    cudaGetSymbolAddress((void**)&qkv, g_qkv);
    cudaGetSymbolAddress((void**)&pah, g_pa_h);
    cudaGetSymbolAddress((void**)&pal, g_pa_l);
    cudaGetSymbolAddress((void**)&pbh, g_pb_h);
    cudaGetSymbolAddress((void**)&pbl, g_pb_l);
    cudaGetSymbolAddress((void**)&wh,  g_wh);
    cudaGetSymbolAddress((void**)&wl,  g_wl);

    cudaFuncSetAttribute(attn_kernel, cudaFuncAttributeMaxDynamicSharedMemorySize,
                         ATT_SMEM_FLOATS * (int)sizeof(float));
    cudaFuncSetAttribute(gemm_hmma<EPI_NONE>, cudaFuncAttributeMaxDynamicSharedMemorySize, GEMM_SMEM);
    cudaFuncSetAttribute(gemm_hmma<EPI_ADD>,  cudaFuncAttributeMaxDynamicSharedMemorySize, GEMM_SMEM);
    cudaFuncSetAttribute(gemm_hmma<EPI_GELU>, cudaFuncAttributeMaxDynamicSharedMemorySize, GEMM_SMEM);
    cudaFuncSetAttribute(gemm_hmma<EPI_QKV>,  cudaFuncAttributeMaxDynamicSharedMemorySize, GEMM_SMEM);

    auto cvt = [&](const float* src, long off, long n) {
        cvt_pair<<<(int)((n / 4 + 255) / 256), 256>>>(src, wh + off, wl + off, n);
    };
    cvt(Wq, OFF_WQ, 8L * DD);
    cvt(Wk, OFF_WK, 8L * DD);
    cvt(Wv, OFF_WV, 8L * DD);
    cvt(Wo, OFF_WO, 8L * DD);
    cvt(W1, OFF_W1, 16L * DD);
    cvt(W2, OFF_W2, 16L * DD);
    cvt(hw, OFF_HW, 8L * DD);

    embed_kernel<<<(BT * Dm) / 256, 256>>>(idx, ts, tok, pos, gpos, x);

    const dim3 gD(Dm / 128, BT / 128);
    const dim3 gQKV(3 * Dm / 128, BT / 128);
    const dim3 g2D(2 * Dm / 128, BT / 128);
    const dim3 gV(Vv / 128, BT / 128);

    float* qb = qkv;
    float* kb = qkv + (long)BT * Dm;
    float* vb = qkv + 2L * BT * Dm;

    for (int l = 0; l < Ll; l++) {
        layernorm_pair<<<BT, 256>>>(x, ln1w + (long)l * Dm, ln1b + (long)l * Dm, pah, pal);

        gemm_hmma<EPI_QKV><<<gQKV, 256, GEMM_SMEM>>>(
            pah, pal, wh + OFF_WQ + (long)l * DD, wl + OFF_WQ + (long)l * DD,
            8L * DD,
            bq + (long)l * Dm, bk + (long)l * Dm, bv + (long)l * Dm,
            nullptr, qkv, nullptr, nullptr, BT, 3 * Dm, Dm);

        attn_kernel<<<dim3(Tq / 64, Hh, Bq), 256,
                      ATT_SMEM_FLOATS * sizeof(float)>>>(qb, kb, vb, pah, pal);

        gemm_hmma<EPI_ADD><<<gD, 256, GEMM_SMEM>>>(
            pah, pal, wh + OFF_WO + (long)l * DD, wl + OFF_WO + (long)l * DD, 0,
            bo + (long)l * Dm, nullptr, nullptr, x, x, nullptr, nullptr, BT, Dm, Dm);

        layernorm_pair<<<BT, 256>>>(x, ln2w + (long)l * Dm, ln2b + (long)l * Dm, pah, pal);

        gemm_hmma<EPI_GELU><<<g2D, 256, GEMM_SMEM>>>(
            pah, pal, wh + OFF_W1 + (long)l * 2 * DD, wl + OFF_W1 + (long)l * 2 * DD, 0,
            b1 + (long)l * 2 * Dm, nullptr, nullptr, nullptr,
            nullptr, pbh, pbl, BT, 2 * Dm, Dm);

        gemm_hmma<EPI_ADD><<<gD, 256, GEMM_SMEM>>>(
            pbh, pbl, wh + OFF_W2 + (long)l * 2 * DD, wl + OFF_W2 + (long)l * 2 * DD, 0,
            b2 + (long)l * Dm, nullptr, nullptr, x, x, nullptr, nullptr, BT, Dm, 2 * Dm);
    }

    layernorm_pair<<<BT, 256>>>(x, lnfw, lnfb, pah, pal);
    gemm_hmma<EPI_NONE><<<gV, 256, GEMM_SMEM>>>(
        pah, pal, wh + OFF_HW, wl + OFF_HW, 0,
        nullptr, nullptr, nullptr, nullptr, out, nullptr, nullptr, BT, Vv, Dm);
}

// round 10
// speedup vs baseline: 2.2430x; 1.1310x over previous
#include <cuda_runtime.h>
#include <cuda_fp16.h>
#include <math.h>
#include <stdint.h>

// ---------------------------------------------------------------------------
// Problem constants
// ---------------------------------------------------------------------------
#define Bq   8
#define Tq   1024
#define Dm   1024
#define Hh   16
#define Ll   8
#define Vv   8192
#define HD   64
#define BT   (Bq*Tq)

// ---------------------------------------------------------------------------
// Scratch (static device globals)
// ---------------------------------------------------------------------------
__device__ float g_x[BT * Dm];           // residual stream (f32)
__device__ float g_qkv[3L * BT * Dm];    // q | k | v

__device__ __half g_pa_h[BT * Dm];       // pair buf A: LN out / attn out
__device__ __half g_pa_l[BT * Dm];
__device__ __half g_pb_h[BT * 2 * Dm];   // pair buf B: MLP hidden
__device__ __half g_pb_l[BT * 2 * Dm];

#define DD      (Dm*Dm)
#define OFF_WQ  0L
#define OFF_WK  (8L*DD)
#define OFF_WV  (16L*DD)
#define OFF_WO  (24L*DD)
#define OFF_W1  (32L*DD)
#define OFF_W2  (48L*DD)
#define OFF_HW  (64L*DD)
#define WTOT    (72L*DD)
__device__ __half g_wh[WTOT];
__device__ __half g_wl[WTOT];

// ---------------------------------------------------------------------------
// Helpers
// ---------------------------------------------------------------------------
__device__ __forceinline__ uint32_t smem_u32(const void* p) {
    uint32_t a;
    asm("{ .reg .u64 t; cvta.to.shared.u64 t, %1; cvt.u32.u64 %0, t; }"
        : "=r"(a) : "l"(p));
    return a;
}
__device__ __forceinline__ void cpa16(uint32_t dst, const void* src) {
    asm volatile("cp.async.cg.shared.global [%0], [%1], 16;" :: "r"(dst), "l"(src));
}
__device__ __forceinline__ void ldm_x4(uint32_t& r0, uint32_t& r1,
                                       uint32_t& r2, uint32_t& r3, uint32_t addr) {
    asm volatile("ldmatrix.sync.aligned.m8n8.x4.shared.b16 {%0,%1,%2,%3}, [%4];"
                 : "=r"(r0), "=r"(r1), "=r"(r2), "=r"(r3) : "r"(addr));
}
__device__ __forceinline__ void mma_f16(float& d0, float& d1, float& d2, float& d3,
                                        uint32_t a0, uint32_t a1, uint32_t a2, uint32_t a3,
                                        uint32_t b0, uint32_t b1) {
    asm volatile(
        "mma.sync.aligned.m16n8k16.row.col.f32.f16.f16.f32 "
        "{%0,%1,%2,%3}, {%4,%5,%6,%7}, {%8,%9}, {%0,%1,%2,%3};"
        : "+f"(d0), "+f"(d1), "+f"(d2), "+f"(d3)
        : "r"(a0), "r"(a1), "r"(a2), "r"(a3), "r"(b0), "r"(b1));
}
__device__ __forceinline__ void split16(float x, __half& hi, __half& lo) {
    hi = __float2half_rn(x);
    lo = __float2half_rn(x - __half2float(hi));
}

// --- packed f32x2 ---
__device__ __forceinline__ unsigned long long pack2(float lo, float hi) {
    unsigned long long r;
    asm("mov.b64 %0, {%1, %2};" : "=l"(r) : "f"(lo), "f"(hi));
    return r;
}
__device__ __forceinline__ void unpack2(unsigned long long v, float& lo, float& hi) {
    asm("mov.b64 {%0, %1}, %2;" : "=f"(lo), "=f"(hi) : "l"(v));
}
#define FMA2(d, a, b) \
    asm("fma.rn.f32x2 %0, %1, %2, %0;" : "+l"(d) : "l"(a), "l"(b))
#define MUL2(d, a, b) \
    asm("mul.rn.f32x2 %0, %1, %2;" : "=l"(d) : "l"(a), "l"(b))

// ---------------------------------------------------------------------------
// Weight f32 -> f16 hi/lo pair conversion
// ---------------------------------------------------------------------------
__global__ __launch_bounds__(256) void cvt_pair(
    const float* __restrict__ s, __half* __restrict__ h,
    __half* __restrict__ l, long n)
{
    long i = ((long)blockIdx.x * 256 + threadIdx.x) * 4;
    if (i >= n) return;
    float4 v = *(const float4*)(s + i);
    __half h0, h1, h2, h3, l0, l1, l2, l3;
    split16(v.x, h0, l0); split16(v.y, h1, l1);
    split16(v.z, h2, l2); split16(v.w, h3, l3);
    *(__half2*)(h + i)     = __halves2half2(h0, h1);
    *(__half2*)(h + i + 2) = __halves2half2(h2, h3);
    *(__half2*)(l + i)     = __halves2half2(l0, l1);
    *(__half2*)(l + i + 2) = __halves2half2(l2, l3);
}

// ---------------------------------------------------------------------------
// Fused embedding + LayerNorm(layer0 ln1) -> x and f16 pair output
// one block per row
// ---------------------------------------------------------------------------
__global__ __launch_bounds__(256) void embed_ln(
    const int* __restrict__ idx, const int* __restrict__ ts,
    const float* __restrict__ tok, const float* __restrict__ pos,
    const float* __restrict__ gpos,
    const float* __restrict__ w, const float* __restrict__ b,
    float* __restrict__ X, __half* __restrict__ Yh, __half* __restrict__ Yl)
{
    int row = blockIdx.x;
    int t = row & (Tq - 1);
    int bb = row >> 10;
    int tid = threadIdx.x;
    int i = tid * 4;

    long tokbase = (long)idx[row] * Dm + i;
    long gposbase = (long)ts[bb] * Dm + i;
    long posbase = (long)t * Dm + i;

    float4 tv = *(const float4*)(tok + tokbase);
    float4 gv = *(const float4*)(gpos + gposbase);
    float4 pv = *(const float4*)(pos + posbase);
    float4 v;
    v.x = tv.x + gv.x + pv.x;
    v.y = tv.y + gv.y + pv.y;
    v.z = tv.z + gv.z + pv.z;
    v.w = tv.w + gv.w + pv.w;

    long base = (long)row * Dm + i;
    *(float4*)(X + base) = v;

    float s  = v.x + v.y + v.z + v.w;
    float ss = v.x*v.x + v.y*v.y + v.z*v.z + v.w*v.w;

    __shared__ float rs[8], rss[8];
    #pragma unroll
    for (int m = 16; m; m >>= 1) {
        s  += __shfl_xor_sync(0xffffffffu, s,  m);
        ss += __shfl_xor_sync(0xffffffffu, ss, m);
    }
    int wid = tid >> 5, lane = tid & 31;
    if (lane == 0) { rs[wid] = s; rss[wid] = ss; }
    __syncthreads();
    if (wid == 0) {
        s  = (lane < 8) ? rs[lane]  : 0.f;
        ss = (lane < 8) ? rss[lane] : 0.f;
        #pragma unroll
        for (int m = 4; m; m >>= 1) {
            s  += __shfl_xor_sync(0xffffffffu, s,  m);
            ss += __shfl_xor_sync(0xffffffffu, ss, m);
        }
        if (lane == 0) { rs[0] = s; rss[0] = ss; }
    }
    __syncthreads();
    float mean = rs[0] * (1.0f / Dm);
    float var  = rss[0] * (1.0f / Dm) - mean * mean;
    float rstd = rsqrtf(var + 1e-5f);

    float4 wv = *(const float4*)(w + i);
    float4 bv = *(const float4*)(b + i);
    float o0 = (v.x - mean) * rstd * wv.x + bv.x;
    float o1 = (v.y - mean) * rstd * wv.y + bv.y;
    float o2 = (v.z - mean) * rstd * wv.z + bv.z;
    float o3 = (v.w - mean) * rstd * wv.w + bv.w;

    __half h0, h1, h2, h3, l0, l1, l2, l3;
    split16(o0, h0, l0); split16(o1, h1, l1);
    split16(o2, h2, l2); split16(o3, h3, l3);
    *(__half2*)(Yh + base)     = __halves2half2(h0, h1);
    *(__half2*)(Yh + base + 2) = __halves2half2(h2, h3);
    *(__half2*)(Yl + base)     = __halves2half2(l0, l1);
    *(__half2*)(Yl + base + 2) = __halves2half2(l2, l3);
}

// ---------------------------------------------------------------------------
// LayerNorm -> f16 hi/lo pair output
// ---------------------------------------------------------------------------
__global__ __launch_bounds__(256) void layernorm_pair(
    const float* __restrict__ X, const float* __restrict__ w,
    const float* __restrict__ b, __half* __restrict__ Yh, __half* __restrict__ Yl)
{
    int row = blockIdx.x;
    const float* x = X + (long)row * Dm;
    int tid = threadIdx.x;

    int i = tid * 4;
    float4 v = *(const float4*)(x + i);
    float s  = v.x + v.y + v.z + v.w;
    float ss = v.x*v.x + v.y*v.y + v.z*v.z + v.w*v.w;

    __shared__ float rs[8], rss[8];
    #pragma unroll
    for (int m = 16; m; m >>= 1) {
        s  += __shfl_xor_sync(0xffffffffu, s,  m);
        ss += __shfl_xor_sync(0xffffffffu, ss, m);
    }
    int wid = tid >> 5, lane = tid & 31;
    if (lane == 0) { rs[wid] = s; rss[wid] = ss; }
    __syncthreads();
    if (wid == 0) {
        s  = (lane < 8) ? rs[lane]  : 0.f;
        ss = (lane < 8) ? rss[lane] : 0.f;
        #pragma unroll
        for (int m = 4; m; m >>= 1) {
            s  += __shfl_xor_sync(0xffffffffu, s,  m);
            ss += __shfl_xor_sync(0xffffffffu, ss, m);
        }
        if (lane == 0) { rs[0] = s; rss[0] = ss; }
    }
    __syncthreads();
    float mean = rs[0] * (1.0f / Dm);
    float var  = rss[0] * (1.0f / Dm) - mean * mean;
    float rstd = rsqrtf(var + 1e-5f);

    float4 wv = *(const float4*)(w + i);
    float4 bv = *(const float4*)(b + i);
    float o0 = (v.x - mean) * rstd * wv.x + bv.x;
    float o1 = (v.y - mean) * rstd * wv.y + bv.y;
    float o2 = (v.z - mean) * rstd * wv.z + bv.z;
    float o3 = (v.w - mean) * rstd * wv.w + bv.w;

    long base = (long)row * Dm + i;
    __half h0, h1, h2, h3, l0, l1, l2, l3;
    split16(o0, h0, l0); split16(o1, h1, l1);
    split16(o2, h2, l2); split16(o3, h3, l3);
    *(__half2*)(Yh + base)     = __halves2half2(h0, h1);
    *(__half2*)(Yh + base + 2) = __halves2half2(h2, h3);
    *(__half2*)(Yl + base)     = __halves2half2(l0, l1);
    *(__half2*)(Yl + base + 2) = __halves2half2(l2, l3);
}

// ---------------------------------------------------------------------------
// HMMA GEMM (TERMS = 3: full 3x split; TERMS = 2: drop Al term + Al loads).
// CTA 128x128, k-step 32, cp.async double buffer, 8 warps of 64x32.
// ---------------------------------------------------------------------------
#define EPI_NONE 0
#define EPI_ADD  1
#define EPI_GELU 2
#define EPI_QKV  3

#define PK      40
#define TILE_H  (128*PK)
#define STG_H   (4*TILE_H)
#define GEMM_SMEM (2*STG_H*2)

template<int EPI, int TERMS>
__global__ __launch_bounds__(256, 2) void gemm_hmma(
    const __half* __restrict__ Ah, const __half* __restrict__ Al,
    const __half* __restrict__ Bh, const __half* __restrict__ Bl,
    long bStride,
    const float* __restrict__ b0p, const float* __restrict__ b1p,
    const float* __restrict__ b2p, const float* __restrict__ res,
    float* __restrict__ C, __half* __restrict__ Ch, __half* __restrict__ Cl,
    int M, int N, int K)
{
    extern __shared__ __align__(16) __half gsm[];
    const uint32_t sbase = smem_u32(gsm);

    const int tid = threadIdx.x, lane = tid & 31, warp = tid >> 5;
    const int g = lane >> 2, t = lane & 3, l7 = lane & 7;
    const int wm = warp & 1, wn = warp >> 1;
    const int m0 = blockIdx.y * 128, n0 = blockIdx.x * 128;

    float acc[4][4][4];
    #pragma unroll
    for (int a = 0; a < 4; a++)
        #pragma unroll
        for (int b = 0; b < 4; b++)
            #pragma unroll
            for (int c = 0; c < 4; c++) acc[a][b][c] = 0.f;

    const int S = K >> 5;

    auto issue = [&](int k0, int buf) {
        #pragma unroll
        for (int j = 0; j < 8; j++) {
            int c = tid + 256 * j;
            int tile = c >> 9;
            if (TERMS == 2 && tile == 1) continue;   // Al tile unused
            int r = (c >> 2) & 127;
            int q = c & 3;
            const __half* src;
            if (tile == 0)      src = Ah + (long)(m0 + r) * K + k0 + q * 8;
            else if (tile == 1) src = Al + (long)(m0 + r) * K + k0 + q * 8;
            else {
                long roff;
                if (EPI == EPI_QKV) {
                    int rg = n0 + r;
                    roff = (long)(rg >> 10) * bStride + (long)(rg & 1023) * K;
                } else {
                    roff = (long)(n0 + r) * K;
                }
                src = (tile == 2 ? Bh : Bl) + roff + k0 + q * 8;
            }
            uint32_t dst = sbase + (uint32_t)(buf * STG_H + tile * TILE_H + r * PK + q * 8) * 2u;
            cpa16(dst, src);
        }
        asm volatile("cp.async.commit_group;" ::: "memory");
    };

    issue(0, 0);

    for (int s = 0; s < S; s++) {
        asm volatile("cp.async.wait_group 0;" ::: "memory");
        __syncthreads();
        if (s + 1 < S) issue((s + 1) << 5, (s + 1) & 1);

        uint32_t sb  = sbase + (uint32_t)((s & 1) * STG_H) * 2u;
        uint32_t A_h = sb;
        uint32_t A_l = sb + TILE_H * 2u;
        uint32_t B_h = sb + 2u * TILE_H * 2u;
        uint32_t B_l = sb + 3u * TILE_H * 2u;

        #pragma unroll
        for (int kk = 0; kk < 32; kk += 16) {
            uint32_t bh[4][2], bl[4][2];
            #pragma unroll
            for (int p = 0; p < 2; p++) {
                int row = wn * 32 + p * 16 + l7 + ((lane & 16) >> 1);
                int kc  = kk + (lane & 8);
                uint32_t off = (uint32_t)(row * PK + kc) * 2u;
                ldm_x4(bh[2*p][0], bh[2*p][1], bh[2*p+1][0], bh[2*p+1][1], B_h + off);
                ldm_x4(bl[2*p][0], bl[2*p][1], bl[2*p+1][0], bl[2*p+1][1], B_l + off);
            }
            #pragma unroll
            for (int mi = 0; mi < 4; mi++) {
                int row = wm * 64 + mi * 16 + l7 + (lane & 8);
                int kc  = kk + ((lane & 16) >> 1);
                uint32_t off = (uint32_t)(row * PK + kc) * 2u;
                uint32_t ah0, ah1, ah2, ah3;
                ldm_x4(ah0, ah1, ah2, ah3, A_h + off);
                uint32_t al0 = 0, al1 = 0, al2 = 0, al3 = 0;
                if (TERMS == 3) ldm_x4(al0, al1, al2, al3, A_l + off);
                #pragma unroll
                for (int ni = 0; ni < 4; ni++) {
                    float* d = acc[mi][ni];
                    mma_f16(d[0], d[1], d[2], d[3], ah0, ah1, ah2, ah3, bh[ni][0], bh[ni][1]);
                    mma_f16(d[0], d[1], d[2], d[3], ah0, ah1, ah2, ah3, bl[ni][0], bl[ni][1]);
                    if (TERMS == 3)
                        mma_f16(d[0], d[1], d[2], d[3], al0, al1, al2, al3, bh[ni][0], bh[ni][1]);
                }
            }
        }
    }

    // --- epilogue ---
    const float* bias = b0p;
    float* Cd = C;
    int csub = 0, Nw = N;
    if (EPI == EPI_QKV) {
        int sel = n0 >> 10;
        bias = (sel == 0) ? b0p : (sel == 1) ? b1p : b2p;
        Cd = C + (long)sel * BT * Dm;
        csub = sel << 10;
        Nw = Dm;
    }

    #pragma unroll
    for (int mi = 0; mi < 4; mi++) {
        int r0 = m0 + wm * 64 + mi * 16 + g;
        #pragma unroll
        for (int ni = 0; ni < 4; ni++) {
            int cc = n0 + wn * 32 + ni * 8 + 2 * t;
            float b0v = bias ? bias[cc - csub] : 0.f;
            float b1v = bias ? bias[cc - csub + 1] : 0.f;
            float v0 = acc[mi][ni][0] + b0v, v1 = acc[mi][ni][1] + b1v;
            float v2 = acc[mi][ni][2] + b0v, v3 = acc[mi][ni][3] + b1v;
            long i0 = (long)r0 * Nw + (cc - csub);
            long i1 = (long)(r0 + 8) * Nw + (cc - csub);
            if (EPI == EPI_ADD) {
                v0 += res[i0]; v1 += res[i0 + 1];
                v2 += res[i1]; v3 += res[i1 + 1];
            }
            if (EPI == EPI_GELU) {
                v0 = 0.5f * v0 * (1.f + erff(v0 * 0.70710678118654752f));
                v1 = 0.5f * v1 * (1.f + erff(v1 * 0.70710678118654752f));
                v2 = 0.5f * v2 * (1.f + erff(v2 * 0.70710678118654752f));
                v3 = 0.5f * v3 * (1.f + erff(v3 * 0.70710678118654752f));
                __half h0, h1, h2, h3, l0, l1, l2, l3;
                split16(v0, h0, l0); split16(v1, h1, l1);
                split16(v2, h2, l2); split16(v3, h3, l3);
                *(__half2*)(Ch + i0) = __halves2half2(h0, h1);
                *(__half2*)(Ch + i1) = __halves2half2(h2, h3);
                *(__half2*)(Cl + i0) = __halves2half2(l0, l1);
                *(__half2*)(Cl + i1) = __halves2half2(l2, l3);
            } else {
                *(float2*)(Cd + i0) = make_float2(v0, v1);
                *(float2*)(Cd + i1) = make_float2(v2, v3);
            }
        }
    }
}

// ---------------------------------------------------------------------------
// Flash attention (fp32, causal) with packed f32x2 FMA -> f16 hi/lo pairs
// ---------------------------------------------------------------------------
#define APAD 68
#define ATT_SMEM_FLOATS (4 * 64 * APAD)

__global__ __launch_bounds__(256) void attn_kernel(
    const float* __restrict__ Q, const float* __restrict__ K,
    const float* __restrict__ V, __half* __restrict__ Yh, __half* __restrict__ Yl)
{
    extern __shared__ float smem[];
    float (*Qs)[APAD]  = (float (*)[APAD])(smem);
    float (*Kst)[APAD] = (float (*)[APAD])(smem + 64 * APAD);
    float (*Vs)[APAD]  = (float (*)[APAD])(smem + 2 * 64 * APAD);
    float (*Ps)[APAD]  = (float (*)[APAD])(smem + 3 * 64 * APAD);

    const int qt = blockIdx.x, h = blockIdx.y, b = blockIdx.z;
    const int tid = threadIdx.x;
    const int tx = tid & 15;
    const int ty = tid >> 4;

    const long baseq = ((long)(b * Tq + qt * 64)) * Dm + h * HD;

    for (int i = tid; i < 64 * 16; i += 256) {
        int r = i >> 4, c4 = (i & 15) << 2;
        float4 v = *(const float4*)(Q + baseq + (long)r * Dm + c4);
        Qs[r][c4] = v.x; Qs[r][c4 + 1] = v.y; Qs[r][c4 + 2] = v.z; Qs[r][c4 + 3] = v.w;
    }

    float m_i[4], l_i[4];
    unsigned long long o2[4][2];
    #pragma unroll
    for (int i = 0; i < 4; i++) {
        m_i[i] = -1e30f; l_i[i] = 0.f;
        o2[i][0] = 0ull; o2[i][1] = 0ull;
    }

    for (int kt = 0; kt <= qt; kt++) {
        const long basek = ((long)(b * Tq + kt * 64)) * Dm + h * HD;
        for (int i = tid; i < 64 * 16; i += 256) {
            int r = i >> 4, c4 = (i & 15) << 2;
            float4 kv = *(const float4*)(K + basek + (long)r * Dm + c4);
            Kst[c4][r] = kv.x; Kst[c4 + 1][r] = kv.y; Kst[c4 + 2][r] = kv.z; Kst[c4 + 3][r] = kv.w;
            float4 vv = *(const float4*)(V + basek + (long)r * Dm + c4);
            Vs[r][c4] = vv.x; Vs[r][c4 + 1] = vv.y; Vs[r][c4 + 2] = vv.z; Vs[r][c4 + 3] = vv.w;
        }
        __syncthreads();

        unsigned long long s2[4][2];
        #pragma unroll
        for (int i = 0; i < 4; i++) { s2[i][0] = 0ull; s2[i][1] = 0ull; }

        #pragma unroll 8
        for (int kk = 0; kk < 64; kk++) {
            ulonglong2 bb = *(const ulonglong2*)&Kst[kk][4 * tx];
            #pragma unroll
            for (int i = 0; i < 4; i++) {
                float a = Qs[4 * ty + i][kk];
                unsigned long long ap = pack2(a, a);
                FMA2(s2[i][0], ap, bb.x);
                FMA2(s2[i][1], ap, bb.y);
            }
        }

        float s[4][4];
        #pragma unroll
        for (int i = 0; i < 4; i++) {
            unpack2(s2[i][0], s[i][0], s[i][1]);
            unpack2(s2[i][1], s[i][2], s[i][3]);
        }

        const float scale = 0.125f;
        #pragma unroll
        for (int i = 0; i < 4; i++)
            #pragma unroll
            for (int j = 0; j < 4; j++) s[i][j] *= scale;

        if (kt == qt) {
            #pragma unroll
            for (int i = 0; i < 4; i++)
                #pragma unroll
                for (int j = 0; j < 4; j++)
                    if (4 * tx + j > 4 * ty + i) s[i][j] = -1e30f;
        }

        #pragma unroll
        for (int i = 0; i < 4; i++) {
            float rmax = fmaxf(fmaxf(s[i][0], s[i][1]), fmaxf(s[i][2], s[i][3]));
            #pragma unroll
            for (int m = 8; m; m >>= 1)
                rmax = fmaxf(rmax, __shfl_xor_sync(0xffffffffu, rmax, m));
            float mnew  = fmaxf(m_i[i], rmax);
            float alpha = expf(m_i[i] - mnew);
            m_i[i] = mnew;
            float rsum = 0.f;
            #pragma unroll
            for (int j = 0; j < 4; j++) {
                float p = expf(s[i][j] - mnew);
                s[i][j] = p;
                rsum += p;
            }
            #pragma unroll
            for (int m = 8; m; m >>= 1)
                rsum += __shfl_xor_sync(0xffffffffu, rsum, m);
            l_i[i] = l_i[i] * alpha + rsum;
            unsigned long long apk = pack2(alpha, alpha);
            MUL2(o2[i][0], o2[i][0], apk);
            MUL2(o2[i][1], o2[i][1], apk);
        }

        #pragma unroll
        for (int i = 0; i < 4; i++)
            #pragma unroll
            for (int j = 0; j < 4; j++)
                Ps[4 * ty + i][4 * tx + j] = s[i][j];
        __syncthreads();

        #pragma unroll 8
        for (int kk = 0; kk < 64; kk++) {
            ulonglong2 bb = *(const ulonglong2*)&Vs[kk][4 * tx];
            #pragma unroll
            for (int i = 0; i < 4; i++) {
                float a = Ps[4 * ty + i][kk];
                unsigned long long ap = pack2(a, a);
                FMA2(o2[i][0], ap, bb.x);
                FMA2(o2[i][1], ap, bb.y);
            }
        }
        __syncthreads();
    }

    #pragma unroll
    for (int i = 0; i < 4; i++) {
        float inv = 1.f / l_i[i];
        float o0, o1, oo2, o3;
        unpack2(o2[i][0], o0, o1);
        unpack2(o2[i][1], oo2, o3);
        long orow = baseq + (long)(4 * ty + i) * Dm + 4 * tx;
        float vals[4] = {o0 * inv, o1 * inv, oo2 * inv, o3 * inv};
        #pragma unroll
        for (int j = 0; j < 4; j++) {
            __half hi, lo;
            split16(vals[j], hi, lo);
            Yh[orow + j] = hi;
            Yl[orow + j] = lo;
        }
    }
}

// ---------------------------------------------------------------------------
// Launcher (ordered so layer-0 QKV GEMM lands at global launch idx 5 for ncu)
// ---------------------------------------------------------------------------
extern "C" void kernel_launch(void* const* d_in, const int* in_sizes, int n_in,
                              void* d_out, int out_size)
{
    const int*   idx  = (const int*)  d_in[0];
    const int*   ts   = (const int*)  d_in[1];
    const float* tok  = (const float*)d_in[2];
    const float* pos  = (const float*)d_in[3];
    const float* gpos = (const float*)d_in[4];
    const float* ln1w = (const float*)d_in[5];
    const float* ln1b = (const float*)d_in[6];
    const float* Wq   = (const float*)d_in[7];
    const float* bq   = (const float*)d_in[8];
    const float* Wk   = (const float*)d_in[9];
    const float* bk   = (const float*)d_in[10];
    const float* Wv   = (const float*)d_in[11];
    const float* bv   = (const float*)d_in[12];
    const float* Wo   = (const float*)d_in[13];
    const float* bo   = (const float*)d_in[14];
    const float* ln2w = (const float*)d_in[15];
    const float* ln2b = (const float*)d_in[16];
    const float* W1   = (const float*)d_in[17];
    const float* b1   = (const float*)d_in[18];
    const float* W2   = (const float*)d_in[19];
    const float* b2   = (const float*)d_in[20];
    const float* lnfw = (const float*)d_in[21];
    const float* lnfb = (const float*)d_in[22];
    const float* hw   = (const float*)d_in[23];
    float* out = (float*)d_out;

    float *x, *qkv;
    __half *pah, *pal, *pbh, *pbl, *wh, *wl;
    cudaGetSymbolAddress((void**)&x,   g_x);
    cudaGetSymbolAddress((void**)&qkv, g_qkv);
    cudaGetSymbolAddress((void**)&pah, g_pa_h);
    cudaGetSymbolAddress((void**)&pal, g_pa_l);
    cudaGetSymbolAddress((void**)&pbh, g_pb_h);
    cudaGetSymbolAddress((void**)&pbl, g_pb_l);
    cudaGetSymbolAddress((void**)&wh,  g_wh);
    cudaGetSymbolAddress((void**)&wl,  g_wl);

    cudaFuncSetAttribute(attn_kernel, cudaFuncAttributeMaxDynamicSharedMemorySize,
                         ATT_SMEM_FLOATS * (int)sizeof(float));
    cudaFuncSetAttribute(gemm_hmma<EPI_QKV, 3>,  cudaFuncAttributeMaxDynamicSharedMemorySize, GEMM_SMEM);
    cudaFuncSetAttribute(gemm_hmma<EPI_ADD, 3>,  cudaFuncAttributeMaxDynamicSharedMemorySize, GEMM_SMEM);
    cudaFuncSetAttribute(gemm_hmma<EPI_ADD, 2>,  cudaFuncAttributeMaxDynamicSharedMemorySize, GEMM_SMEM);
    cudaFuncSetAttribute(gemm_hmma<EPI_GELU, 2>, cudaFuncAttributeMaxDynamicSharedMemorySize, GEMM_SMEM);
    cudaFuncSetAttribute(gemm_hmma<EPI_NONE, 2>, cudaFuncAttributeMaxDynamicSharedMemorySize, GEMM_SMEM);

    auto cvt = [&](const float* src, long off, long n) {
        cvt_pair<<<(int)((n / 4 + 255) / 256), 256>>>(src, wh + off, wl + off, n);
    };

    const dim3 gD(Dm / 128, BT / 128);
    const dim3 gQKV(3 * Dm / 128, BT / 128);
    const dim3 g2D(2 * Dm / 128, BT / 128);
    const dim3 gV(Vv / 128, BT / 128);

    float* qb = qkv;
    float* kb = qkv + (long)BT * Dm;
    float* vb = qkv + 2L * BT * Dm;

    // launches 1-3: QKV weight conversion; 4: fused embed+LN0; 5: QKV GEMM
    cvt(Wq, OFF_WQ, 8L * DD);
    cvt(Wk, OFF_WK, 8L * DD);
    cvt(Wv, OFF_WV, 8L * DD);
    embed_ln<<<BT, 256>>>(idx, ts, tok, pos, gpos, ln1w, ln1b, x, pah, pal);

    bool cvted = false;

    for (int l = 0; l < Ll; l++) {
        if (l > 0)
            layernorm_pair<<<BT, 256>>>(x, ln1w + (long)l * Dm, ln1b + (long)l * Dm, pah, pal);

        gemm_hmma<EPI_QKV, 3><<<gQKV, 256, GEMM_SMEM>>>(
            pah, pal, wh + OFF_WQ + (long)l * DD, wl + OFF_WQ + (long)l * DD,
            8L * DD,
            bq + (long)l * Dm, bk + (long)l * Dm, bv + (long)l * Dm,
            nullptr, qkv, nullptr, nullptr, BT, 3 * Dm, Dm);

        attn_kernel<<<dim3(Tq / 64, Hh, Bq), 256,
                      ATT_SMEM_FLOATS * sizeof(float)>>>(qb, kb, vb, pah, pal);

        if (!cvted) cvt(Wo, OFF_WO, 8L * DD);

        gemm_hmma<EPI_ADD, 3><<<gD, 256, GEMM_SMEM>>>(
            pah, pal, wh + OFF_WO + (long)l * DD, wl + OFF_WO + (long)l * DD, 0,
            bo + (long)l * Dm, nullptr, nullptr, x, x, nullptr, nullptr, BT, Dm, Dm);

        layernorm_pair<<<BT, 256>>>(x, ln2w + (long)l * Dm, ln2b + (long)l * Dm, pah, pal);

        if (!cvted) cvt(W1, OFF_W1, 16L * DD);

        gemm_hmma<EPI_GELU, 2><<<g2D, 256, GEMM_SMEM>>>(
            pah, pal, wh + OFF_W1 + (long)l * 2 * DD, wl + OFF_W1 + (long)l * 2 * DD, 0,
            b1 + (long)l * 2 * Dm, nullptr, nullptr, nullptr,
            nullptr, pbh, pbl, BT, 2 * Dm, Dm);

        if (!cvted) { cvt(W2, OFF_W2, 16L * DD); cvted = true; }

        gemm_hmma<EPI_ADD, 2><<<gD, 256, GEMM_SMEM>>>(
            pbh, pbl, wh + OFF_W2 + (long)l * 2 * DD, wl + OFF_W2 + (long)l * 2 * DD, 0,
            b2 + (long)l * Dm, nullptr, nullptr, x, x, nullptr, nullptr, BT, Dm, 2 * Dm);
    }

    layernorm_pair<<<BT, 256>>>(x, lnfw, lnfb, pah, pal);
    cvt(hw, OFF_HW, 8L * DD);
    gemm_hmma<EPI_NONE, 2><<<gV, 256, GEMM_SMEM>>>(
        pah, pal, wh + OFF_HW, wl + OFF_HW, 0,
        nullptr, nullptr, nullptr, nullptr, out, nullptr, nullptr, BT, Vv, Dm);
}

// round 11
// speedup vs baseline: 2.5287x; 1.1273x over previous
#include <cuda_runtime.h>
#include <cuda_fp16.h>
#include <math.h>
#include <stdint.h>

// ---------------------------------------------------------------------------
// Problem constants
// ---------------------------------------------------------------------------
#define Bq   8
#define Tq   1024
#define Dm   1024
#define Hh   16
#define Ll   8
#define Vv   8192
#define HD   64
#define BT   (Bq*Tq)

// ---------------------------------------------------------------------------
// Scratch (static device globals)
// ---------------------------------------------------------------------------
__device__ float g_x[BT * Dm];           // residual stream (f32)
__device__ float g_qkv[3L * BT * Dm];    // q | k | v

__device__ __half g_pa[BT * Dm];         // act buf A: LN out / attn out (hi only)
__device__ __half g_pb[BT * 2 * Dm];     // act buf B: MLP hidden (hi only)

#define DD      (Dm*Dm)
#define OFF_WQ  0L
#define OFF_WK  (8L*DD)
#define OFF_WV  (16L*DD)
#define OFF_WO  (24L*DD)
#define OFF_W1  (32L*DD)
#define OFF_W2  (48L*DD)
#define OFF_HW  (64L*DD)
#define WTOT    (72L*DD)
__device__ __half g_wh[WTOT];
__device__ __half g_wl[WTOT];

// ---------------------------------------------------------------------------
// Helpers
// ---------------------------------------------------------------------------
__device__ __forceinline__ uint32_t smem_u32(const void* p) {
    uint32_t a;
    asm("{ .reg .u64 t; cvta.to.shared.u64 t, %1; cvt.u32.u64 %0, t; }"
        : "=r"(a) : "l"(p));
    return a;
}
__device__ __forceinline__ void cpa16(uint32_t dst, const void* src) {
    asm volatile("cp.async.cg.shared.global [%0], [%1], 16;" :: "r"(dst), "l"(src));
}
__device__ __forceinline__ void ldm_x4(uint32_t& r0, uint32_t& r1,
                                       uint32_t& r2, uint32_t& r3, uint32_t addr) {
    asm volatile("ldmatrix.sync.aligned.m8n8.x4.shared.b16 {%0,%1,%2,%3}, [%4];"
                 : "=r"(r0), "=r"(r1), "=r"(r2), "=r"(r3) : "r"(addr));
}
__device__ __forceinline__ void mma_f16(float& d0, float& d1, float& d2, float& d3,
                                        uint32_t a0, uint32_t a1, uint32_t a2, uint32_t a3,
                                        uint32_t b0, uint32_t b1) {
    asm volatile(
        "mma.sync.aligned.m16n8k16.row.col.f32.f16.f16.f32 "
        "{%0,%1,%2,%3}, {%4,%5,%6,%7}, {%8,%9}, {%0,%1,%2,%3};"
        : "+f"(d0), "+f"(d1), "+f"(d2), "+f"(d3)
        : "r"(a0), "r"(a1), "r"(a2), "r"(a3), "r"(b0), "r"(b1));
}
__device__ __forceinline__ void split16(float x, __half& hi, __half& lo) {
    hi = __float2half_rn(x);
    lo = __float2half_rn(x - __half2float(hi));
}

// --- packed f32x2 ---
__device__ __forceinline__ unsigned long long pack2(float lo, float hi) {
    unsigned long long r;
    asm("mov.b64 %0, {%1, %2};" : "=l"(r) : "f"(lo), "f"(hi));
    return r;
}
__device__ __forceinline__ void unpack2(unsigned long long v, float& lo, float& hi) {
    asm("mov.b64 {%0, %1}, %2;" : "=f"(lo), "=f"(hi) : "l"(v));
}
#define FMA2(d, a, b) \
    asm("fma.rn.f32x2 %0, %1, %2, %0;" : "+l"(d) : "l"(a), "l"(b))
#define MUL2(d, a, b) \
    asm("mul.rn.f32x2 %0, %1, %2;" : "=l"(d) : "l"(a), "l"(b))

// ---------------------------------------------------------------------------
// Weight f32 -> f16 hi/lo pair conversion (weights keep 2 slices)
// ---------------------------------------------------------------------------
__global__ __launch_bounds__(256) void cvt_pair(
    const float* __restrict__ s, __half* __restrict__ h,
    __half* __restrict__ l, long n)
{
    long i = ((long)blockIdx.x * 256 + threadIdx.x) * 4;
    if (i >= n) return;
    float4 v = *(const float4*)(s + i);
    __half h0, h1, h2, h3, l0, l1, l2, l3;
    split16(v.x, h0, l0); split16(v.y, h1, l1);
    split16(v.z, h2, l2); split16(v.w, h3, l3);
    *(__half2*)(h + i)     = __halves2half2(h0, h1);
    *(__half2*)(h + i + 2) = __halves2half2(h2, h3);
    *(__half2*)(l + i)     = __halves2half2(l0, l1);
    *(__half2*)(l + i + 2) = __halves2half2(l2, l3);
}

// ---------------------------------------------------------------------------
// Fused embedding + LayerNorm(layer0 ln1) -> x and f16 output
// ---------------------------------------------------------------------------
__global__ __launch_bounds__(256) void embed_ln(
    const int* __restrict__ idx, const int* __restrict__ ts,
    const float* __restrict__ tok, const float* __restrict__ pos,
    const float* __restrict__ gpos,
    const float* __restrict__ w, const float* __restrict__ b,
    float* __restrict__ X, __half* __restrict__ Y)
{
    int row = blockIdx.x;
    int t = row & (Tq - 1);
    int bb = row >> 10;
    int tid = threadIdx.x;
    int i = tid * 4;

    long tokbase = (long)idx[row] * Dm + i;
    long gposbase = (long)ts[bb] * Dm + i;
    long posbase = (long)t * Dm + i;

    float4 tv = *(const float4*)(tok + tokbase);
    float4 gv = *(const float4*)(gpos + gposbase);
    float4 pv = *(const float4*)(pos + posbase);
    float4 v;
    v.x = tv.x + gv.x + pv.x;
    v.y = tv.y + gv.y + pv.y;
    v.z = tv.z + gv.z + pv.z;
    v.w = tv.w + gv.w + pv.w;

    long base = (long)row * Dm + i;
    *(float4*)(X + base) = v;

    float s  = v.x + v.y + v.z + v.w;
    float ss = v.x*v.x + v.y*v.y + v.z*v.z + v.w*v.w;

    __shared__ float rs[8], rss[8];
    #pragma unroll
    for (int m = 16; m; m >>= 1) {
        s  += __shfl_xor_sync(0xffffffffu, s,  m);
        ss += __shfl_xor_sync(0xffffffffu, ss, m);
    }
    int wid = tid >> 5, lane = tid & 31;
    if (lane == 0) { rs[wid] = s; rss[wid] = ss; }
    __syncthreads();
    if (wid == 0) {
        s  = (lane < 8) ? rs[lane]  : 0.f;
        ss = (lane < 8) ? rss[lane] : 0.f;
        #pragma unroll
        for (int m = 4; m; m >>= 1) {
            s  += __shfl_xor_sync(0xffffffffu, s,  m);
            ss += __shfl_xor_sync(0xffffffffu, ss, m);
        }
        if (lane == 0) { rs[0] = s; rss[0] = ss; }
    }
    __syncthreads();
    float mean = rs[0] * (1.0f / Dm);
    float var  = rss[0] * (1.0f / Dm) - mean * mean;
    float rstd = rsqrtf(var + 1e-5f);

    float4 wv = *(const float4*)(w + i);
    float4 bv = *(const float4*)(b + i);
    float o0 = (v.x - mean) * rstd * wv.x + bv.x;
    float o1 = (v.y - mean) * rstd * wv.y + bv.y;
    float o2 = (v.z - mean) * rstd * wv.z + bv.z;
    float o3 = (v.w - mean) * rstd * wv.w + bv.w;

    *(__half2*)(Y + base)     = __halves2half2(__float2half_rn(o0), __float2half_rn(o1));
    *(__half2*)(Y + base + 2) = __halves2half2(__float2half_rn(o2), __float2half_rn(o3));
}

// ---------------------------------------------------------------------------
// LayerNorm -> f16 output
// ---------------------------------------------------------------------------
__global__ __launch_bounds__(256) void layernorm_f16(
    const float* __restrict__ X, const float* __restrict__ w,
    const float* __restrict__ b, __half* __restrict__ Y)
{
    int row = blockIdx.x;
    const float* x = X + (long)row * Dm;
    int tid = threadIdx.x;

    int i = tid * 4;
    float4 v = *(const float4*)(x + i);
    float s  = v.x + v.y + v.z + v.w;
    float ss = v.x*v.x + v.y*v.y + v.z*v.z + v.w*v.w;

    __shared__ float rs[8], rss[8];
    #pragma unroll
    for (int m = 16; m; m >>= 1) {
        s  += __shfl_xor_sync(0xffffffffu, s,  m);
        ss += __shfl_xor_sync(0xffffffffu, ss, m);
    }
    int wid = tid >> 5, lane = tid & 31;
    if (lane == 0) { rs[wid] = s; rss[wid] = ss; }
    __syncthreads();
    if (wid == 0) {
        s  = (lane < 8) ? rs[lane]  : 0.f;
        ss = (lane < 8) ? rss[lane] : 0.f;
        #pragma unroll
        for (int m = 4; m; m >>= 1) {
            s  += __shfl_xor_sync(0xffffffffu, s,  m);
            ss += __shfl_xor_sync(0xffffffffu, ss, m);
        }
        if (lane == 0) { rs[0] = s; rss[0] = ss; }
    }
    __syncthreads();
    float mean = rs[0] * (1.0f / Dm);
    float var  = rss[0] * (1.0f / Dm) - mean * mean;
    float rstd = rsqrtf(var + 1e-5f);

    float4 wv = *(const float4*)(w + i);
    float4 bv = *(const float4*)(b + i);
    float o0 = (v.x - mean) * rstd * wv.x + bv.x;
    float o1 = (v.y - mean) * rstd * wv.y + bv.y;
    float o2 = (v.z - mean) * rstd * wv.z + bv.z;
    float o3 = (v.w - mean) * rstd * wv.w + bv.w;

    long base = (long)row * Dm + i;
    *(__half2*)(Y + base)     = __halves2half2(__float2half_rn(o0), __float2half_rn(o1));
    *(__half2*)(Y + base + 2) = __halves2half2(__float2half_rn(o2), __float2half_rn(o3));
}

// ---------------------------------------------------------------------------
// HMMA GEMM, 2-term split everywhere: C = Ah·Bh + Ah·Bl (+bias)(+res | gelu).
// CTA 128x128, k-step 32, cp.async double buffer, 8 warps of 64x32.
// smem: 2 stages x 3 tiles x (128x40 halfs) = 61440 B.
// ---------------------------------------------------------------------------
#define EPI_NONE 0
#define EPI_ADD  1
#define EPI_GELU 2
#define EPI_QKV  3

#define PK      40
#define TILE_H  (128*PK)
#define STG_H   (3*TILE_H)
#define GEMM_SMEM (2*STG_H*2)

template<int EPI>
__global__ __launch_bounds__(256, 2) void gemm_hmma(
    const __half* __restrict__ Ah,
    const __half* __restrict__ Bh, const __half* __restrict__ Bl,
    long bStride,
    const float* __restrict__ b0p, const float* __restrict__ b1p,
    const float* __restrict__ b2p, const float* __restrict__ res,
    float* __restrict__ C, __half* __restrict__ Ch,
    int M, int N, int K)
{
    extern __shared__ __align__(16) __half gsm[];
    const uint32_t sbase = smem_u32(gsm);

    const int tid = threadIdx.x, lane = tid & 31, warp = tid >> 5;
    const int g = lane >> 2, t = lane & 3, l7 = lane & 7;
    const int wm = warp & 1, wn = warp >> 1;
    const int m0 = blockIdx.y * 128, n0 = blockIdx.x * 128;

    float acc[4][4][4];
    #pragma unroll
    for (int a = 0; a < 4; a++)
        #pragma unroll
        for (int b = 0; b < 4; b++)
            #pragma unroll
            for (int c = 0; c < 4; c++) acc[a][b][c] = 0.f;

    const int S = K >> 5;

    // 1536 16B-chunks per stage: Ah[0,512) Bh[512,1024) Bl[1024,1536)
    auto issue = [&](int k0, int buf) {
        #pragma unroll
        for (int j = 0; j < 6; j++) {
            int c = tid + 256 * j;
            int tile = c >> 9;
            int r = (c >> 2) & 127;
            int q = c & 3;
            const __half* src;
            if (tile == 0) src = Ah + (long)(m0 + r) * K + k0 + q * 8;
            else {
                long roff;
                if (EPI == EPI_QKV) {
                    int rg = n0 + r;
                    roff = (long)(rg >> 10) * bStride + (long)(rg & 1023) * K;
                } else {
                    roff = (long)(n0 + r) * K;
                }
                src = (tile == 1 ? Bh : Bl) + roff + k0 + q * 8;
            }
            uint32_t dst = sbase + (uint32_t)(buf * STG_H + tile * TILE_H + r * PK + q * 8) * 2u;
            cpa16(dst, src);
        }
        asm volatile("cp.async.commit_group;" ::: "memory");
    };

    issue(0, 0);

    for (int s = 0; s < S; s++) {
        asm volatile("cp.async.wait_group 0;" ::: "memory");
        __syncthreads();
        if (s + 1 < S) issue((s + 1) << 5, (s + 1) & 1);

        uint32_t sb  = sbase + (uint32_t)((s & 1) * STG_H) * 2u;
        uint32_t A_h = sb;
        uint32_t B_h = sb + TILE_H * 2u;
        uint32_t B_l = sb + 2u * TILE_H * 2u;

        #pragma unroll
        for (int kk = 0; kk < 32; kk += 16) {
            uint32_t bh[4][2], bl[4][2];
            #pragma unroll
            for (int p = 0; p < 2; p++) {
                int row = wn * 32 + p * 16 + l7 + ((lane & 16) >> 1);
                int kc  = kk + (lane & 8);
                uint32_t off = (uint32_t)(row * PK + kc) * 2u;
                ldm_x4(bh[2*p][0], bh[2*p][1], bh[2*p+1][0], bh[2*p+1][1], B_h + off);
                ldm_x4(bl[2*p][0], bl[2*p][1], bl[2*p+1][0], bl[2*p+1][1], B_l + off);
            }
            #pragma unroll
            for (int mi = 0; mi < 4; mi++) {
                int row = wm * 64 + mi * 16 + l7 + (lane & 8);
                int kc  = kk + ((lane & 16) >> 1);
                uint32_t off = (uint32_t)(row * PK + kc) * 2u;
                uint32_t ah0, ah1, ah2, ah3;
                ldm_x4(ah0, ah1, ah2, ah3, A_h + off);
                #pragma unroll
                for (int ni = 0; ni < 4; ni++) {
                    float* d = acc[mi][ni];
                    mma_f16(d[0], d[1], d[2], d[3], ah0, ah1, ah2, ah3, bh[ni][0], bh[ni][1]);
                    mma_f16(d[0], d[1], d[2], d[3], ah0, ah1, ah2, ah3, bl[ni][0], bl[ni][1]);
                }
            }
        }
    }

    // --- epilogue ---
    const float* bias = b0p;
    float* Cd = C;
    int csub = 0, Nw = N;
    if (EPI == EPI_QKV) {
        int sel = n0 >> 10;
        bias = (sel == 0) ? b0p : (sel == 1) ? b1p : b2p;
        Cd = C + (long)sel * BT * Dm;
        csub = sel << 10;
        Nw = Dm;
    }

    #pragma unroll
    for (int mi = 0; mi < 4; mi++) {
        int r0 = m0 + wm * 64 + mi * 16 + g;
        #pragma unroll
        for (int ni = 0; ni < 4; ni++) {
            int cc = n0 + wn * 32 + ni * 8 + 2 * t;
            float b0v = bias ? bias[cc - csub] : 0.f;
            float b1v = bias ? bias[cc - csub + 1] : 0.f;
            float v0 = acc[mi][ni][0] + b0v, v1 = acc[mi][ni][1] + b1v;
            float v2 = acc[mi][ni][2] + b0v, v3 = acc[mi][ni][3] + b1v;
            long i0 = (long)r0 * Nw + (cc - csub);
            long i1 = (long)(r0 + 8) * Nw + (cc - csub);
            if (EPI == EPI_ADD) {
                v0 += res[i0]; v1 += res[i0 + 1];
                v2 += res[i1]; v3 += res[i1 + 1];
            }
            if (EPI == EPI_GELU) {
                v0 = 0.5f * v0 * (1.f + erff(v0 * 0.70710678118654752f));
                v1 = 0.5f * v1 * (1.f + erff(v1 * 0.70710678118654752f));
                v2 = 0.5f * v2 * (1.f + erff(v2 * 0.70710678118654752f));
                v3 = 0.5f * v3 * (1.f + erff(v3 * 0.70710678118654752f));
                *(__half2*)(Ch + i0) = __halves2half2(__float2half_rn(v0), __float2half_rn(v1));
                *(__half2*)(Ch + i1) = __halves2half2(__float2half_rn(v2), __float2half_rn(v3));
            } else {
                *(float2*)(Cd + i0) = make_float2(v0, v1);
                *(float2*)(Cd + i1) = make_float2(v2, v3);
            }
        }
    }
}

// ---------------------------------------------------------------------------
// Flash attention (fp32, causal) with packed f32x2 FMA -> f16 output
// ---------------------------------------------------------------------------
#define APAD 68
#define ATT_SMEM_FLOATS (4 * 64 * APAD)

__global__ __launch_bounds__(256) void attn_kernel(
    const float* __restrict__ Q, const float* __restrict__ K,
    const float* __restrict__ V, __half* __restrict__ Y)
{
    extern __shared__ float smem[];
    float (*Qs)[APAD]  = (float (*)[APAD])(smem);
    float (*Kst)[APAD] = (float (*)[APAD])(smem + 64 * APAD);
    float (*Vs)[APAD]  = (float (*)[APAD])(smem + 2 * 64 * APAD);
    float (*Ps)[APAD]  = (float (*)[APAD])(smem + 3 * 64 * APAD);

    const int qt = blockIdx.x, h = blockIdx.y, b = blockIdx.z;
    const int tid = threadIdx.x;
    const int tx = tid & 15;
    const int ty = tid >> 4;

    const long baseq = ((long)(b * Tq + qt * 64)) * Dm + h * HD;

    for (int i = tid; i < 64 * 16; i += 256) {
        int r = i >> 4, c4 = (i & 15) << 2;
        float4 v = *(const float4*)(Q + baseq + (long)r * Dm + c4);
        Qs[r][c4] = v.x; Qs[r][c4 + 1] = v.y; Qs[r][c4 + 2] = v.z; Qs[r][c4 + 3] = v.w;
    }

    float m_i[4], l_i[4];
    unsigned long long o2[4][2];
    #pragma unroll
    for (int i = 0; i < 4; i++) {
        m_i[i] = -1e30f; l_i[i] = 0.f;
        o2[i][0] = 0ull; o2[i][1] = 0ull;
    }

    for (int kt = 0; kt <= qt; kt++) {
        const long basek = ((long)(b * Tq + kt * 64)) * Dm + h * HD;
        for (int i = tid; i < 64 * 16; i += 256) {
            int r = i >> 4, c4 = (i & 15) << 2;
            float4 kv = *(const float4*)(K + basek + (long)r * Dm + c4);
            Kst[c4][r] = kv.x; Kst[c4 + 1][r] = kv.y; Kst[c4 + 2][r] = kv.z; Kst[c4 + 3][r] = kv.w;
            float4 vv = *(const float4*)(V + basek + (long)r * Dm + c4);
            Vs[r][c4] = vv.x; Vs[r][c4 + 1] = vv.y; Vs[r][c4 + 2] = vv.z; Vs[r][c4 + 3] = vv.w;
        }
        __syncthreads();

        unsigned long long s2[4][2];
        #pragma unroll
        for (int i = 0; i < 4; i++) { s2[i][0] = 0ull; s2[i][1] = 0ull; }

        #pragma unroll 8
        for (int kk = 0; kk < 64; kk++) {
            ulonglong2 bb = *(const ulonglong2*)&Kst[kk][4 * tx];
            #pragma unroll
            for (int i = 0; i < 4; i++) {
                float a = Qs[4 * ty + i][kk];
                unsigned long long ap = pack2(a, a);
                FMA2(s2[i][0], ap, bb.x);
                FMA2(s2[i][1], ap, bb.y);
            }
        }

        float s[4][4];
        #pragma unroll
        for (int i = 0; i < 4; i++) {
            unpack2(s2[i][0], s[i][0], s[i][1]);
            unpack2(s2[i][1], s[i][2], s[i][3]);
        }

        const float scale = 0.125f;
        #pragma unroll
        for (int i = 0; i < 4; i++)
            #pragma unroll
            for (int j = 0; j < 4; j++) s[i][j] *= scale;

        if (kt == qt) {
            #pragma unroll
            for (int i = 0; i < 4; i++)
                #pragma unroll
                for (int j = 0; j < 4; j++)
                    if (4 * tx + j > 4 * ty + i) s[i][j] = -1e30f;
        }

        #pragma unroll
        for (int i = 0; i < 4; i++) {
            float rmax = fmaxf(fmaxf(s[i][0], s[i][1]), fmaxf(s[i][2], s[i][3]));
            #pragma unroll
            for (int m = 8; m; m >>= 1)
                rmax = fmaxf(rmax, __shfl_xor_sync(0xffffffffu, rmax, m));
            float mnew  = fmaxf(m_i[i], rmax);
            float alpha = expf(m_i[i] - mnew);
            m_i[i] = mnew;
            float rsum = 0.f;
            #pragma unroll
            for (int j = 0; j < 4; j++) {
                float p = expf(s[i][j] - mnew);
                s[i][j] = p;
                rsum += p;
            }
            #pragma unroll
            for (int m = 8; m; m >>= 1)
                rsum += __shfl_xor_sync(0xffffffffu, rsum, m);
            l_i[i] = l_i[i] * alpha + rsum;
            unsigned long long apk = pack2(alpha, alpha);
            MUL2(o2[i][0], o2[i][0], apk);
            MUL2(o2[i][1], o2[i][1], apk);
        }

        #pragma unroll
        for (int i = 0; i < 4; i++)
            #pragma unroll
            for (int j = 0; j < 4; j++)
                Ps[4 * ty + i][4 * tx + j] = s[i][j];
        __syncthreads();

        #pragma unroll 8
        for (int kk = 0; kk < 64; kk++) {
            ulonglong2 bb = *(const ulonglong2*)&Vs[kk][4 * tx];
            #pragma unroll
            for (int i = 0; i < 4; i++) {
                float a = Ps[4 * ty + i][kk];
                unsigned long long ap = pack2(a, a);
                FMA2(o2[i][0], ap, bb.x);
                FMA2(o2[i][1], ap, bb.y);
            }
        }
        __syncthreads();
    }

    #pragma unroll
    for (int i = 0; i < 4; i++) {
        float inv = 1.f / l_i[i];
        float o0, o1, oo2, o3;
        unpack2(o2[i][0], o0, o1);
        unpack2(o2[i][1], oo2, o3);
        long orow = baseq + (long)(4 * ty + i) * Dm + 4 * tx;
        *(__half2*)(Y + orow)     = __halves2half2(__float2half_rn(o0 * inv),
                                                    __float2half_rn(o1 * inv));
        *(__half2*)(Y + orow + 2) = __halves2half2(__float2half_rn(oo2 * inv),
                                                    __float2half_rn(o3 * inv));
    }
}

// ---------------------------------------------------------------------------
// Launcher (ordered so layer-0 QKV GEMM lands at global launch idx 5 for ncu)
// ---------------------------------------------------------------------------
extern "C" void kernel_launch(void* const* d_in, const int* in_sizes, int n_in,
                              void* d_out, int out_size)
{
    const int*   idx  = (const int*)  d_in[0];
    const int*   ts   = (const int*)  d_in[1];
    const float* tok  = (const float*)d_in[2];
    const float* pos  = (const float*)d_in[3];
    const float* gpos = (const float*)d_in[4];
    const float* ln1w = (const float*)d_in[5];
    const float* ln1b = (const float*)d_in[6];
    const float* Wq   = (const float*)d_in[7];
    const float* bq   = (const float*)d_in[8];
    const float* Wk   = (const float*)d_in[9];
    const float* bk   = (const float*)d_in[10];
    const float* Wv   = (const float*)d_in[11];
    const float* bv   = (const float*)d_in[12];
    const float* Wo   = (const float*)d_in[13];
    const float* bo   = (const float*)d_in[14];
    const float* ln2w = (const float*)d_in[15];
    const float* ln2b = (const float*)d_in[16];
    const float* W1   = (const float*)d_in[17];
    const float* b1   = (const float*)d_in[18];
    const float* W2   = (const float*)d_in[19];
    const float* b2   = (const float*)d_in[20];
    const float* lnfw = (const float*)d_in[21];
    const float* lnfb = (const float*)d_in[22];
    const float* hw   = (const float*)d_in[23];
    float* out = (float*)d_out;

    float *x, *qkv;
    __half *pa, *pb, *wh, *wl;
    cudaGetSymbolAddress((void**)&x,   g_x);
    cudaGetSymbolAddress((void**)&qkv, g_qkv);
    cudaGetSymbolAddress((void**)&pa,  g_pa);
    cudaGetSymbolAddress((void**)&pb,  g_pb);
    cudaGetSymbolAddress((void**)&wh,  g_wh);
    cudaGetSymbolAddress((void**)&wl,  g_wl);

    cudaFuncSetAttribute(attn_kernel, cudaFuncAttributeMaxDynamicSharedMemorySize,
                         ATT_SMEM_FLOATS * (int)sizeof(float));
    cudaFuncSetAttribute(gemm_hmma<EPI_QKV>,  cudaFuncAttributeMaxDynamicSharedMemorySize, GEMM_SMEM);
    cudaFuncSetAttribute(gemm_hmma<EPI_ADD>,  cudaFuncAttributeMaxDynamicSharedMemorySize, GEMM_SMEM);
    cudaFuncSetAttribute(gemm_hmma<EPI_GELU>, cudaFuncAttributeMaxDynamicSharedMemorySize, GEMM_SMEM);
    cudaFuncSetAttribute(gemm_hmma<EPI_NONE>, cudaFuncAttributeMaxDynamicSharedMemorySize, GEMM_SMEM);

    auto cvt = [&](const float* src, long off, long n) {
        cvt_pair<<<(int)((n / 4 + 255) / 256), 256>>>(src, wh + off, wl + off, n);
    };

    const dim3 gD(Dm / 128, BT / 128);
    const dim3 gQKV(3 * Dm / 128, BT / 128);
    const dim3 g2D(2 * Dm / 128, BT / 128);
    const dim3 gV(Vv / 128, BT / 128);

    float* qb = qkv;
    float* kb = qkv + (long)BT * Dm;
    float* vb = qkv + 2L * BT * Dm;

    // launches 1-3: QKV weight conversion; 4: fused embed+LN0; 5: QKV GEMM
    cvt(Wq, OFF_WQ, 8L * DD);
    cvt(Wk, OFF_WK, 8L * DD);
    cvt(Wv, OFF_WV, 8L * DD);
    embed_ln<<<BT, 256>>>(idx, ts, tok, pos, gpos, ln1w, ln1b, x, pa);

    bool cvted = false;

    for (int l = 0; l < Ll; l++) {
        if (l > 0)
            layernorm_f16<<<BT, 256>>>(x, ln1w + (long)l * Dm, ln1b + (long)l * Dm, pa);

        gemm_hmma<EPI_QKV><<<gQKV, 256, GEMM_SMEM>>>(
            pa, wh + OFF_WQ + (long)l * DD, wl + OFF_WQ + (long)l * DD,
            8L * DD,
            bq + (long)l * Dm, bk + (long)l * Dm, bv + (long)l * Dm,
            nullptr, qkv, nullptr, BT, 3 * Dm, Dm);

        attn_kernel<<<dim3(Tq / 64, Hh, Bq), 256,
                      ATT_SMEM_FLOATS * sizeof(float)>>>(qb, kb, vb, pa);

        if (!cvted) cvt(Wo, OFF_WO, 8L * DD);

        gemm_hmma<EPI_ADD><<<gD, 256, GEMM_SMEM>>>(
            pa, wh + OFF_WO + (long)l * DD, wl + OFF_WO + (long)l * DD, 0,
            bo + (long)l * Dm, nullptr, nullptr, x, x, nullptr, BT, Dm, Dm);

        layernorm_f16<<<BT, 256>>>(x, ln2w + (long)l * Dm, ln2b + (long)l * Dm, pa);

        if (!cvted) cvt(W1, OFF_W1, 16L * DD);

        gemm_hmma<EPI_GELU><<<g2D, 256, GEMM_SMEM>>>(
            pa, wh + OFF_W1 + (long)l * 2 * DD, wl + OFF_W1 + (long)l * 2 * DD, 0,
            b1 + (long)l * 2 * Dm, nullptr, nullptr, nullptr,
            nullptr, pb, BT, 2 * Dm, Dm);

        if (!cvted) { cvt(W2, OFF_W2, 16L * DD); cvted = true; }

        gemm_hmma<EPI_ADD><<<gD, 256, GEMM_SMEM>>>(
            pb, wh + OFF_W2 + (long)l * 2 * DD, wl + OFF_W2 + (long)l * 2 * DD, 0,
            b2 + (long)l * Dm, nullptr, nullptr, x, x, nullptr, BT, Dm, 2 * Dm);
    }

    layernorm_f16<<<BT, 256>>>(x, lnfw, lnfb, pa);
    cvt(hw, OFF_HW, 8L * DD);
    gemm_hmma<EPI_NONE><<<gV, 256, GEMM_SMEM>>>(
        pa, wh + OFF_HW, wl + OFF_HW, 0,
        nullptr, nullptr, nullptr, nullptr, out, nullptr, BT, Vv, Dm);
}

// round 12
// speedup vs baseline: 3.6996x; 1.4631x over previous
#include <cuda_runtime.h>
#include <cuda_fp16.h>
#include <math.h>
#include <stdint.h>

// ---------------------------------------------------------------------------
// Problem constants
// ---------------------------------------------------------------------------
#define Bq   8
#define Tq   1024
#define Dm   1024
#define Hh   16
#define Ll   8
#define Vv   8192
#define HD   64
#define BT   (Bq*Tq)

// ---------------------------------------------------------------------------
// Scratch (static device globals)
// ---------------------------------------------------------------------------
__device__ float  g_x[BT * Dm];          // residual stream (f32)
__device__ __half g_qkvh[3L * BT * Dm];  // q | k | v  (f16)

__device__ __half g_pa[BT * Dm];         // act buf A: LN out / attn out
__device__ __half g_pb[BT * 2 * Dm];     // act buf B: MLP hidden

#define DD      (Dm*Dm)
#define OFF_WQ  0L
#define OFF_WK  (8L*DD)
#define OFF_WV  (16L*DD)
#define OFF_WO  (24L*DD)
#define OFF_W1  (32L*DD)
#define OFF_W2  (48L*DD)
#define OFF_HW  (64L*DD)
#define WTOT    (72L*DD)
__device__ __half g_wh[WTOT];
__device__ __half g_wl[WTOT];

// ---------------------------------------------------------------------------
// Helpers
// ---------------------------------------------------------------------------
__device__ __forceinline__ uint32_t smem_u32(const void* p) {
    uint32_t a;
    asm("{ .reg .u64 t; cvta.to.shared.u64 t, %1; cvt.u32.u64 %0, t; }"
        : "=r"(a) : "l"(p));
    return a;
}
__device__ __forceinline__ void cpa16(uint32_t dst, const void* src) {
    asm volatile("cp.async.cg.shared.global [%0], [%1], 16;" :: "r"(dst), "l"(src));
}
__device__ __forceinline__ void ldm_x4(uint32_t& r0, uint32_t& r1,
                                       uint32_t& r2, uint32_t& r3, uint32_t addr) {
    asm volatile("ldmatrix.sync.aligned.m8n8.x4.shared.b16 {%0,%1,%2,%3}, [%4];"
                 : "=r"(r0), "=r"(r1), "=r"(r2), "=r"(r3) : "r"(addr));
}
__device__ __forceinline__ void ldm_x4t(uint32_t& r0, uint32_t& r1,
                                        uint32_t& r2, uint32_t& r3, uint32_t addr) {
    asm volatile("ldmatrix.sync.aligned.m8n8.x4.trans.shared.b16 {%0,%1,%2,%3}, [%4];"
                 : "=r"(r0), "=r"(r1), "=r"(r2), "=r"(r3) : "r"(addr));
}
__device__ __forceinline__ void mma_f16(float& d0, float& d1, float& d2, float& d3,
                                        uint32_t a0, uint32_t a1, uint32_t a2, uint32_t a3,
                                        uint32_t b0, uint32_t b1) {
    asm volatile(
        "mma.sync.aligned.m16n8k16.row.col.f32.f16.f16.f32 "
        "{%0,%1,%2,%3}, {%4,%5,%6,%7}, {%8,%9}, {%0,%1,%2,%3};"
        : "+f"(d0), "+f"(d1), "+f"(d2), "+f"(d3)
        : "r"(a0), "r"(a1), "r"(a2), "r"(a3), "r"(b0), "r"(b1));
}
__device__ __forceinline__ void split16(float x, __half& hi, __half& lo) {
    hi = __float2half_rn(x);
    lo = __float2half_rn(x - __half2float(hi));
}
__device__ __forceinline__ uint32_t packh2(float a, float b) {
    __half2 h = __halves2half2(__float2half_rn(a), __float2half_rn(b));
    return *(uint32_t*)&h;
}

// ---------------------------------------------------------------------------
// Weight f32 -> f16 hi/lo pair conversion
// ---------------------------------------------------------------------------
__global__ __launch_bounds__(256) void cvt_pair(
    const float* __restrict__ s, __half* __restrict__ h,
    __half* __restrict__ l, long n)
{
    long i = ((long)blockIdx.x * 256 + threadIdx.x) * 4;
    if (i >= n) return;
    float4 v = *(const float4*)(s + i);
    __half h0, h1, h2, h3, l0, l1, l2, l3;
    split16(v.x, h0, l0); split16(v.y, h1, l1);
    split16(v.z, h2, l2); split16(v.w, h3, l3);
    *(__half2*)(h + i)     = __halves2half2(h0, h1);
    *(__half2*)(h + i + 2) = __halves2half2(h2, h3);
    *(__half2*)(l + i)     = __halves2half2(l0, l1);
    *(__half2*)(l + i + 2) = __halves2half2(l2, l3);
}

// ---------------------------------------------------------------------------
// Fused embedding + LayerNorm(layer0 ln1) -> x and f16 output
// ---------------------------------------------------------------------------
__global__ __launch_bounds__(256) void embed_ln(
    const int* __restrict__ idx, const int* __restrict__ ts,
    const float* __restrict__ tok, const float* __restrict__ pos,
    const float* __restrict__ gpos,
    const float* __restrict__ w, const float* __restrict__ b,
    float* __restrict__ X, __half* __restrict__ Y)
{
    int row = blockIdx.x;
    int t = row & (Tq - 1);
    int bb = row >> 10;
    int tid = threadIdx.x;
    int i = tid * 4;

    float4 tv = *(const float4*)(tok + (long)idx[row] * Dm + i);
    float4 gv = *(const float4*)(gpos + (long)ts[bb] * Dm + i);
    float4 pv = *(const float4*)(pos + (long)t * Dm + i);
    float4 v;
    v.x = tv.x + gv.x + pv.x;
    v.y = tv.y + gv.y + pv.y;
    v.z = tv.z + gv.z + pv.z;
    v.w = tv.w + gv.w + pv.w;

    long base = (long)row * Dm + i;
    *(float4*)(X + base) = v;

    float s  = v.x + v.y + v.z + v.w;
    float ss = v.x*v.x + v.y*v.y + v.z*v.z + v.w*v.w;

    __shared__ float rs[8], rss[8];
    #pragma unroll
    for (int m = 16; m; m >>= 1) {
        s  += __shfl_xor_sync(0xffffffffu, s,  m);
        ss += __shfl_xor_sync(0xffffffffu, ss, m);
    }
    int wid = tid >> 5, lane = tid & 31;
    if (lane == 0) { rs[wid] = s; rss[wid] = ss; }
    __syncthreads();
    if (wid == 0) {
        s  = (lane < 8) ? rs[lane]  : 0.f;
        ss = (lane < 8) ? rss[lane] : 0.f;
        #pragma unroll
        for (int m = 4; m; m >>= 1) {
            s  += __shfl_xor_sync(0xffffffffu, s,  m);
            ss += __shfl_xor_sync(0xffffffffu, ss, m);
        }
        if (lane == 0) { rs[0] = s; rss[0] = ss; }
    }
    __syncthreads();
    float mean = rs[0] * (1.0f / Dm);
    float var  = rss[0] * (1.0f / Dm) - mean * mean;
    float rstd = rsqrtf(var + 1e-5f);

    float4 wv = *(const float4*)(w + i);
    float4 bv = *(const float4*)(b + i);
    float o0 = (v.x - mean) * rstd * wv.x + bv.x;
    float o1 = (v.y - mean) * rstd * wv.y + bv.y;
    float o2 = (v.z - mean) * rstd * wv.z + bv.z;
    float o3 = (v.w - mean) * rstd * wv.w + bv.w;

    *(__half2*)(Y + base)     = __halves2half2(__float2half_rn(o0), __float2half_rn(o1));
    *(__half2*)(Y + base + 2) = __halves2half2(__float2half_rn(o2), __float2half_rn(o3));
}

// ---------------------------------------------------------------------------
// LayerNorm -> f16 output
// ---------------------------------------------------------------------------
__global__ __launch_bounds__(256) void layernorm_f16(
    const float* __restrict__ X, const float* __restrict__ w,
    const float* __restrict__ b, __half* __restrict__ Y)
{
    int row = blockIdx.x;
    const float* x = X + (long)row * Dm;
    int tid = threadIdx.x;

    int i = tid * 4;
    float4 v = *(const float4*)(x + i);
    float s  = v.x + v.y + v.z + v.w;
    float ss = v.x*v.x + v.y*v.y + v.z*v.z + v.w*v.w;

    __shared__ float rs[8], rss[8];
    #pragma unroll
    for (int m = 16; m; m >>= 1) {
        s  += __shfl_xor_sync(0xffffffffu, s,  m);
        ss += __shfl_xor_sync(0xffffffffu, ss, m);
    }
    int wid = tid >> 5, lane = tid & 31;
    if (lane == 0) { rs[wid] = s; rss[wid] = ss; }
    __syncthreads();
    if (wid == 0) {
        s  = (lane < 8) ? rs[lane]  : 0.f;
        ss = (lane < 8) ? rss[lane] : 0.f;
        #pragma unroll
        for (int m = 4; m; m >>= 1) {
            s  += __shfl_xor_sync(0xffffffffu, s,  m);
            ss += __shfl_xor_sync(0xffffffffu, ss, m);
        }
        if (lane == 0) { rs[0] = s; rss[0] = ss; }
    }
    __syncthreads();
    float mean = rs[0] * (1.0f / Dm);
    float var  = rss[0] * (1.0f / Dm) - mean * mean;
    float rstd = rsqrtf(var + 1e-5f);

    float4 wv = *(const float4*)(w + i);
    float4 bv = *(const float4*)(b + i);
    float o0 = (v.x - mean) * rstd * wv.x + bv.x;
    float o1 = (v.y - mean) * rstd * wv.y + bv.y;
    float o2 = (v.z - mean) * rstd * wv.z + bv.z;
    float o3 = (v.w - mean) * rstd * wv.w + bv.w;

    long base = (long)row * Dm + i;
    *(__half2*)(Y + base)     = __halves2half2(__float2half_rn(o0), __float2half_rn(o1));
    *(__half2*)(Y + base + 2) = __halves2half2(__float2half_rn(o2), __float2half_rn(o3));
}

// ---------------------------------------------------------------------------
// HMMA GEMM, 2-term split: C = Ah·Bh + Ah·Bl (+bias)(+res | gelu | ->f16 qkv).
// CTA 128x128, k-step 32, cp.async double buffer, 8 warps of 64x32.
// ---------------------------------------------------------------------------
#define EPI_NONE 0
#define EPI_ADD  1
#define EPI_GELU 2
#define EPI_QKV  3

#define PK      40
#define TILE_H  (128*PK)
#define STG_H   (3*TILE_H)
#define GEMM_SMEM (2*STG_H*2)

template<int EPI>
__global__ __launch_bounds__(256, 2) void gemm_hmma(
    const __half* __restrict__ Ah,
    const __half* __restrict__ Bh, const __half* __restrict__ Bl,
    long bStride,
    const float* __restrict__ b0p, const float* __restrict__ b1p,
    const float* __restrict__ b2p, const float* __restrict__ res,
    float* __restrict__ C, __half* __restrict__ Ch,
    int M, int N, int K)
{
    extern __shared__ __align__(16) __half gsm[];
    const uint32_t sbase = smem_u32(gsm);

    const int tid = threadIdx.x, lane = tid & 31, warp = tid >> 5;
    const int g = lane >> 2, t = lane & 3, l7 = lane & 7;
    const int wm = warp & 1, wn = warp >> 1;
    const int m0 = blockIdx.y * 128, n0 = blockIdx.x * 128;

    float acc[4][4][4];
    #pragma unroll
    for (int a = 0; a < 4; a++)
        #pragma unroll
        for (int b = 0; b < 4; b++)
            #pragma unroll
            for (int c = 0; c < 4; c++) acc[a][b][c] = 0.f;

    const int S = K >> 5;

    auto issue = [&](int k0, int buf) {
        #pragma unroll
        for (int j = 0; j < 6; j++) {
            int c = tid + 256 * j;
            int tile = c >> 9;
            int r = (c >> 2) & 127;
            int q = c & 3;
            const __half* src;
            if (tile == 0) src = Ah + (long)(m0 + r) * K + k0 + q * 8;
            else {
                long roff;
                if (EPI == EPI_QKV) {
                    int rg = n0 + r;
                    roff = (long)(rg >> 10) * bStride + (long)(rg & 1023) * K;
                } else {
                    roff = (long)(n0 + r) * K;
                }
                src = (tile == 1 ? Bh : Bl) + roff + k0 + q * 8;
            }
            uint32_t dst = sbase + (uint32_t)(buf * STG_H + tile * TILE_H + r * PK + q * 8) * 2u;
            cpa16(dst, src);
        }
        asm volatile("cp.async.commit_group;" ::: "memory");
    };

    issue(0, 0);

    for (int s = 0; s < S; s++) {
        asm volatile("cp.async.wait_group 0;" ::: "memory");
        __syncthreads();
        if (s + 1 < S) issue((s + 1) << 5, (s + 1) & 1);

        uint32_t sb  = sbase + (uint32_t)((s & 1) * STG_H) * 2u;
        uint32_t A_h = sb;
        uint32_t B_h = sb + TILE_H * 2u;
        uint32_t B_l = sb + 2u * TILE_H * 2u;

        #pragma unroll
        for (int kk = 0; kk < 32; kk += 16) {
            uint32_t bh[4][2], bl[4][2];
            #pragma unroll
            for (int p = 0; p < 2; p++) {
                int row = wn * 32 + p * 16 + l7 + ((lane & 16) >> 1);
                int kc  = kk + (lane & 8);
                uint32_t off = (uint32_t)(row * PK + kc) * 2u;
                ldm_x4(bh[2*p][0], bh[2*p][1], bh[2*p+1][0], bh[2*p+1][1], B_h + off);
                ldm_x4(bl[2*p][0], bl[2*p][1], bl[2*p+1][0], bl[2*p+1][1], B_l + off);
            }
            #pragma unroll
            for (int mi = 0; mi < 4; mi++) {
                int row = wm * 64 + mi * 16 + l7 + (lane & 8);
                int kc  = kk + ((lane & 16) >> 1);
                uint32_t off = (uint32_t)(row * PK + kc) * 2u;
                uint32_t ah0, ah1, ah2, ah3;
                ldm_x4(ah0, ah1, ah2, ah3, A_h + off);
                #pragma unroll
                for (int ni = 0; ni < 4; ni++) {
                    float* d = acc[mi][ni];
                    mma_f16(d[0], d[1], d[2], d[3], ah0, ah1, ah2, ah3, bh[ni][0], bh[ni][1]);
                    mma_f16(d[0], d[1], d[2], d[3], ah0, ah1, ah2, ah3, bl[ni][0], bl[ni][1]);
                }
            }
        }
    }

    // --- epilogue ---
    const float* bias = b0p;
    float* Cd = C;
    __half* Chd = Ch;
    int csub = 0, Nw = N;
    if (EPI == EPI_QKV) {
        int sel = n0 >> 10;
        bias = (sel == 0) ? b0p : (sel == 1) ? b1p : b2p;
        Chd = Ch + (long)sel * BT * Dm;
        csub = sel << 10;
        Nw = Dm;
    }

    #pragma unroll
    for (int mi = 0; mi < 4; mi++) {
        int r0 = m0 + wm * 64 + mi * 16 + g;
        #pragma unroll
        for (int ni = 0; ni < 4; ni++) {
            int cc = n0 + wn * 32 + ni * 8 + 2 * t;
            float b0v = bias ? bias[cc - csub] : 0.f;
            float b1v = bias ? bias[cc - csub + 1] : 0.f;
            float v0 = acc[mi][ni][0] + b0v, v1 = acc[mi][ni][1] + b1v;
            float v2 = acc[mi][ni][2] + b0v, v3 = acc[mi][ni][3] + b1v;
            long i0 = (long)r0 * Nw + (cc - csub);
            long i1 = (long)(r0 + 8) * Nw + (cc - csub);
            if (EPI == EPI_ADD) {
                v0 += res[i0]; v1 += res[i0 + 1];
                v2 += res[i1]; v3 += res[i1 + 1];
            }
            if (EPI == EPI_GELU) {
                v0 = 0.5f * v0 * (1.f + erff(v0 * 0.70710678118654752f));
                v1 = 0.5f * v1 * (1.f + erff(v1 * 0.70710678118654752f));
                v2 = 0.5f * v2 * (1.f + erff(v2 * 0.70710678118654752f));
                v3 = 0.5f * v3 * (1.f + erff(v3 * 0.70710678118654752f));
            }
            if (EPI == EPI_GELU || EPI == EPI_QKV) {
                *(__half2*)(Chd + i0) = __halves2half2(__float2half_rn(v0), __float2half_rn(v1));
                *(__half2*)(Chd + i1) = __halves2half2(__float2half_rn(v2), __float2half_rn(v3));
            } else {
                *(float2*)(Cd + i0) = make_float2(v0, v1);
                *(float2*)(Cd + i1) = make_float2(v2, v3);
            }
        }
    }
}

// ---------------------------------------------------------------------------
// Flash attention (HMMA, causal). q/k/v f16 inputs (qkvh), f16 output.
// Block = 128 q rows (8 warps x 16), K/V tiles of 64 tokens.
// smem rows padded to 72 halfs (144B, 16B-aligned, ldmatrix conflict-free).
// ---------------------------------------------------------------------------
#define APD 72
#define ATT_SMEM ((128 + 64 + 64) * APD * 2)

__global__ __launch_bounds__(256, 2) void attn_hmma(
    const __half* __restrict__ Qg, const __half* __restrict__ Kg,
    const __half* __restrict__ Vg, __half* __restrict__ Y)
{
    extern __shared__ __align__(16) __half asmem[];
    const uint32_t sb = smem_u32(asmem);
    const uint32_t Qs = sb;
    const uint32_t Ks = sb + 128 * APD * 2;
    const uint32_t Vs = Ks + 64 * APD * 2;

    const int qt = blockIdx.x, h = blockIdx.y, b = blockIdx.z;
    const int tid = threadIdx.x, lane = tid & 31, warp = tid >> 5;
    const int g = lane >> 2, c2 = (lane & 3) * 2;

    const long rowbase = (long)(b * Tq + qt * 128);
    const __half* qsrc = Qg + rowbase * Dm + h * HD;

    // load Q tile 128x64 f16
    #pragma unroll
    for (int j = 0; j < 4; j++) {
        int c = tid + 256 * j;               // 1024 chunks
        int r = c >> 3, col8 = (c & 7) * 8;
        cpa16(Qs + (uint32_t)(r * APD + col8) * 2u, qsrc + (long)r * Dm + col8);
    }
    asm volatile("cp.async.commit_group;" ::: "memory");
    asm volatile("cp.async.wait_group 0;" ::: "memory");
    __syncthreads();

    // Q fragments (warp's 16 rows x 64 hd)
    uint32_t qf[4][4];
    #pragma unroll
    for (int kf = 0; kf < 4; kf++) {
        uint32_t addr = Qs + (uint32_t)((warp * 16 + (lane & 15)) * APD
                                        + kf * 16 + ((lane >> 4) & 1) * 8) * 2u;
        ldm_x4(qf[kf][0], qf[kf][1], qf[kf][2], qf[kf][3], addr);
    }

    const int r0g = qt * 128 + warp * 16 + g;   // global q row (and +8)
    const int q_hi = qt * 128 + warp * 16 + 15;

    float O[8][4];
    #pragma unroll
    for (int nf = 0; nf < 8; nf++)
        #pragma unroll
        for (int j = 0; j < 4; j++) O[nf][j] = 0.f;
    float m0 = -1e30f, m1 = -1e30f, l0 = 0.f, l1 = 0.f;

    const int ktmax = qt * 2 + 1;
    for (int kt = 0; kt <= ktmax; kt++) {
        // load K/V tiles (64x64 each)
        const __half* ksrc = Kg + (rowbase - qt * 128 + (long)(qt * 0)) * 0; // unused
        const long krow = (long)(b * Tq + kt * 64);
        #pragma unroll
        for (int j = 0; j < 4; j++) {
            int c = tid + 256 * j;            // 1024 chunks: 512 K + 512 V
            int tsel = c >> 9;
            int r = (c >> 3) & 63, col8 = (c & 7) * 8;
            const __half* src = (tsel ? Vg : Kg) + (krow + r) * (long)Dm + h * HD + col8;
            uint32_t dst = (tsel ? Vs : Ks) + (uint32_t)(r * APD + col8) * 2u;
            cpa16(dst, src);
        }
        asm volatile("cp.async.commit_group;" ::: "memory");
        asm volatile("cp.async.wait_group 0;" ::: "memory");
        __syncthreads();

        if (kt * 64 <= q_hi) {
            // ---- S = Q K^T ----
            float S[8][4];
            #pragma unroll
            for (int nf = 0; nf < 8; nf++)
                #pragma unroll
                for (int j = 0; j < 4; j++) S[nf][j] = 0.f;

            #pragma unroll
            for (int tg = 0; tg < 4; tg++) {
                #pragma unroll
                for (int kf = 0; kf < 4; kf++) {
                    uint32_t k0, k1, k2, k3;
                    uint32_t addr = Ks + (uint32_t)((tg * 16 + (lane & 15)) * APD
                                                    + kf * 16 + ((lane >> 4) & 1) * 8) * 2u;
                    ldm_x4(k0, k1, k2, k3, addr);
                    mma_f16(S[2*tg][0], S[2*tg][1], S[2*tg][2], S[2*tg][3],
                            qf[kf][0], qf[kf][1], qf[kf][2], qf[kf][3], k0, k2);
                    mma_f16(S[2*tg+1][0], S[2*tg+1][1], S[2*tg+1][2], S[2*tg+1][3],
                            qf[kf][0], qf[kf][1], qf[kf][2], qf[kf][3], k1, k3);
                }
            }

            const float scale = 0.125f;
            #pragma unroll
            for (int nf = 0; nf < 8; nf++)
                #pragma unroll
                for (int j = 0; j < 4; j++) S[nf][j] *= scale;

            if (kt * 64 + 63 > r0g) {       // diagonal tile: mask col > row
                #pragma unroll
                for (int nf = 0; nf < 8; nf++) {
                    int col = kt * 64 + nf * 8 + c2;
                    if (col     > r0g)     S[nf][0] = -1e30f;
                    if (col + 1 > r0g)     S[nf][1] = -1e30f;
                    if (col     > r0g + 8) S[nf][2] = -1e30f;
                    if (col + 1 > r0g + 8) S[nf][3] = -1e30f;
                }
            }

            // ---- online softmax (rows r0g, r0g+8 per quad) ----
            float rmax0 = -1e30f, rmax1 = -1e30f;
            #pragma unroll
            for (int nf = 0; nf < 8; nf++) {
                rmax0 = fmaxf(rmax0, fmaxf(S[nf][0], S[nf][1]));
                rmax1 = fmaxf(rmax1, fmaxf(S[nf][2], S[nf][3]));
            }
            #pragma unroll
            for (int m = 1; m <= 2; m <<= 1) {
                rmax0 = fmaxf(rmax0, __shfl_xor_sync(0xffffffffu, rmax0, m));
                rmax1 = fmaxf(rmax1, __shfl_xor_sync(0xffffffffu, rmax1, m));
            }
            float mn0 = fmaxf(m0, rmax0), mn1 = fmaxf(m1, rmax1);
            float a0 = __expf(m0 - mn0), a1 = __expf(m1 - mn1);
            m0 = mn0; m1 = mn1;

            float rs0 = 0.f, rs1 = 0.f;
            uint32_t pa[4][4];
            #pragma unroll
            for (int nf = 0; nf < 8; nf++) {
                float p0 = __expf(S[nf][0] - mn0);
                float p1 = __expf(S[nf][1] - mn0);
                float p2 = __expf(S[nf][2] - mn1);
                float p3 = __expf(S[nf][3] - mn1);
                rs0 += p0 + p1; rs1 += p2 + p3;
                pa[nf >> 1][(nf & 1) * 2 + 0] = packh2(p0, p1);
                pa[nf >> 1][(nf & 1) * 2 + 1] = packh2(p2, p3);
            }
            #pragma unroll
            for (int m = 1; m <= 2; m <<= 1) {
                rs0 += __shfl_xor_sync(0xffffffffu, rs0, m);
                rs1 += __shfl_xor_sync(0xffffffffu, rs1, m);
            }
            l0 = l0 * a0 + rs0;
            l1 = l1 * a1 + rs1;
            #pragma unroll
            for (int nf = 0; nf < 8; nf++) {
                O[nf][0] *= a0; O[nf][1] *= a0;
                O[nf][2] *= a1; O[nf][3] *= a1;
            }

            // ---- O += P V ----
            #pragma unroll
            for (int kf = 0; kf < 4; kf++) {
                #pragma unroll
                for (int hg = 0; hg < 4; hg++) {
                    uint32_t v0, v1, v2, v3;
                    uint32_t addr = Vs + (uint32_t)((kf * 16 + (lane & 15)) * APD
                                                    + hg * 16 + ((lane >> 4) & 1) * 8) * 2u;
                    ldm_x4t(v0, v1, v2, v3, addr);
                    mma_f16(O[2*hg][0], O[2*hg][1], O[2*hg][2], O[2*hg][3],
                            pa[kf][0], pa[kf][1], pa[kf][2], pa[kf][3], v0, v1);
                    mma_f16(O[2*hg+1][0], O[2*hg+1][1], O[2*hg+1][2], O[2*hg+1][3],
                            pa[kf][0], pa[kf][1], pa[kf][2], pa[kf][3], v2, v3);
                }
            }
        }
        __syncthreads();
    }

    float inv0 = 1.f / l0, inv1 = 1.f / l1;
    long ybase0 = (rowbase + warp * 16 + g) * (long)Dm + h * HD;
    long ybase1 = ybase0 + 8L * Dm;
    #pragma unroll
    for (int nf = 0; nf < 8; nf++) {
        int col = nf * 8 + c2;
        *(__half2*)(Y + ybase0 + col) =
            __halves2half2(__float2half_rn(O[nf][0] * inv0), __float2half_rn(O[nf][1] * inv0));
        *(__half2*)(Y + ybase1 + col) =
            __halves2half2(__float2half_rn(O[nf][2] * inv1), __float2half_rn(O[nf][3] * inv1));
    }
}

// ---------------------------------------------------------------------------
// Launcher
// ---------------------------------------------------------------------------
extern "C" void kernel_launch(void* const* d_in, const int* in_sizes, int n_in,
                              void* d_out, int out_size)
{
    const int*   idx  = (const int*)  d_in[0];
    const int*   ts   = (const int*)  d_in[1];
    const float* tok  = (const float*)d_in[2];
    const float* pos  = (const float*)d_in[3];
    const float* gpos = (const float*)d_in[4];
    const float* ln1w = (const float*)d_in[5];
    const float* ln1b = (const float*)d_in[6];
    const float* Wq   = (const float*)d_in[7];
    const float* bq   = (const float*)d_in[8];
    const float* Wk   = (const float*)d_in[9];
    const float* bk   = (const float*)d_in[10];
    const float* Wv   = (const float*)d_in[11];
    const float* bv   = (const float*)d_in[12];
    const float* Wo   = (const float*)d_in[13];
    const float* bo   = (const float*)d_in[14];
    const float* ln2w = (const float*)d_in[15];
    const float* ln2b = (const float*)d_in[16];
    const float* W1   = (const float*)d_in[17];
    const float* b1   = (const float*)d_in[18];
    const float* W2   = (const float*)d_in[19];
    const float* b2   = (const float*)d_in[20];
    const float* lnfw = (const float*)d_in[21];
    const float* lnfb = (const float*)d_in[22];
    const float* hw   = (const float*)d_in[23];
    float* out = (float*)d_out;

    float* x;
    __half *qkvh, *pa, *pb, *wh, *wl;
    cudaGetSymbolAddress((void**)&x,    g_x);
    cudaGetSymbolAddress((void**)&qkvh, g_qkvh);
    cudaGetSymbolAddress((void**)&pa,   g_pa);
    cudaGetSymbolAddress((void**)&pb,   g_pb);
    cudaGetSymbolAddress((void**)&wh,   g_wh);
    cudaGetSymbolAddress((void**)&wl,   g_wl);

    cudaFuncSetAttribute(attn_hmma, cudaFuncAttributeMaxDynamicSharedMemorySize, ATT_SMEM);
    cudaFuncSetAttribute(gemm_hmma<EPI_QKV>,  cudaFuncAttributeMaxDynamicSharedMemorySize, GEMM_SMEM);
    cudaFuncSetAttribute(gemm_hmma<EPI_ADD>,  cudaFuncAttributeMaxDynamicSharedMemorySize, GEMM_SMEM);
    cudaFuncSetAttribute(gemm_hmma<EPI_GELU>, cudaFuncAttributeMaxDynamicSharedMemorySize, GEMM_SMEM);
    cudaFuncSetAttribute(gemm_hmma<EPI_NONE>, cudaFuncAttributeMaxDynamicSharedMemorySize, GEMM_SMEM);

    auto cvt = [&](const float* src, long off, long n) {
        cvt_pair<<<(int)((n / 4 + 255) / 256), 256>>>(src, wh + off, wl + off, n);
    };

    const dim3 gD(Dm / 128, BT / 128);
    const dim3 gQKV(3 * Dm / 128, BT / 128);
    const dim3 g2D(2 * Dm / 128, BT / 128);
    const dim3 gV(Vv / 128, BT / 128);

    __half* qb = qkvh;
    __half* kb = qkvh + (long)BT * Dm;
    __half* vb = qkvh + 2L * BT * Dm;

    cvt(Wq, OFF_WQ, 8L * DD);
    cvt(Wk, OFF_WK, 8L * DD);
    cvt(Wv, OFF_WV, 8L * DD);
    embed_ln<<<BT, 256>>>(idx, ts, tok, pos, gpos, ln1w, ln1b, x, pa);

    bool cvted = false;

    for (int l = 0; l < Ll; l++) {
        if (l > 0)
            layernorm_f16<<<BT, 256>>>(x, ln1w + (long)l * Dm, ln1b + (long)l * Dm, pa);

        gemm_hmma<EPI_QKV><<<gQKV, 256, GEMM_SMEM>>>(
            pa, wh + OFF_WQ + (long)l * DD, wl + OFF_WQ + (long)l * DD,
            8L * DD,
            bq + (long)l * Dm, bk + (long)l * Dm, bv + (long)l * Dm,
            nullptr, nullptr, qkvh, BT, 3 * Dm, Dm);

        attn_hmma<<<dim3(Tq / 128, Hh, Bq), 256, ATT_SMEM>>>(qb, kb, vb, pa);

        if (!cvted) cvt(Wo, OFF_WO, 8L * DD);

        gemm_hmma<EPI_ADD><<<gD, 256, GEMM_SMEM>>>(
            pa, wh + OFF_WO + (long)l * DD, wl + OFF_WO + (long)l * DD, 0,
            bo + (long)l * Dm, nullptr, nullptr, x, x, nullptr, BT, Dm, Dm);

        layernorm_f16<<<BT, 256>>>(x, ln2w + (long)l * Dm, ln2b + (long)l * Dm, pa);

        if (!cvted) cvt(W1, OFF_W1, 16L * DD);

        gemm_hmma<EPI_GELU><<<g2D, 256, GEMM_SMEM>>>(
            pa, wh + OFF_W1 + (long)l * 2 * DD, wl + OFF_W1 + (long)l * 2 * DD, 0,
            b1 + (long)l * 2 * Dm, nullptr, nullptr, nullptr,
            nullptr, pb, BT, 2 * Dm, Dm);

        if (!cvted) { cvt(W2, OFF_W2, 16L * DD); cvted = true; }

        gemm_hmma<EPI_ADD><<<gD, 256, GEMM_SMEM>>>(
            pb, wh + OFF_W2 + (long)l * 2 * DD, wl + OFF_W2 + (long)l * 2 * DD, 0,
            b2 + (long)l * Dm, nullptr, nullptr, x, x, nullptr, BT, Dm, 2 * Dm);
    }

    layernorm_f16<<<BT, 256>>>(x, lnfw, lnfb, pa);
    cvt(hw, OFF_HW, 8L * DD);
    gemm_hmma<EPI_NONE><<<gV, 256, GEMM_SMEM>>>(
        pa, wh + OFF_HW, wl + OFF_HW, 0,
        nullptr, nullptr, nullptr, nullptr, out, nullptr, BT, Vv, Dm);
}

// round 13
// speedup vs baseline: 4.6411x; 1.2545x over previous
#include <cuda_runtime.h>
#include <cuda_fp16.h>
#include <math.h>
#include <stdint.h>

// ---------------------------------------------------------------------------
// Problem constants
// ---------------------------------------------------------------------------
#define Bq   8
#define Tq   1024
#define Dm   1024
#define Hh   16
#define Ll   8
#define Vv   8192
#define HD   64
#define BT   (Bq*Tq)

// ---------------------------------------------------------------------------
// Scratch (static device globals)
// ---------------------------------------------------------------------------
__device__ float  g_x[BT * Dm];          // residual stream (f32)
__device__ __half g_qkvh[3L * BT * Dm];  // q | k | v  (f16)

__device__ __half g_pa[BT * Dm];         // act buf A: LN out / attn out
__device__ __half g_pb[BT * 2 * Dm];     // act buf B: MLP hidden

#define DD      (Dm*Dm)
#define OFF_WQ  0L
#define OFF_WK  (8L*DD)
#define OFF_WV  (16L*DD)
#define OFF_WO  (24L*DD)
#define OFF_W1  (32L*DD)
#define OFF_W2  (48L*DD)
#define OFF_HW  (64L*DD)
#define WTOT    (72L*DD)
__device__ __half g_wh[WTOT];
__device__ __half g_wl[WTOT];            // lo slices only used for Wo/W2/head

// ---------------------------------------------------------------------------
// Helpers
// ---------------------------------------------------------------------------
__device__ __forceinline__ uint32_t smem_u32(const void* p) {
    uint32_t a;
    asm("{ .reg .u64 t; cvta.to.shared.u64 t, %1; cvt.u32.u64 %0, t; }"
        : "=r"(a) : "l"(p));
    return a;
}
__device__ __forceinline__ void cpa16(uint32_t dst, const void* src) {
    asm volatile("cp.async.cg.shared.global [%0], [%1], 16;" :: "r"(dst), "l"(src));
}
__device__ __forceinline__ void ldm_x4(uint32_t& r0, uint32_t& r1,
                                       uint32_t& r2, uint32_t& r3, uint32_t addr) {
    asm volatile("ldmatrix.sync.aligned.m8n8.x4.shared.b16 {%0,%1,%2,%3}, [%4];"
                 : "=r"(r0), "=r"(r1), "=r"(r2), "=r"(r3) : "r"(addr));
}
__device__ __forceinline__ void ldm_x4t(uint32_t& r0, uint32_t& r1,
                                        uint32_t& r2, uint32_t& r3, uint32_t addr) {
    asm volatile("ldmatrix.sync.aligned.m8n8.x4.trans.shared.b16 {%0,%1,%2,%3}, [%4];"
                 : "=r"(r0), "=r"(r1), "=r"(r2), "=r"(r3) : "r"(addr));
}
__device__ __forceinline__ void mma_f16(float& d0, float& d1, float& d2, float& d3,
                                        uint32_t a0, uint32_t a1, uint32_t a2, uint32_t a3,
                                        uint32_t b0, uint32_t b1) {
    asm volatile(
        "mma.sync.aligned.m16n8k16.row.col.f32.f16.f16.f32 "
        "{%0,%1,%2,%3}, {%4,%5,%6,%7}, {%8,%9}, {%0,%1,%2,%3};"
        : "+f"(d0), "+f"(d1), "+f"(d2), "+f"(d3)
        : "r"(a0), "r"(a1), "r"(a2), "r"(a3), "r"(b0), "r"(b1));
}
__device__ __forceinline__ void split16(float x, __half& hi, __half& lo) {
    hi = __float2half_rn(x);
    lo = __float2half_rn(x - __half2float(hi));
}
__device__ __forceinline__ uint32_t packh2(float a, float b) {
    __half2 h = __halves2half2(__float2half_rn(a), __float2half_rn(b));
    return *(uint32_t*)&h;
}

// ---------------------------------------------------------------------------
// Weight conversions
// ---------------------------------------------------------------------------
__global__ __launch_bounds__(256) void cvt_pair(
    const float* __restrict__ s, __half* __restrict__ h,
    __half* __restrict__ l, long n)
{
    long i = ((long)blockIdx.x * 256 + threadIdx.x) * 4;
    if (i >= n) return;
    float4 v = *(const float4*)(s + i);
    __half h0, h1, h2, h3, l0, l1, l2, l3;
    split16(v.x, h0, l0); split16(v.y, h1, l1);
    split16(v.z, h2, l2); split16(v.w, h3, l3);
    *(__half2*)(h + i)     = __halves2half2(h0, h1);
    *(__half2*)(h + i + 2) = __halves2half2(h2, h3);
    *(__half2*)(l + i)     = __halves2half2(l0, l1);
    *(__half2*)(l + i + 2) = __halves2half2(l2, l3);
}
__global__ __launch_bounds__(256) void cvt_hi(
    const float* __restrict__ s, __half* __restrict__ h, long n)
{
    long i = ((long)blockIdx.x * 256 + threadIdx.x) * 4;
    if (i >= n) return;
    float4 v = *(const float4*)(s + i);
    *(__half2*)(h + i)     = __halves2half2(__float2half_rn(v.x), __float2half_rn(v.y));
    *(__half2*)(h + i + 2) = __halves2half2(__float2half_rn(v.z), __float2half_rn(v.w));
}

// ---------------------------------------------------------------------------
// Fused embedding + LayerNorm(layer0 ln1) -> x and f16 output
// ---------------------------------------------------------------------------
__global__ __launch_bounds__(256) void embed_ln(
    const int* __restrict__ idx, const int* __restrict__ ts,
    const float* __restrict__ tok, const float* __restrict__ pos,
    const float* __restrict__ gpos,
    const float* __restrict__ w, const float* __restrict__ b,
    float* __restrict__ X, __half* __restrict__ Y)
{
    int row = blockIdx.x;
    int t = row & (Tq - 1);
    int bb = row >> 10;
    int tid = threadIdx.x;
    int i = tid * 4;

    float4 tv = *(const float4*)(tok + (long)idx[row] * Dm + i);
    float4 gv = *(const float4*)(gpos + (long)ts[bb] * Dm + i);
    float4 pv = *(const float4*)(pos + (long)t * Dm + i);
    float4 v;
    v.x = tv.x + gv.x + pv.x;
    v.y = tv.y + gv.y + pv.y;
    v.z = tv.z + gv.z + pv.z;
    v.w = tv.w + gv.w + pv.w;

    long base = (long)row * Dm + i;
    *(float4*)(X + base) = v;

    float s  = v.x + v.y + v.z + v.w;
    float ss = v.x*v.x + v.y*v.y + v.z*v.z + v.w*v.w;

    __shared__ float rs[8], rss[8];
    #pragma unroll
    for (int m = 16; m; m >>= 1) {
        s  += __shfl_xor_sync(0xffffffffu, s,  m);
        ss += __shfl_xor_sync(0xffffffffu, ss, m);
    }
    int wid = tid >> 5, lane = tid & 31;
    if (lane == 0) { rs[wid] = s; rss[wid] = ss; }
    __syncthreads();
    if (wid == 0) {
        s  = (lane < 8) ? rs[lane]  : 0.f;
        ss = (lane < 8) ? rss[lane] : 0.f;
        #pragma unroll
        for (int m = 4; m; m >>= 1) {
            s  += __shfl_xor_sync(0xffffffffu, s,  m);
            ss += __shfl_xor_sync(0xffffffffu, ss, m);
        }
        if (lane == 0) { rs[0] = s; rss[0] = ss; }
    }
    __syncthreads();
    float mean = rs[0] * (1.0f / Dm);
    float var  = rss[0] * (1.0f / Dm) - mean * mean;
    float rstd = rsqrtf(var + 1e-5f);

    float4 wv = *(const float4*)(w + i);
    float4 bv = *(const float4*)(b + i);
    float o0 = (v.x - mean) * rstd * wv.x + bv.x;
    float o1 = (v.y - mean) * rstd * wv.y + bv.y;
    float o2 = (v.z - mean) * rstd * wv.z + bv.z;
    float o3 = (v.w - mean) * rstd * wv.w + bv.w;

    *(__half2*)(Y + base)     = __halves2half2(__float2half_rn(o0), __float2half_rn(o1));
    *(__half2*)(Y + base + 2) = __halves2half2(__float2half_rn(o2), __float2half_rn(o3));
}

// ---------------------------------------------------------------------------
// LayerNorm -> f16 output
// ---------------------------------------------------------------------------
__global__ __launch_bounds__(256) void layernorm_f16(
    const float* __restrict__ X, const float* __restrict__ w,
    const float* __restrict__ b, __half* __restrict__ Y)
{
    int row = blockIdx.x;
    const float* x = X + (long)row * Dm;
    int tid = threadIdx.x;

    int i = tid * 4;
    float4 v = *(const float4*)(x + i);
    float s  = v.x + v.y + v.z + v.w;
    float ss = v.x*v.x + v.y*v.y + v.z*v.z + v.w*v.w;

    __shared__ float rs[8], rss[8];
    #pragma unroll
    for (int m = 16; m; m >>= 1) {
        s  += __shfl_xor_sync(0xffffffffu, s,  m);
        ss += __shfl_xor_sync(0xffffffffu, ss, m);
    }
    int wid = tid >> 5, lane = tid & 31;
    if (lane == 0) { rs[wid] = s; rss[wid] = ss; }
    __syncthreads();
    if (wid == 0) {
        s  = (lane < 8) ? rs[lane]  : 0.f;
        ss = (lane < 8) ? rss[lane] : 0.f;
        #pragma unroll
        for (int m = 4; m; m >>= 1) {
            s  += __shfl_xor_sync(0xffffffffu, s,  m);
            ss += __shfl_xor_sync(0xffffffffu, ss, m);
        }
        if (lane == 0) { rs[0] = s; rss[0] = ss; }
    }
    __syncthreads();
    float mean = rs[0] * (1.0f / Dm);
    float var  = rss[0] * (1.0f / Dm) - mean * mean;
    float rstd = rsqrtf(var + 1e-5f);

    float4 wv = *(const float4*)(w + i);
    float4 bv = *(const float4*)(b + i);
    float o0 = (v.x - mean) * rstd * wv.x + bv.x;
    float o1 = (v.y - mean) * rstd * wv.y + bv.y;
    float o2 = (v.z - mean) * rstd * wv.z + bv.z;
    float o3 = (v.w - mean) * rstd * wv.w + bv.w;

    long base = (long)row * Dm + i;
    *(__half2*)(Y + base)     = __halves2half2(__float2half_rn(o0), __float2half_rn(o1));
    *(__half2*)(Y + base + 2) = __halves2half2(__float2half_rn(o2), __float2half_rn(o3));
}

// ---------------------------------------------------------------------------
// HMMA GEMM. TERMS=2: C = Ah·Bh + Ah·Bl ; TERMS=1: C = Ah·Bh.
// CTA 128x128, k-step 32, cp.async double buffer, 8 warps of 64x32.
// ---------------------------------------------------------------------------
#define EPI_NONE 0
#define EPI_ADD  1
#define EPI_GELU 2
#define EPI_QKV  3

#define PK      40
#define TILE_H  (128*PK)
#define STG_H   (3*TILE_H)
#define GEMM_SMEM (2*STG_H*2)

template<int EPI, int TERMS>
__global__ __launch_bounds__(256, 2) void gemm_hmma(
    const __half* __restrict__ Ah,
    const __half* __restrict__ Bh, const __half* __restrict__ Bl,
    long bStride,
    const float* __restrict__ b0p, const float* __restrict__ b1p,
    const float* __restrict__ b2p, const float* __restrict__ res,
    float* __restrict__ C, __half* __restrict__ Ch,
    int M, int N, int K)
{
    extern __shared__ __align__(16) __half gsm[];
    const uint32_t sbase = smem_u32(gsm);

    const int tid = threadIdx.x, lane = tid & 31, warp = tid >> 5;
    const int g = lane >> 2, t = lane & 3, l7 = lane & 7;
    const int wm = warp & 1, wn = warp >> 1;
    const int m0 = blockIdx.y * 128, n0 = blockIdx.x * 128;

    float acc[4][4][4];
    #pragma unroll
    for (int a = 0; a < 4; a++)
        #pragma unroll
        for (int b = 0; b < 4; b++)
            #pragma unroll
            for (int c = 0; c < 4; c++) acc[a][b][c] = 0.f;

    const int S = K >> 5;
    const int NCH = (TERMS == 2) ? 6 : 4;   // 16B chunks / 256 per stage

    auto issue = [&](int k0, int buf) {
        #pragma unroll
        for (int j = 0; j < NCH; j++) {
            int c = tid + 256 * j;
            int tile = c >> 9;
            int r = (c >> 2) & 127;
            int q = c & 3;
            const __half* src;
            if (tile == 0) src = Ah + (long)(m0 + r) * K + k0 + q * 8;
            else {
                long roff;
                if (EPI == EPI_QKV) {
                    int rg = n0 + r;
                    roff = (long)(rg >> 10) * bStride + (long)(rg & 1023) * K;
                } else {
                    roff = (long)(n0 + r) * K;
                }
                src = (tile == 1 ? Bh : Bl) + roff + k0 + q * 8;
            }
            uint32_t dst = sbase + (uint32_t)(buf * STG_H + tile * TILE_H + r * PK + q * 8) * 2u;
            cpa16(dst, src);
        }
        asm volatile("cp.async.commit_group;" ::: "memory");
    };

    issue(0, 0);

    for (int s = 0; s < S; s++) {
        asm volatile("cp.async.wait_group 0;" ::: "memory");
        __syncthreads();
        if (s + 1 < S) issue((s + 1) << 5, (s + 1) & 1);

        uint32_t sb  = sbase + (uint32_t)((s & 1) * STG_H) * 2u;
        uint32_t A_h = sb;
        uint32_t B_h = sb + TILE_H * 2u;
        uint32_t B_l = sb + 2u * TILE_H * 2u;

        #pragma unroll
        for (int kk = 0; kk < 32; kk += 16) {
            uint32_t bh[4][2], bl[4][2];
            #pragma unroll
            for (int p = 0; p < 2; p++) {
                int row = wn * 32 + p * 16 + l7 + ((lane & 16) >> 1);
                int kc  = kk + (lane & 8);
                uint32_t off = (uint32_t)(row * PK + kc) * 2u;
                ldm_x4(bh[2*p][0], bh[2*p][1], bh[2*p+1][0], bh[2*p+1][1], B_h + off);
                if (TERMS == 2)
                    ldm_x4(bl[2*p][0], bl[2*p][1], bl[2*p+1][0], bl[2*p+1][1], B_l + off);
            }
            #pragma unroll
            for (int mi = 0; mi < 4; mi++) {
                int row = wm * 64 + mi * 16 + l7 + (lane & 8);
                int kc  = kk + ((lane & 16) >> 1);
                uint32_t off = (uint32_t)(row * PK + kc) * 2u;
                uint32_t ah0, ah1, ah2, ah3;
                ldm_x4(ah0, ah1, ah2, ah3, A_h + off);
                #pragma unroll
                for (int ni = 0; ni < 4; ni++) {
                    float* d = acc[mi][ni];
                    mma_f16(d[0], d[1], d[2], d[3], ah0, ah1, ah2, ah3, bh[ni][0], bh[ni][1]);
                    if (TERMS == 2)
                        mma_f16(d[0], d[1], d[2], d[3], ah0, ah1, ah2, ah3, bl[ni][0], bl[ni][1]);
                }
            }
        }
    }

    // --- epilogue ---
    const float* bias = b0p;
    float* Cd = C;
    __half* Chd = Ch;
    int csub = 0, Nw = N;
    if (EPI == EPI_QKV) {
        int sel = n0 >> 10;
        bias = (sel == 0) ? b0p : (sel == 1) ? b1p : b2p;
        Chd = Ch + (long)sel * BT * Dm;
        csub = sel << 10;
        Nw = Dm;
    }

    #pragma unroll
    for (int mi = 0; mi < 4; mi++) {
        int r0 = m0 + wm * 64 + mi * 16 + g;
        #pragma unroll
        for (int ni = 0; ni < 4; ni++) {
            int cc = n0 + wn * 32 + ni * 8 + 2 * t;
            float b0v = bias ? bias[cc - csub] : 0.f;
            float b1v = bias ? bias[cc - csub + 1] : 0.f;
            float v0 = acc[mi][ni][0] + b0v, v1 = acc[mi][ni][1] + b1v;
            float v2 = acc[mi][ni][2] + b0v, v3 = acc[mi][ni][3] + b1v;
            long i0 = (long)r0 * Nw + (cc - csub);
            long i1 = (long)(r0 + 8) * Nw + (cc - csub);
            if (EPI == EPI_ADD) {
                v0 += res[i0]; v1 += res[i0 + 1];
                v2 += res[i1]; v3 += res[i1 + 1];
            }
            if (EPI == EPI_GELU) {
                v0 = 0.5f * v0 * (1.f + erff(v0 * 0.70710678118654752f));
                v1 = 0.5f * v1 * (1.f + erff(v1 * 0.70710678118654752f));
                v2 = 0.5f * v2 * (1.f + erff(v2 * 0.70710678118654752f));
                v3 = 0.5f * v3 * (1.f + erff(v3 * 0.70710678118654752f));
            }
            if (EPI == EPI_GELU || EPI == EPI_QKV) {
                *(__half2*)(Chd + i0) = __halves2half2(__float2half_rn(v0), __float2half_rn(v1));
                *(__half2*)(Chd + i1) = __halves2half2(__float2half_rn(v2), __float2half_rn(v3));
            } else {
                *(float2*)(Cd + i0) = make_float2(v0, v1);
                *(float2*)(Cd + i1) = make_float2(v2, v3);
            }
        }
    }
}

// ---------------------------------------------------------------------------
// Flash attention (HMMA, causal). q/k/v f16 inputs, f16 output.
// Block = 128 q rows (8 warps x 16), K/V tiles of 64 tokens.
// ---------------------------------------------------------------------------
#define APD 72
#define ATT_SMEM ((128 + 64 + 64) * APD * 2)

__global__ __launch_bounds__(256, 2) void attn_hmma(
    const __half* __restrict__ Qg, const __half* __restrict__ Kg,
    const __half* __restrict__ Vg, __half* __restrict__ Y)
{
    extern __shared__ __align__(16) __half asmem[];
    const uint32_t sb = smem_u32(asmem);
    const uint32_t Qs = sb;
    const uint32_t Ks = sb + 128 * APD * 2;
    const uint32_t Vs = Ks + 64 * APD * 2;

    const int qt = blockIdx.x, h = blockIdx.y, b = blockIdx.z;
    const int tid = threadIdx.x, lane = tid & 31, warp = tid >> 5;
    const int g = lane >> 2, c2 = (lane & 3) * 2;

    const long rowbase = (long)(b * Tq + qt * 128);
    const __half* qsrc = Qg + rowbase * Dm + h * HD;

    #pragma unroll
    for (int j = 0; j < 4; j++) {
        int c = tid + 256 * j;
        int r = c >> 3, col8 = (c & 7) * 8;
        cpa16(Qs + (uint32_t)(r * APD + col8) * 2u, qsrc + (long)r * Dm + col8);
    }
    asm volatile("cp.async.commit_group;" ::: "memory");
    asm volatile("cp.async.wait_group 0;" ::: "memory");
    __syncthreads();

    uint32_t qf[4][4];
    #pragma unroll
    for (int kf = 0; kf < 4; kf++) {
        uint32_t addr = Qs + (uint32_t)((warp * 16 + (lane & 15)) * APD
                                        + kf * 16 + ((lane >> 4) & 1) * 8) * 2u;
        ldm_x4(qf[kf][0], qf[kf][1], qf[kf][2], qf[kf][3], addr);
    }

    const int r0g = qt * 128 + warp * 16 + g;
    const int q_hi = qt * 128 + warp * 16 + 15;

    float O[8][4];
    #pragma unroll
    for (int nf = 0; nf < 8; nf++)
        #pragma unroll
        for (int j = 0; j < 4; j++) O[nf][j] = 0.f;
    float m0 = -1e30f, m1 = -1e30f, l0 = 0.f, l1 = 0.f;

    const int ktmax = qt * 2 + 1;
    for (int kt = 0; kt <= ktmax; kt++) {
        const long krow = (long)(b * Tq + kt * 64);
        #pragma unroll
        for (int j = 0; j < 4; j++) {
            int c = tid + 256 * j;
            int tsel = c >> 9;
            int r = (c >> 3) & 63, col8 = (c & 7) * 8;
            const __half* src = (tsel ? Vg : Kg) + (krow + r) * (long)Dm + h * HD + col8;
            uint32_t dst = (tsel ? Vs : Ks) + (uint32_t)(r * APD + col8) * 2u;
            cpa16(dst, src);
        }
        asm volatile("cp.async.commit_group;" ::: "memory");
        asm volatile("cp.async.wait_group 0;" ::: "memory");
        __syncthreads();

        if (kt * 64 <= q_hi) {
            float S[8][4];
            #pragma unroll
            for (int nf = 0; nf < 8; nf++)
                #pragma unroll
                for (int j = 0; j < 4; j++) S[nf][j] = 0.f;

            #pragma unroll
            for (int tg = 0; tg < 4; tg++) {
                #pragma unroll
                for (int kf = 0; kf < 4; kf++) {
                    uint32_t k0, k1, k2, k3;
                    uint32_t addr = Ks + (uint32_t)((tg * 16 + (lane & 15)) * APD
                                                    + kf * 16 + ((lane >> 4) & 1) * 8) * 2u;
                    ldm_x4(k0, k1, k2, k3, addr);
                    mma_f16(S[2*tg][0], S[2*tg][1], S[2*tg][2], S[2*tg][3],
                            qf[kf][0], qf[kf][1], qf[kf][2], qf[kf][3], k0, k2);
                    mma_f16(S[2*tg+1][0], S[2*tg+1][1], S[2*tg+1][2], S[2*tg+1][3],
                            qf[kf][0], qf[kf][1], qf[kf][2], qf[kf][3], k1, k3);
                }
            }

            const float scale = 0.125f;
            #pragma unroll
            for (int nf = 0; nf < 8; nf++)
                #pragma unroll
                for (int j = 0; j < 4; j++) S[nf][j] *= scale;

            if (kt * 64 + 63 > r0g) {
                #pragma unroll
                for (int nf = 0; nf < 8; nf++) {
                    int col = kt * 64 + nf * 8 + c2;
                    if (col     > r0g)     S[nf][0] = -1e30f;
                    if (col + 1 > r0g)     S[nf][1] = -1e30f;
                    if (col     > r0g + 8) S[nf][2] = -1e30f;
                    if (col + 1 > r0g + 8) S[nf][3] = -1e30f;
                }
            }

            float rmax0 = -1e30f, rmax1 = -1e30f;
            #pragma unroll
            for (int nf = 0; nf < 8; nf++) {
                rmax0 = fmaxf(rmax0, fmaxf(S[nf][0], S[nf][1]));
                rmax1 = fmaxf(rmax1, fmaxf(S[nf][2], S[nf][3]));
            }
            #pragma unroll
            for (int m = 1; m <= 2; m <<= 1) {
                rmax0 = fmaxf(rmax0, __shfl_xor_sync(0xffffffffu, rmax0, m));
                rmax1 = fmaxf(rmax1, __shfl_xor_sync(0xffffffffu, rmax1, m));
            }
            float mn0 = fmaxf(m0, rmax0), mn1 = fmaxf(m1, rmax1);
            float a0 = __expf(m0 - mn0), a1 = __expf(m1 - mn1);
            m0 = mn0; m1 = mn1;

            float rs0 = 0.f, rs1 = 0.f;
            uint32_t pa[4][4];
            #pragma unroll
            for (int nf = 0; nf < 8; nf++) {
                float p0 = __expf(S[nf][0] - mn0);
                float p1 = __expf(S[nf][1] - mn0);
                float p2 = __expf(S[nf][2] - mn1);
                float p3 = __expf(S[nf][3] - mn1);
                rs0 += p0 + p1; rs1 += p2 + p3;
                pa[nf >> 1][(nf & 1) * 2 + 0] = packh2(p0, p1);
                pa[nf >> 1][(nf & 1) * 2 + 1] = packh2(p2, p3);
            }
            #pragma unroll
            for (int m = 1; m <= 2; m <<= 1) {
                rs0 += __shfl_xor_sync(0xffffffffu, rs0, m);
                rs1 += __shfl_xor_sync(0xffffffffu, rs1, m);
            }
            l0 = l0 * a0 + rs0;
            l1 = l1 * a1 + rs1;
            #pragma unroll
            for (int nf = 0; nf < 8; nf++) {
                O[nf][0] *= a0; O[nf][1] *= a0;
                O[nf][2] *= a1; O[nf][3] *= a1;
            }

            #pragma unroll
            for (int kf = 0; kf < 4; kf++) {
                #pragma unroll
                for (int hg = 0; hg < 4; hg++) {
                    uint32_t v0, v1, v2, v3;
                    uint32_t addr = Vs + (uint32_t)((kf * 16 + (lane & 15)) * APD
                                                    + hg * 16 + ((lane >> 4) & 1) * 8) * 2u;
                    ldm_x4t(v0, v1, v2, v3, addr);
                    mma_f16(O[2*hg][0], O[2*hg][1], O[2*hg][2], O[2*hg][3],
                            pa[kf][0], pa[kf][1], pa[kf][2], pa[kf][3], v0, v1);
                    mma_f16(O[2*hg+1][0], O[2*hg+1][1], O[2*hg+1][2], O[2*hg+1][3],
                            pa[kf][0], pa[kf][1], pa[kf][2], pa[kf][3], v2, v3);
                }
            }
        }
        __syncthreads();
    }

    float inv0 = 1.f / l0, inv1 = 1.f / l1;
    long ybase0 = (rowbase + warp * 16 + g) * (long)Dm + h * HD;
    long ybase1 = ybase0 + 8L * Dm;
    #pragma unroll
    for (int nf = 0; nf < 8; nf++) {
        int col = nf * 8 + c2;
        *(__half2*)(Y + ybase0 + col) =
            __halves2half2(__float2half_rn(O[nf][0] * inv0), __float2half_rn(O[nf][1] * inv0));
        *(__half2*)(Y + ybase1 + col) =
            __halves2half2(__float2half_rn(O[nf][2] * inv1), __float2half_rn(O[nf][3] * inv1));
    }
}

// ---------------------------------------------------------------------------
// Launcher
// ---------------------------------------------------------------------------
extern "C" void kernel_launch(void* const* d_in, const int* in_sizes, int n_in,
                              void* d_out, int out_size)
{
    const int*   idx  = (const int*)  d_in[0];
    const int*   ts   = (const int*)  d_in[1];
    const float* tok  = (const float*)d_in[2];
    const float* pos  = (const float*)d_in[3];
    const float* gpos = (const float*)d_in[4];
    const float* ln1w = (const float*)d_in[5];
    const float* ln1b = (const float*)d_in[6];
    const float* Wq   = (const float*)d_in[7];
    const float* bq   = (const float*)d_in[8];
    const float* Wk   = (const float*)d_in[9];
    const float* bk   = (const float*)d_in[10];
    const float* Wv   = (const float*)d_in[11];
    const float* bv   = (const float*)d_in[12];
    const float* Wo   = (const float*)d_in[13];
    const float* bo   = (const float*)d_in[14];
    const float* ln2w = (const float*)d_in[15];
    const float* ln2b = (const float*)d_in[16];
    const float* W1   = (const float*)d_in[17];
    const float* b1   = (const float*)d_in[18];
    const float* W2   = (const float*)d_in[19];
    const float* b2   = (const float*)d_in[20];
    const float* lnfw = (const float*)d_in[21];
    const float* lnfb = (const float*)d_in[22];
    const float* hw   = (const float*)d_in[23];
    float* out = (float*)d_out;

    float* x;
    __half *qkvh, *pa, *pb, *wh, *wl;
    cudaGetSymbolAddress((void**)&x,    g_x);
    cudaGetSymbolAddress((void**)&qkvh, g_qkvh);
    cudaGetSymbolAddress((void**)&pa,   g_pa);
    cudaGetSymbolAddress((void**)&pb,   g_pb);
    cudaGetSymbolAddress((void**)&wh,   g_wh);
    cudaGetSymbolAddress((void**)&wl,   g_wl);

    cudaFuncSetAttribute(attn_hmma, cudaFuncAttributeMaxDynamicSharedMemorySize, ATT_SMEM);
    cudaFuncSetAttribute((gemm_hmma<EPI_QKV, 1>),  cudaFuncAttributeMaxDynamicSharedMemorySize, GEMM_SMEM);
    cudaFuncSetAttribute((gemm_hmma<EPI_GELU, 1>), cudaFuncAttributeMaxDynamicSharedMemorySize, GEMM_SMEM);
    cudaFuncSetAttribute((gemm_hmma<EPI_ADD, 2>),  cudaFuncAttributeMaxDynamicSharedMemorySize, GEMM_SMEM);
    cudaFuncSetAttribute((gemm_hmma<EPI_NONE, 2>), cudaFuncAttributeMaxDynamicSharedMemorySize, GEMM_SMEM);

    auto cvt2 = [&](const float* src, long off, long n) {
        cvt_pair<<<(int)((n / 4 + 255) / 256), 256>>>(src, wh + off, wl + off, n);
    };
    auto cvt1 = [&](const float* src, long off, long n) {
        cvt_hi<<<(int)((n / 4 + 255) / 256), 256>>>(src, wh + off, n);
    };

    const dim3 gD(Dm / 128, BT / 128);
    const dim3 gQKV(3 * Dm / 128, BT / 128);
    const dim3 g2D(2 * Dm / 128, BT / 128);
    const dim3 gV(Vv / 128, BT / 128);

    __half* qb = qkvh;
    __half* kb = qkvh + (long)BT * Dm;
    __half* vb = qkvh + 2L * BT * Dm;

    cvt1(Wq, OFF_WQ, 8L * DD);
    cvt1(Wk, OFF_WK, 8L * DD);
    cvt1(Wv, OFF_WV, 8L * DD);
    embed_ln<<<BT, 256>>>(idx, ts, tok, pos, gpos, ln1w, ln1b, x, pa);

    bool cvted = false;

    for (int l = 0; l < Ll; l++) {
        if (l > 0)
            layernorm_f16<<<BT, 256>>>(x, ln1w + (long)l * Dm, ln1b + (long)l * Dm, pa);

        gemm_hmma<EPI_QKV, 1><<<gQKV, 256, GEMM_SMEM>>>(
            pa, wh + OFF_WQ + (long)l * DD, nullptr,
            8L * DD,
            bq + (long)l * Dm, bk + (long)l * Dm, bv + (long)l * Dm,
            nullptr, nullptr, qkvh, BT, 3 * Dm, Dm);

        attn_hmma<<<dim3(Tq / 128, Hh, Bq), 256, ATT_SMEM>>>(qb, kb, vb, pa);

        if (!cvted) cvt2(Wo, OFF_WO, 8L * DD);

        gemm_hmma<EPI_ADD, 2><<<gD, 256, GEMM_SMEM>>>(
            pa, wh + OFF_WO + (long)l * DD, wl + OFF_WO + (long)l * DD, 0,
            bo + (long)l * Dm, nullptr, nullptr, x, x, nullptr, BT, Dm, Dm);

        layernorm_f16<<<BT, 256>>>(x, ln2w + (long)l * Dm, ln2b + (long)l * Dm, pa);

        if (!cvted) cvt1(W1, OFF_W1, 16L * DD);

        gemm_hmma<EPI_GELU, 1><<<g2D, 256, GEMM_SMEM>>>(
            pa, wh + OFF_W1 + (long)l * 2 * DD, nullptr, 0,
            b1 + (long)l * 2 * Dm, nullptr, nullptr, nullptr,
            nullptr, pb, BT, 2 * Dm, Dm);

        if (!cvted) { cvt2(W2, OFF_W2, 16L * DD); cvted = true; }

        gemm_hmma<EPI_ADD, 2><<<gD, 256, GEMM_SMEM>>>(
            pb, wh + OFF_W2 + (long)l * 2 * DD, wl + OFF_W2 + (long)l * 2 * DD, 0,
            b2 + (long)l * Dm, nullptr, nullptr, x, x, nullptr, BT, Dm, 2 * Dm);
    }

    layernorm_f16<<<BT, 256>>>(x, lnfw, lnfb, pa);
    cvt2(hw, OFF_HW, 8L * DD);
    gemm_hmma<EPI_NONE, 2><<<gV, 256, GEMM_SMEM>>>(
        pa, wh + OFF_HW, wl + OFF_HW, 0,
        nullptr, nullptr, nullptr, nullptr, out, nullptr, BT, Vv, Dm);
}

// round 14
// speedup vs baseline: 4.8873x; 1.0531x over previous
#include <cuda_runtime.h>
#include <cuda_fp16.h>
#include <math.h>
#include <stdint.h>

// ---------------------------------------------------------------------------
// Problem constants
// ---------------------------------------------------------------------------
#define Bq   8
#define Tq   1024
#define Dm   1024
#define Hh   16
#define Ll   8
#define Vv   8192
#define HD   64
#define BT   (Bq*Tq)

// ---------------------------------------------------------------------------
// Scratch (static device globals)
// ---------------------------------------------------------------------------
__device__ float  g_x[BT * Dm];          // residual stream (f32)
__device__ __half g_qkvh[3L * BT * Dm];  // q | k | v  (f16)

__device__ __half g_pa[BT * Dm];         // act buf A: LN out / attn out
__device__ __half g_pb[BT * 2 * Dm];     // act buf B: MLP hidden

#define DD      (Dm*Dm)
#define OFF_WQ  0L
#define OFF_WK  (8L*DD)
#define OFF_WV  (16L*DD)
#define OFF_WO  (24L*DD)
#define OFF_W1  (32L*DD)
#define OFF_W2  (48L*DD)
#define OFF_HW  (64L*DD)
#define WTOT    (72L*DD)
__device__ __half g_wh[WTOT];
__device__ __half g_wl[WTOT];            // lo slices: Wo / W2 only

// ---------------------------------------------------------------------------
// Helpers
// ---------------------------------------------------------------------------
__device__ __forceinline__ uint32_t smem_u32(const void* p) {
    uint32_t a;
    asm("{ .reg .u64 t; cvta.to.shared.u64 t, %1; cvt.u32.u64 %0, t; }"
        : "=r"(a) : "l"(p));
    return a;
}
__device__ __forceinline__ void cpa16(uint32_t dst, const void* src) {
    asm volatile("cp.async.cg.shared.global [%0], [%1], 16;" :: "r"(dst), "l"(src));
}
__device__ __forceinline__ void ldm_x4(uint32_t& r0, uint32_t& r1,
                                       uint32_t& r2, uint32_t& r3, uint32_t addr) {
    asm volatile("ldmatrix.sync.aligned.m8n8.x4.shared.b16 {%0,%1,%2,%3}, [%4];"
                 : "=r"(r0), "=r"(r1), "=r"(r2), "=r"(r3) : "r"(addr));
}
__device__ __forceinline__ void ldm_x4t(uint32_t& r0, uint32_t& r1,
                                        uint32_t& r2, uint32_t& r3, uint32_t addr) {
    asm volatile("ldmatrix.sync.aligned.m8n8.x4.trans.shared.b16 {%0,%1,%2,%3}, [%4];"
                 : "=r"(r0), "=r"(r1), "=r"(r2), "=r"(r3) : "r"(addr));
}
__device__ __forceinline__ void mma_f16(float& d0, float& d1, float& d2, float& d3,
                                        uint32_t a0, uint32_t a1, uint32_t a2, uint32_t a3,
                                        uint32_t b0, uint32_t b1) {
    asm volatile(
        "mma.sync.aligned.m16n8k16.row.col.f32.f16.f16.f32 "
        "{%0,%1,%2,%3}, {%4,%5,%6,%7}, {%8,%9}, {%0,%1,%2,%3};"
        : "+f"(d0), "+f"(d1), "+f"(d2), "+f"(d3)
        : "r"(a0), "r"(a1), "r"(a2), "r"(a3), "r"(b0), "r"(b1));
}
__device__ __forceinline__ void split16(float x, __half& hi, __half& lo) {
    hi = __float2half_rn(x);
    lo = __float2half_rn(x - __half2float(hi));
}
__device__ __forceinline__ uint32_t packh2(float a, float b) {
    __half2 h = __halves2half2(__float2half_rn(a), __float2half_rn(b));
    return *(uint32_t*)&h;
}

// ---------------------------------------------------------------------------
// Weight conversions
// ---------------------------------------------------------------------------
__global__ __launch_bounds__(256) void cvt_pair(
    const float* __restrict__ s, __half* __restrict__ h,
    __half* __restrict__ l, long n)
{
    long i = ((long)blockIdx.x * 256 + threadIdx.x) * 4;
    if (i >= n) return;
    float4 v = *(const float4*)(s + i);
    __half h0, h1, h2, h3, l0, l1, l2, l3;
    split16(v.x, h0, l0); split16(v.y, h1, l1);
    split16(v.z, h2, l2); split16(v.w, h3, l3);
    *(__half2*)(h + i)     = __halves2half2(h0, h1);
    *(__half2*)(h + i + 2) = __halves2half2(h2, h3);
    *(__half2*)(l + i)     = __halves2half2(l0, l1);
    *(__half2*)(l + i + 2) = __halves2half2(l2, l3);
}
__global__ __launch_bounds__(256) void cvt_hi(
    const float* __restrict__ s, __half* __restrict__ h, long n)
{
    long i = ((long)blockIdx.x * 256 + threadIdx.x) * 4;
    if (i >= n) return;
    float4 v = *(const float4*)(s + i);
    *(__half2*)(h + i)     = __halves2half2(__float2half_rn(v.x), __float2half_rn(v.y));
    *(__half2*)(h + i + 2) = __halves2half2(__float2half_rn(v.z), __float2half_rn(v.w));
}

// ---------------------------------------------------------------------------
// Fused embedding + LayerNorm(layer0 ln1) -> x and f16 output
// ---------------------------------------------------------------------------
__global__ __launch_bounds__(256) void embed_ln(
    const int* __restrict__ idx, const int* __restrict__ ts,
    const float* __restrict__ tok, const float* __restrict__ pos,
    const float* __restrict__ gpos,
    const float* __restrict__ w, const float* __restrict__ b,
    float* __restrict__ X, __half* __restrict__ Y)
{
    int row = blockIdx.x;
    int t = row & (Tq - 1);
    int bb = row >> 10;
    int tid = threadIdx.x;
    int i = tid * 4;

    float4 tv = *(const float4*)(tok + (long)idx[row] * Dm + i);
    float4 gv = *(const float4*)(gpos + (long)ts[bb] * Dm + i);
    float4 pv = *(const float4*)(pos + (long)t * Dm + i);
    float4 v;
    v.x = tv.x + gv.x + pv.x;
    v.y = tv.y + gv.y + pv.y;
    v.z = tv.z + gv.z + pv.z;
    v.w = tv.w + gv.w + pv.w;

    long base = (long)row * Dm + i;
    *(float4*)(X + base) = v;

    float s  = v.x + v.y + v.z + v.w;
    float ss = v.x*v.x + v.y*v.y + v.z*v.z + v.w*v.w;

    __shared__ float rs[8], rss[8];
    #pragma unroll
    for (int m = 16; m; m >>= 1) {
        s  += __shfl_xor_sync(0xffffffffu, s,  m);
        ss += __shfl_xor_sync(0xffffffffu, ss, m);
    }
    int wid = tid >> 5, lane = tid & 31;
    if (lane == 0) { rs[wid] = s; rss[wid] = ss; }
    __syncthreads();
    if (wid == 0) {
        s  = (lane < 8) ? rs[lane]  : 0.f;
        ss = (lane < 8) ? rss[lane] : 0.f;
        #pragma unroll
        for (int m = 4; m; m >>= 1) {
            s  += __shfl_xor_sync(0xffffffffu, s,  m);
            ss += __shfl_xor_sync(0xffffffffu, ss, m);
        }
        if (lane == 0) { rs[0] = s; rss[0] = ss; }
    }
    __syncthreads();
    float mean = rs[0] * (1.0f / Dm);
    float var  = rss[0] * (1.0f / Dm) - mean * mean;
    float rstd = rsqrtf(var + 1e-5f);

    float4 wv = *(const float4*)(w + i);
    float4 bv = *(const float4*)(b + i);
    float o0 = (v.x - mean) * rstd * wv.x + bv.x;
    float o1 = (v.y - mean) * rstd * wv.y + bv.y;
    float o2 = (v.z - mean) * rstd * wv.z + bv.z;
    float o3 = (v.w - mean) * rstd * wv.w + bv.w;

    *(__half2*)(Y + base)     = __halves2half2(__float2half_rn(o0), __float2half_rn(o1));
    *(__half2*)(Y + base + 2) = __halves2half2(__float2half_rn(o2), __float2half_rn(o3));
}

// ---------------------------------------------------------------------------
// LayerNorm -> f16 output
// ---------------------------------------------------------------------------
__global__ __launch_bounds__(256) void layernorm_f16(
    const float* __restrict__ X, const float* __restrict__ w,
    const float* __restrict__ b, __half* __restrict__ Y)
{
    int row = blockIdx.x;
    const float* x = X + (long)row * Dm;
    int tid = threadIdx.x;

    int i = tid * 4;
    float4 v = *(const float4*)(x + i);
    float s  = v.x + v.y + v.z + v.w;
    float ss = v.x*v.x + v.y*v.y + v.z*v.z + v.w*v.w;

    __shared__ float rs[8], rss[8];
    #pragma unroll
    for (int m = 16; m; m >>= 1) {
        s  += __shfl_xor_sync(0xffffffffu, s,  m);
        ss += __shfl_xor_sync(0xffffffffu, ss, m);
    }
    int wid = tid >> 5, lane = tid & 31;
    if (lane == 0) { rs[wid] = s; rss[wid] = ss; }
    __syncthreads();
    if (wid == 0) {
        s  = (lane < 8) ? rs[lane]  : 0.f;
        ss = (lane < 8) ? rss[lane] : 0.f;
        #pragma unroll
        for (int m = 4; m; m >>= 1) {
            s  += __shfl_xor_sync(0xffffffffu, s,  m);
            ss += __shfl_xor_sync(0xffffffffu, ss, m);
        }
        if (lane == 0) { rs[0] = s; rss[0] = ss; }
    }
    __syncthreads();
    float mean = rs[0] * (1.0f / Dm);
    float var  = rss[0] * (1.0f / Dm) - mean * mean;
    float rstd = rsqrtf(var + 1e-5f);

    float4 wv = *(const float4*)(w + i);
    float4 bv = *(const float4*)(b + i);
    float o0 = (v.x - mean) * rstd * wv.x + bv.x;
    float o1 = (v.y - mean) * rstd * wv.y + bv.y;
    float o2 = (v.z - mean) * rstd * wv.z + bv.z;
    float o3 = (v.w - mean) * rstd * wv.w + bv.w;

    long base = (long)row * Dm + i;
    *(__half2*)(Y + base)     = __halves2half2(__float2half_rn(o0), __float2half_rn(o1));
    *(__half2*)(Y + base + 2) = __halves2half2(__float2half_rn(o2), __float2half_rn(o3));
}

// ---------------------------------------------------------------------------
// HMMA GEMM. TERMS=2: C = Ah·Bh + Ah·Bl ; TERMS=1: C = Ah·Bh.
// CTA 128x128, k-step 32, cp.async double buffer, 8 warps of 64x32.
// ---------------------------------------------------------------------------
#define EPI_NONE 0
#define EPI_ADD  1
#define EPI_GELU 2
#define EPI_QKV  3

#define PK      40
#define TILE_H  (128*PK)
#define STG_H   (3*TILE_H)
#define GEMM_SMEM (2*STG_H*2)

template<int EPI, int TERMS>
__global__ __launch_bounds__(256, 2) void gemm_hmma(
    const __half* __restrict__ Ah,
    const __half* __restrict__ Bh, const __half* __restrict__ Bl,
    long bStride,
    const float* __restrict__ b0p, const float* __restrict__ b1p,
    const float* __restrict__ b2p, const float* __restrict__ res,
    float* __restrict__ C, __half* __restrict__ Ch,
    int M, int N, int K)
{
    extern __shared__ __align__(16) __half gsm[];
    const uint32_t sbase = smem_u32(gsm);

    const int tid = threadIdx.x, lane = tid & 31, warp = tid >> 5;
    const int g = lane >> 2, t = lane & 3, l7 = lane & 7;
    const int wm = warp & 1, wn = warp >> 1;
    const int m0 = blockIdx.y * 128, n0 = blockIdx.x * 128;

    float acc[4][4][4];
    #pragma unroll
    for (int a = 0; a < 4; a++)
        #pragma unroll
        for (int b = 0; b < 4; b++)
            #pragma unroll
            for (int c = 0; c < 4; c++) acc[a][b][c] = 0.f;

    const int S = K >> 5;
    const int NCH = (TERMS == 2) ? 6 : 4;

    auto issue = [&](int k0, int buf) {
        #pragma unroll
        for (int j = 0; j < NCH; j++) {
            int c = tid + 256 * j;
            int tile = c >> 9;
            int r = (c >> 2) & 127;
            int q = c & 3;
            const __half* src;
            if (tile == 0) src = Ah + (long)(m0 + r) * K + k0 + q * 8;
            else {
                long roff;
                if (EPI == EPI_QKV) {
                    int rg = n0 + r;
                    roff = (long)(rg >> 10) * bStride + (long)(rg & 1023) * K;
                } else {
                    roff = (long)(n0 + r) * K;
                }
                src = (tile == 1 ? Bh : Bl) + roff + k0 + q * 8;
            }
            uint32_t dst = sbase + (uint32_t)(buf * STG_H + tile * TILE_H + r * PK + q * 8) * 2u;
            cpa16(dst, src);
        }
        asm volatile("cp.async.commit_group;" ::: "memory");
    };

    issue(0, 0);

    for (int s = 0; s < S; s++) {
        asm volatile("cp.async.wait_group 0;" ::: "memory");
        __syncthreads();
        if (s + 1 < S) issue((s + 1) << 5, (s + 1) & 1);

        uint32_t sb  = sbase + (uint32_t)((s & 1) * STG_H) * 2u;
        uint32_t A_h = sb;
        uint32_t B_h = sb + TILE_H * 2u;
        uint32_t B_l = sb + 2u * TILE_H * 2u;

        #pragma unroll
        for (int kk = 0; kk < 32; kk += 16) {
            uint32_t bh[4][2], bl[4][2];
            #pragma unroll
            for (int p = 0; p < 2; p++) {
                int row = wn * 32 + p * 16 + l7 + ((lane & 16) >> 1);
                int kc  = kk + (lane & 8);
                uint32_t off = (uint32_t)(row * PK + kc) * 2u;
                ldm_x4(bh[2*p][0], bh[2*p][1], bh[2*p+1][0], bh[2*p+1][1], B_h + off);
                if (TERMS == 2)
                    ldm_x4(bl[2*p][0], bl[2*p][1], bl[2*p+1][0], bl[2*p+1][1], B_l + off);
            }
            #pragma unroll
            for (int mi = 0; mi < 4; mi++) {
                int row = wm * 64 + mi * 16 + l7 + (lane & 8);
                int kc  = kk + ((lane & 16) >> 1);
                uint32_t off = (uint32_t)(row * PK + kc) * 2u;
                uint32_t ah0, ah1, ah2, ah3;
                ldm_x4(ah0, ah1, ah2, ah3, A_h + off);
                #pragma unroll
                for (int ni = 0; ni < 4; ni++) {
                    float* d = acc[mi][ni];
                    mma_f16(d[0], d[1], d[2], d[3], ah0, ah1, ah2, ah3, bh[ni][0], bh[ni][1]);
                    if (TERMS == 2)
                        mma_f16(d[0], d[1], d[2], d[3], ah0, ah1, ah2, ah3, bl[ni][0], bl[ni][1]);
                }
            }
        }
    }

    // --- epilogue ---
    const float* bias = b0p;
    float* Cd = C;
    __half* Chd = Ch;
    int csub = 0, Nw = N;
    if (EPI == EPI_QKV) {
        int sel = n0 >> 10;
        bias = (sel == 0) ? b0p : (sel == 1) ? b1p : b2p;
        Chd = Ch + (long)sel * BT * Dm;
        csub = sel << 10;
        Nw = Dm;
    }

    #pragma unroll
    for (int mi = 0; mi < 4; mi++) {
        int r0 = m0 + wm * 64 + mi * 16 + g;
        #pragma unroll
        for (int ni = 0; ni < 4; ni++) {
            int cc = n0 + wn * 32 + ni * 8 + 2 * t;
            float b0v = bias ? bias[cc - csub] : 0.f;
            float b1v = bias ? bias[cc - csub + 1] : 0.f;
            float v0 = acc[mi][ni][0] + b0v, v1 = acc[mi][ni][1] + b1v;
            float v2 = acc[mi][ni][2] + b0v, v3 = acc[mi][ni][3] + b1v;
            long i0 = (long)r0 * Nw + (cc - csub);
            long i1 = (long)(r0 + 8) * Nw + (cc - csub);
            if (EPI == EPI_ADD) {
                v0 += res[i0]; v1 += res[i0 + 1];
                v2 += res[i1]; v3 += res[i1 + 1];
            }
            if (EPI == EPI_GELU) {
                v0 = 0.5f * v0 * (1.f + erff(v0 * 0.70710678118654752f));
                v1 = 0.5f * v1 * (1.f + erff(v1 * 0.70710678118654752f));
                v2 = 0.5f * v2 * (1.f + erff(v2 * 0.70710678118654752f));
                v3 = 0.5f * v3 * (1.f + erff(v3 * 0.70710678118654752f));
            }
            if (EPI == EPI_GELU || EPI == EPI_QKV) {
                *(__half2*)(Chd + i0) = __halves2half2(__float2half_rn(v0), __float2half_rn(v1));
                *(__half2*)(Chd + i1) = __halves2half2(__float2half_rn(v2), __float2half_rn(v3));
            } else {
                *(float2*)(Cd + i0) = make_float2(v0, v1);
                *(float2*)(Cd + i1) = make_float2(v2, v3);
            }
        }
    }
}

// ---------------------------------------------------------------------------
// Flash attention (HMMA, causal), double-buffered K/V pipeline.
// q/k/v f16 inputs, f16 output. Block = 128 q rows (8 warps x 16),
// K/V tiles of 64 tokens. smem: Q(128) + 2x(K64+V64) rows of 72 halfs.
// ---------------------------------------------------------------------------
#define APD 72
#define ATT_SMEM ((128 + 4 * 64) * APD * 2)

__global__ __launch_bounds__(256, 2) void attn_hmma(
    const __half* __restrict__ Qg, const __half* __restrict__ Kg,
    const __half* __restrict__ Vg, __half* __restrict__ Y)
{
    extern __shared__ __align__(16) __half asmem[];
    const uint32_t sb = smem_u32(asmem);
    const uint32_t Qs  = sb;
    const uint32_t KVs = sb + 128 * APD * 2;   // buf b: K at KVs + b*128*APD*2, V = K + 64*APD*2

    const int qt = blockIdx.x, h = blockIdx.y, b = blockIdx.z;
    const int tid = threadIdx.x, lane = tid & 31, warp = tid >> 5;
    const int g = lane >> 2, c2 = (lane & 3) * 2;

    const long rowbase = (long)(b * Tq + qt * 128);
    const __half* qsrc = Qg + rowbase * Dm + h * HD;

    // group A: Q tile 128x64
    #pragma unroll
    for (int j = 0; j < 4; j++) {
        int c = tid + 256 * j;
        int r = c >> 3, col8 = (c & 7) * 8;
        cpa16(Qs + (uint32_t)(r * APD + col8) * 2u, qsrc + (long)r * Dm + col8);
    }
    asm volatile("cp.async.commit_group;" ::: "memory");

    auto issue_kv = [&](int kt, int buf) {
        const long krow = (long)(b * Tq + kt * 64);
        uint32_t Kb = KVs + (uint32_t)(buf * 128 * APD) * 2u;
        uint32_t Vb = Kb + (uint32_t)(64 * APD) * 2u;
        #pragma unroll
        for (int j = 0; j < 4; j++) {
            int c = tid + 256 * j;
            int tsel = c >> 9;
            int r = (c >> 3) & 63, col8 = (c & 7) * 8;
            const __half* src = (tsel ? Vg : Kg) + (krow + r) * (long)Dm + h * HD + col8;
            uint32_t dst = (tsel ? Vb : Kb) + (uint32_t)(r * APD + col8) * 2u;
            cpa16(dst, src);
        }
        asm volatile("cp.async.commit_group;" ::: "memory");
    };

    issue_kv(0, 0);                              // group B

    // wait for Q (group A) only; kv0 may still be in flight
    asm volatile("cp.async.wait_group 1;" ::: "memory");
    __syncthreads();

    uint32_t qf[4][4];
    #pragma unroll
    for (int kf = 0; kf < 4; kf++) {
        uint32_t addr = Qs + (uint32_t)((warp * 16 + (lane & 15)) * APD
                                        + kf * 16 + ((lane >> 4) & 1) * 8) * 2u;
        ldm_x4(qf[kf][0], qf[kf][1], qf[kf][2], qf[kf][3], addr);
    }

    const int r0g = qt * 128 + warp * 16 + g;
    const int q_hi = qt * 128 + warp * 16 + 15;

    float O[8][4];
    #pragma unroll
    for (int nf = 0; nf < 8; nf++)
        #pragma unroll
        for (int j = 0; j < 4; j++) O[nf][j] = 0.f;
    float m0 = -1e30f, m1 = -1e30f, l0 = 0.f, l1 = 0.f;

    const int ktmax = qt * 2 + 1;
    for (int kt = 0; kt <= ktmax; kt++) {
        asm volatile("cp.async.wait_group 0;" ::: "memory");
        __syncthreads();
        if (kt + 1 <= ktmax) issue_kv(kt + 1, (kt + 1) & 1);

        uint32_t Kb = KVs + (uint32_t)((kt & 1) * 128 * APD) * 2u;
        uint32_t Vb = Kb + (uint32_t)(64 * APD) * 2u;

        if (kt * 64 <= q_hi) {
            float S[8][4];
            #pragma unroll
            for (int nf = 0; nf < 8; nf++)
                #pragma unroll
                for (int j = 0; j < 4; j++) S[nf][j] = 0.f;

            #pragma unroll
            for (int tg = 0; tg < 4; tg++) {
                #pragma unroll
                for (int kf = 0; kf < 4; kf++) {
                    uint32_t k0, k1, k2, k3;
                    uint32_t addr = Kb + (uint32_t)((tg * 16 + (lane & 15)) * APD
                                                    + kf * 16 + ((lane >> 4) & 1) * 8) * 2u;
                    ldm_x4(k0, k1, k2, k3, addr);
                    mma_f16(S[2*tg][0], S[2*tg][1], S[2*tg][2], S[2*tg][3],
                            qf[kf][0], qf[kf][1], qf[kf][2], qf[kf][3], k0, k2);
                    mma_f16(S[2*tg+1][0], S[2*tg+1][1], S[2*tg+1][2], S[2*tg+1][3],
                            qf[kf][0], qf[kf][1], qf[kf][2], qf[kf][3], k1, k3);
                }
            }

            const float scale = 0.125f;
            #pragma unroll
            for (int nf = 0; nf < 8; nf++)
                #pragma unroll
                for (int j = 0; j < 4; j++) S[nf][j] *= scale;

            if (kt * 64 + 63 > r0g) {
                #pragma unroll
                for (int nf = 0; nf < 8; nf++) {
                    int col = kt * 64 + nf * 8 + c2;
                    if (col     > r0g)     S[nf][0] = -1e30f;
                    if (col + 1 > r0g)     S[nf][1] = -1e30f;
                    if (col     > r0g + 8) S[nf][2] = -1e30f;
                    if (col + 1 > r0g + 8) S[nf][3] = -1e30f;
                }
            }

            float rmax0 = -1e30f, rmax1 = -1e30f;
            #pragma unroll
            for (int nf = 0; nf < 8; nf++) {
                rmax0 = fmaxf(rmax0, fmaxf(S[nf][0], S[nf][1]));
                rmax1 = fmaxf(rmax1, fmaxf(S[nf][2], S[nf][3]));
            }
            #pragma unroll
            for (int m = 1; m <= 2; m <<= 1) {
                rmax0 = fmaxf(rmax0, __shfl_xor_sync(0xffffffffu, rmax0, m));
                rmax1 = fmaxf(rmax1, __shfl_xor_sync(0xffffffffu, rmax1, m));
            }
            float mn0 = fmaxf(m0, rmax0), mn1 = fmaxf(m1, rmax1);
            float a0 = __expf(m0 - mn0), a1 = __expf(m1 - mn1);
            m0 = mn0; m1 = mn1;

            float rs0 = 0.f, rs1 = 0.f;
            uint32_t pa[4][4];
            #pragma unroll
            for (int nf = 0; nf < 8; nf++) {
                float p0 = __expf(S[nf][0] - mn0);
                float p1 = __expf(S[nf][1] - mn0);
                float p2 = __expf(S[nf][2] - mn1);
                float p3 = __expf(S[nf][3] - mn1);
                rs0 += p0 + p1; rs1 += p2 + p3;
                pa[nf >> 1][(nf & 1) * 2 + 0] = packh2(p0, p1);
                pa[nf >> 1][(nf & 1) * 2 + 1] = packh2(p2, p3);
            }
            #pragma unroll
            for (int m = 1; m <= 2; m <<= 1) {
                rs0 += __shfl_xor_sync(0xffffffffu, rs0, m);
                rs1 += __shfl_xor_sync(0xffffffffu, rs1, m);
            }
            l0 = l0 * a0 + rs0;
            l1 = l1 * a1 + rs1;
            #pragma unroll
            for (int nf = 0; nf < 8; nf++) {
                O[nf][0] *= a0; O[nf][1] *= a0;
                O[nf][2] *= a1; O[nf][3] *= a1;
            }

            #pragma unroll
            for (int kf = 0; kf < 4; kf++) {
                #pragma unroll
                for (int hg = 0; hg < 4; hg++) {
                    uint32_t v0, v1, v2, v3;
                    uint32_t addr = Vb + (uint32_t)((kf * 16 + (lane & 15)) * APD
                                                    + hg * 16 + ((lane >> 4) & 1) * 8) * 2u;
                    ldm_x4t(v0, v1, v2, v3, addr);
                    mma_f16(O[2*hg][0], O[2*hg][1], O[2*hg][2], O[2*hg][3],
                            pa[kf][0], pa[kf][1], pa[kf][2], pa[kf][3], v0, v1);
                    mma_f16(O[2*hg+1][0], O[2*hg+1][1], O[2*hg+1][2], O[2*hg+1][3],
                            pa[kf][0], pa[kf][1], pa[kf][2], pa[kf][3], v2, v3);
                }
            }
        }
    }

    float inv0 = 1.f / l0, inv1 = 1.f / l1;
    long ybase0 = (rowbase + warp * 16 + g) * (long)Dm + h * HD;
    long ybase1 = ybase0 + 8L * Dm;
    #pragma unroll
    for (int nf = 0; nf < 8; nf++) {
        int col = nf * 8 + c2;
        *(__half2*)(Y + ybase0 + col) =
            __halves2half2(__float2half_rn(O[nf][0] * inv0), __float2half_rn(O[nf][1] * inv0));
        *(__half2*)(Y + ybase1 + col) =
            __halves2half2(__float2half_rn(O[nf][2] * inv1), __float2half_rn(O[nf][3] * inv1));
    }
}

// ---------------------------------------------------------------------------
// Launcher
// ---------------------------------------------------------------------------
extern "C" void kernel_launch(void* const* d_in, const int* in_sizes, int n_in,
                              void* d_out, int out_size)
{
    const int*   idx  = (const int*)  d_in[0];
    const int*   ts   = (const int*)  d_in[1];
    const float* tok  = (const float*)d_in[2];
    const float* pos  = (const float*)d_in[3];
    const float* gpos = (const float*)d_in[4];
    const float* ln1w = (const float*)d_in[5];
    const float* ln1b = (const float*)d_in[6];
    const float* Wq   = (const float*)d_in[7];
    const float* bq   = (const float*)d_in[8];
    const float* Wk   = (const float*)d_in[9];
    const float* bk   = (const float*)d_in[10];
    const float* Wv   = (const float*)d_in[11];
    const float* bv   = (const float*)d_in[12];
    const float* Wo   = (const float*)d_in[13];
    const float* bo   = (const float*)d_in[14];
    const float* ln2w = (const float*)d_in[15];
    const float* ln2b = (const float*)d_in[16];
    const float* W1   = (const float*)d_in[17];
    const float* b1   = (const float*)d_in[18];
    const float* W2   = (const float*)d_in[19];
    const float* b2   = (const float*)d_in[20];
    const float* lnfw = (const float*)d_in[21];
    const float* lnfb = (const float*)d_in[22];
    const float* hw   = (const float*)d_in[23];
    float* out = (float*)d_out;

    float* x;
    __half *qkvh, *pa, *pb, *wh, *wl;
    cudaGetSymbolAddress((void**)&x,    g_x);
    cudaGetSymbolAddress((void**)&qkvh, g_qkvh);
    cudaGetSymbolAddress((void**)&pa,   g_pa);
    cudaGetSymbolAddress((void**)&pb,   g_pb);
    cudaGetSymbolAddress((void**)&wh,   g_wh);
    cudaGetSymbolAddress((void**)&wl,   g_wl);

    cudaFuncSetAttribute(attn_hmma, cudaFuncAttributeMaxDynamicSharedMemorySize, ATT_SMEM);
    cudaFuncSetAttribute((gemm_hmma<EPI_QKV, 1>),  cudaFuncAttributeMaxDynamicSharedMemorySize, GEMM_SMEM);
    cudaFuncSetAttribute((gemm_hmma<EPI_GELU, 1>), cudaFuncAttributeMaxDynamicSharedMemorySize, GEMM_SMEM);
    cudaFuncSetAttribute((gemm_hmma<EPI_ADD, 2>),  cudaFuncAttributeMaxDynamicSharedMemorySize, GEMM_SMEM);
    cudaFuncSetAttribute((gemm_hmma<EPI_NONE, 1>), cudaFuncAttributeMaxDynamicSharedMemorySize, GEMM_SMEM);

    auto cvt2 = [&](const float* src, long off, long n) {
        cvt_pair<<<(int)((n / 4 + 255) / 256), 256>>>(src, wh + off, wl + off, n);
    };
    auto cvt1 = [&](const float* src, long off, long n) {
        cvt_hi<<<(int)((n / 4 + 255) / 256), 256>>>(src, wh + off, n);
    };

    const dim3 gD(Dm / 128, BT / 128);
    const dim3 gQKV(3 * Dm / 128, BT / 128);
    const dim3 g2D(2 * Dm / 128, BT / 128);
    const dim3 gV(Vv / 128, BT / 128);

    __half* qb = qkvh;
    __half* kb = qkvh + (long)BT * Dm;
    __half* vb = qkvh + 2L * BT * Dm;

    cvt1(Wq, OFF_WQ, 8L * DD);
    cvt1(Wk, OFF_WK, 8L * DD);
    cvt1(Wv, OFF_WV, 8L * DD);
    embed_ln<<<BT, 256>>>(idx, ts, tok, pos, gpos, ln1w, ln1b, x, pa);

    bool cvted = false;

    for (int l = 0; l < Ll; l++) {
        if (l > 0)
            layernorm_f16<<<BT, 256>>>(x, ln1w + (long)l * Dm, ln1b + (long)l * Dm, pa);

        gemm_hmma<EPI_QKV, 1><<<gQKV, 256, GEMM_SMEM>>>(
            pa, wh + OFF_WQ + (long)l * DD, nullptr,
            8L * DD,
            bq + (long)l * Dm, bk + (long)l * Dm, bv + (long)l * Dm,
            nullptr, nullptr, qkvh, BT, 3 * Dm, Dm);

        attn_hmma<<<dim3(Tq / 128, Hh, Bq), 256, ATT_SMEM>>>(qb, kb, vb, pa);

        if (!cvted) cvt2(Wo, OFF_WO, 8L * DD);

        gemm_hmma<EPI_ADD, 2><<<gD, 256, GEMM_SMEM>>>(
            pa, wh + OFF_WO + (long)l * DD, wl + OFF_WO + (long)l * DD, 0,
            bo + (long)l * Dm, nullptr, nullptr, x, x, nullptr, BT, Dm, Dm);

        layernorm_f16<<<BT, 256>>>(x, ln2w + (long)l * Dm, ln2b + (long)l * Dm, pa);

        if (!cvted) cvt1(W1, OFF_W1, 16L * DD);

        gemm_hmma<EPI_GELU, 1><<<g2D, 256, GEMM_SMEM>>>(
            pa, wh + OFF_W1 + (long)l * 2 * DD, nullptr, 0,
            b1 + (long)l * 2 * Dm, nullptr, nullptr, nullptr,
            nullptr, pb, BT, 2 * Dm, Dm);

        if (!cvted) { cvt2(W2, OFF_W2, 16L * DD); cvted = true; }

        gemm_hmma<EPI_ADD, 2><<<gD, 256, GEMM_SMEM>>>(
            pb, wh + OFF_W2 + (long)l * 2 * DD, wl + OFF_W2 + (long)l * 2 * DD, 0,
            b2 + (long)l * Dm, nullptr, nullptr, x, x, nullptr, BT, Dm, 2 * Dm);
    }

    layernorm_f16<<<BT, 256>>>(x, lnfw, lnfb, pa);
    cvt1(hw, OFF_HW, 8L * DD);
    gemm_hmma<EPI_NONE, 1><<<gV, 256, GEMM_SMEM>>>(
        pa, wh + OFF_HW, nullptr, 0,
        nullptr, nullptr, nullptr, nullptr, out, nullptr, BT, Vv, Dm);
}

// round 15
// speedup vs baseline: 5.4748x; 1.1202x over previous
#include <cuda_runtime.h>
#include <cuda_fp16.h>
#include <math.h>
#include <stdint.h>

// ---------------------------------------------------------------------------
// Problem constants
// ---------------------------------------------------------------------------
#define Bq   8
#define Tq   1024
#define Dm   1024
#define Hh   16
#define Ll   8
#define Vv   8192
#define HD   64
#define BT   (Bq*Tq)

// ---------------------------------------------------------------------------
// Scratch (static device globals)
// ---------------------------------------------------------------------------
__device__ float  g_x[BT * Dm];          // residual stream (f32)
__device__ __half g_qkvh[3L * BT * Dm];  // q | k | v  (f16)

__device__ __half g_pa[BT * Dm];         // act buf A: LN out / attn out
__device__ __half g_pb[BT * 2 * Dm];     // act buf B: MLP hidden

#define DD      (Dm*Dm)
#define OFF_WQ  0L
#define OFF_WK  (8L*DD)
#define OFF_WV  (16L*DD)
#define OFF_WO  (24L*DD)
#define OFF_W1  (32L*DD)
#define OFF_W2  (48L*DD)
#define OFF_HW  (64L*DD)
#define WTOT    (72L*DD)
__device__ __half g_wh[WTOT];
__device__ __half g_wl[WTOT];            // lo slices: Wo only

// ---------------------------------------------------------------------------
// Helpers
// ---------------------------------------------------------------------------
__device__ __forceinline__ uint32_t smem_u32(const void* p) {
    uint32_t a;
    asm("{ .reg .u64 t; cvta.to.shared.u64 t, %1; cvt.u32.u64 %0, t; }"
        : "=r"(a) : "l"(p));
    return a;
}
__device__ __forceinline__ void cpa16(uint32_t dst, const void* src) {
    asm volatile("cp.async.cg.shared.global [%0], [%1], 16;" :: "r"(dst), "l"(src));
}
__device__ __forceinline__ void ldm_x4(uint32_t& r0, uint32_t& r1,
                                       uint32_t& r2, uint32_t& r3, uint32_t addr) {
    asm volatile("ldmatrix.sync.aligned.m8n8.x4.shared.b16 {%0,%1,%2,%3}, [%4];"
                 : "=r"(r0), "=r"(r1), "=r"(r2), "=r"(r3) : "r"(addr));
}
__device__ __forceinline__ void ldm_x4t(uint32_t& r0, uint32_t& r1,
                                        uint32_t& r2, uint32_t& r3, uint32_t addr) {
    asm volatile("ldmatrix.sync.aligned.m8n8.x4.trans.shared.b16 {%0,%1,%2,%3}, [%4];"
                 : "=r"(r0), "=r"(r1), "=r"(r2), "=r"(r3) : "r"(addr));
}
__device__ __forceinline__ void mma_f16(float& d0, float& d1, float& d2, float& d3,
                                        uint32_t a0, uint32_t a1, uint32_t a2, uint32_t a3,
                                        uint32_t b0, uint32_t b1) {
    asm volatile(
        "mma.sync.aligned.m16n8k16.row.col.f32.f16.f16.f32 "
        "{%0,%1,%2,%3}, {%4,%5,%6,%7}, {%8,%9}, {%0,%1,%2,%3};"
        : "+f"(d0), "+f"(d1), "+f"(d2), "+f"(d3)
        : "r"(a0), "r"(a1), "r"(a2), "r"(a3), "r"(b0), "r"(b1));
}
__device__ __forceinline__ void split16(float x, __half& hi, __half& lo) {
    hi = __float2half_rn(x);
    lo = __float2half_rn(x - __half2float(hi));
}
__device__ __forceinline__ uint32_t packh2(float a, float b) {
    __half2 h = __halves2half2(__float2half_rn(a), __float2half_rn(b));
    return *(uint32_t*)&h;
}

// ---------------------------------------------------------------------------
// Weight conversions
// ---------------------------------------------------------------------------
__global__ __launch_bounds__(256) void cvt_pair(
    const float* __restrict__ s, __half* __restrict__ h,
    __half* __restrict__ l, long n)
{
    long i = ((long)blockIdx.x * 256 + threadIdx.x) * 4;
    if (i >= n) return;
    float4 v = *(const float4*)(s + i);
    __half h0, h1, h2, h3, l0, l1, l2, l3;
    split16(v.x, h0, l0); split16(v.y, h1, l1);
    split16(v.z, h2, l2); split16(v.w, h3, l3);
    *(__half2*)(h + i)     = __halves2half2(h0, h1);
    *(__half2*)(h + i + 2) = __halves2half2(h2, h3);
    *(__half2*)(l + i)     = __halves2half2(l0, l1);
    *(__half2*)(l + i + 2) = __halves2half2(l2, l3);
}
__global__ __launch_bounds__(256) void cvt_hi(
    const float* __restrict__ s, __half* __restrict__ h, long n)
{
    long i = ((long)blockIdx.x * 256 + threadIdx.x) * 4;
    if (i >= n) return;
    float4 v = *(const float4*)(s + i);
    *(__half2*)(h + i)     = __halves2half2(__float2half_rn(v.x), __float2half_rn(v.y));
    *(__half2*)(h + i + 2) = __halves2half2(__float2half_rn(v.z), __float2half_rn(v.w));
}

// ---------------------------------------------------------------------------
// Fused embedding + LayerNorm(layer0 ln1) -> x and f16 output
// ---------------------------------------------------------------------------
__global__ __launch_bounds__(256) void embed_ln(
    const int* __restrict__ idx, const int* __restrict__ ts,
    const float* __restrict__ tok, const float* __restrict__ pos,
    const float* __restrict__ gpos,
    const float* __restrict__ w, const float* __restrict__ b,
    float* __restrict__ X, __half* __restrict__ Y)
{
    int row = blockIdx.x;
    int t = row & (Tq - 1);
    int bb = row >> 10;
    int tid = threadIdx.x;
    int i = tid * 4;

    float4 tv = *(const float4*)(tok + (long)idx[row] * Dm + i);
    float4 gv = *(const float4*)(gpos + (long)ts[bb] * Dm + i);
    float4 pv = *(const float4*)(pos + (long)t * Dm + i);
    float4 v;
    v.x = tv.x + gv.x + pv.x;
    v.y = tv.y + gv.y + pv.y;
    v.z = tv.z + gv.z + pv.z;
    v.w = tv.w + gv.w + pv.w;

    long base = (long)row * Dm + i;
    *(float4*)(X + base) = v;

    float s  = v.x + v.y + v.z + v.w;
    float ss = v.x*v.x + v.y*v.y + v.z*v.z + v.w*v.w;

    __shared__ float rs[8], rss[8];
    #pragma unroll
    for (int m = 16; m; m >>= 1) {
        s  += __shfl_xor_sync(0xffffffffu, s,  m);
        ss += __shfl_xor_sync(0xffffffffu, ss, m);
    }
    int wid = tid >> 5, lane = tid & 31;
    if (lane == 0) { rs[wid] = s; rss[wid] = ss; }
    __syncthreads();
    if (wid == 0) {
        s  = (lane < 8) ? rs[lane]  : 0.f;
        ss = (lane < 8) ? rss[lane] : 0.f;
        #pragma unroll
        for (int m = 4; m; m >>= 1) {
            s  += __shfl_xor_sync(0xffffffffu, s,  m);
            ss += __shfl_xor_sync(0xffffffffu, ss, m);
        }
        if (lane == 0) { rs[0] = s; rss[0] = ss; }
    }
    __syncthreads();
    float mean = rs[0] * (1.0f / Dm);
    float var  = rss[0] * (1.0f / Dm) - mean * mean;
    float rstd = rsqrtf(var + 1e-5f);

    float4 wv = *(const float4*)(w + i);
    float4 bv = *(const float4*)(b + i);
    float o0 = (v.x - mean) * rstd * wv.x + bv.x;
    float o1 = (v.y - mean) * rstd * wv.y + bv.y;
    float o2 = (v.z - mean) * rstd * wv.z + bv.z;
    float o3 = (v.w - mean) * rstd * wv.w + bv.w;

    *(__half2*)(Y + base)     = __halves2half2(__float2half_rn(o0), __float2half_rn(o1));
    *(__half2*)(Y + base + 2) = __halves2half2(__float2half_rn(o2), __float2half_rn(o3));
}

// ---------------------------------------------------------------------------
// LayerNorm -> f16 output
// ---------------------------------------------------------------------------
__global__ __launch_bounds__(256) void layernorm_f16(
    const float* __restrict__ X, const float* __restrict__ w,
    const float* __restrict__ b, __half* __restrict__ Y)
{
    int row = blockIdx.x;
    const float* x = X + (long)row * Dm;
    int tid = threadIdx.x;

    int i = tid * 4;
    float4 v = *(const float4*)(x + i);
    float s  = v.x + v.y + v.z + v.w;
    float ss = v.x*v.x + v.y*v.y + v.z*v.z + v.w*v.w;

    __shared__ float rs[8], rss[8];
    #pragma unroll
    for (int m = 16; m; m >>= 1) {
        s  += __shfl_xor_sync(0xffffffffu, s,  m);
        ss += __shfl_xor_sync(0xffffffffu, ss, m);
    }
    int wid = tid >> 5, lane = tid & 31;
    if (lane == 0) { rs[wid] = s; rss[wid] = ss; }
    __syncthreads();
    if (wid == 0) {
        s  = (lane < 8) ? rs[lane]  : 0.f;
        ss = (lane < 8) ? rss[lane] : 0.f;
        #pragma unroll
        for (int m = 4; m; m >>= 1) {
            s  += __shfl_xor_sync(0xffffffffu, s,  m);
            ss += __shfl_xor_sync(0xffffffffu, ss, m);
        }
        if (lane == 0) { rs[0] = s; rss[0] = ss; }
    }
    __syncthreads();
    float mean = rs[0] * (1.0f / Dm);
    float var  = rss[0] * (1.0f / Dm) - mean * mean;
    float rstd = rsqrtf(var + 1e-5f);

    float4 wv = *(const float4*)(w + i);
    float4 bv = *(const float4*)(b + i);
    float o0 = (v.x - mean) * rstd * wv.x + bv.x;
    float o1 = (v.y - mean) * rstd * wv.y + bv.y;
    float o2 = (v.z - mean) * rstd * wv.z + bv.z;
    float o3 = (v.w - mean) * rstd * wv.w + bv.w;

    long base = (long)row * Dm + i;
    *(__half2*)(Y + base)     = __halves2half2(__float2half_rn(o0), __float2half_rn(o1));
    *(__half2*)(Y + base + 2) = __halves2half2(__float2half_rn(o2), __float2half_rn(o3));
}

// ---------------------------------------------------------------------------
// HMMA GEMM. TERMS=2: C = Ah·Bh + Ah·Bl ; TERMS=1: C = Ah·Bh.
// CTA 128x128, k-step 32, cp.async double buffer, 8 warps of 64x32.
// ---------------------------------------------------------------------------
#define EPI_NONE 0
#define EPI_ADD  1
#define EPI_GELU 2
#define EPI_QKV  3

#define PK      40
#define TILE_H  (128*PK)
#define STG_H   (3*TILE_H)
#define GEMM_SMEM (2*STG_H*2)

template<int EPI, int TERMS>
__global__ __launch_bounds__(256, 2) void gemm_hmma(
    const __half* __restrict__ Ah,
    const __half* __restrict__ Bh, const __half* __restrict__ Bl,
    long bStride,
    const float* __restrict__ b0p, const float* __restrict__ b1p,
    const float* __restrict__ b2p, const float* __restrict__ res,
    float* __restrict__ C, __half* __restrict__ Ch,
    int M, int N, int K)
{
    extern __shared__ __align__(16) __half gsm[];
    const uint32_t sbase = smem_u32(gsm);

    const int tid = threadIdx.x, lane = tid & 31, warp = tid >> 5;
    const int g = lane >> 2, t = lane & 3, l7 = lane & 7;
    const int wm = warp & 1, wn = warp >> 1;
    const int m0 = blockIdx.y * 128, n0 = blockIdx.x * 128;

    float acc[4][4][4];
    #pragma unroll
    for (int a = 0; a < 4; a++)
        #pragma unroll
        for (int b = 0; b < 4; b++)
            #pragma unroll
            for (int c = 0; c < 4; c++) acc[a][b][c] = 0.f;

    const int S = K >> 5;
    const int NCH = (TERMS == 2) ? 6 : 4;

    auto issue = [&](int k0, int buf) {
        #pragma unroll
        for (int j = 0; j < NCH; j++) {
            int c = tid + 256 * j;
            int tile = c >> 9;
            int r = (c >> 2) & 127;
            int q = c & 3;
            const __half* src;
            if (tile == 0) src = Ah + (long)(m0 + r) * K + k0 + q * 8;
            else {
                long roff;
                if (EPI == EPI_QKV) {
                    int rg = n0 + r;
                    roff = (long)(rg >> 10) * bStride + (long)(rg & 1023) * K;
                } else {
                    roff = (long)(n0 + r) * K;
                }
                src = (tile == 1 ? Bh : Bl) + roff + k0 + q * 8;
            }
            uint32_t dst = sbase + (uint32_t)(buf * STG_H + tile * TILE_H + r * PK + q * 8) * 2u;
            cpa16(dst, src);
        }
        asm volatile("cp.async.commit_group;" ::: "memory");
    };

    issue(0, 0);

    for (int s = 0; s < S; s++) {
        asm volatile("cp.async.wait_group 0;" ::: "memory");
        __syncthreads();
        if (s + 1 < S) issue((s + 1) << 5, (s + 1) & 1);

        uint32_t sb  = sbase + (uint32_t)((s & 1) * STG_H) * 2u;
        uint32_t A_h = sb;
        uint32_t B_h = sb + TILE_H * 2u;
        uint32_t B_l = sb + 2u * TILE_H * 2u;

        #pragma unroll
        for (int kk = 0; kk < 32; kk += 16) {
            uint32_t bh[4][2], bl[4][2];
            #pragma unroll
            for (int p = 0; p < 2; p++) {
                int row = wn * 32 + p * 16 + l7 + ((lane & 16) >> 1);
                int kc  = kk + (lane & 8);
                uint32_t off = (uint32_t)(row * PK + kc) * 2u;
                ldm_x4(bh[2*p][0], bh[2*p][1], bh[2*p+1][0], bh[2*p+1][1], B_h + off);
                if (TERMS == 2)
                    ldm_x4(bl[2*p][0], bl[2*p][1], bl[2*p+1][0], bl[2*p+1][1], B_l + off);
            }
            #pragma unroll
            for (int mi = 0; mi < 4; mi++) {
                int row = wm * 64 + mi * 16 + l7 + (lane & 8);
                int kc  = kk + ((lane & 16) >> 1);
                uint32_t off = (uint32_t)(row * PK + kc) * 2u;
                uint32_t ah0, ah1, ah2, ah3;
                ldm_x4(ah0, ah1, ah2, ah3, A_h + off);
                #pragma unroll
                for (int ni = 0; ni < 4; ni++) {
                    float* d = acc[mi][ni];
                    mma_f16(d[0], d[1], d[2], d[3], ah0, ah1, ah2, ah3, bh[ni][0], bh[ni][1]);
                    if (TERMS == 2)
                        mma_f16(d[0], d[1], d[2], d[3], ah0, ah1, ah2, ah3, bl[ni][0], bl[ni][1]);
                }
            }
        }
    }

    // --- epilogue ---
    const float* bias = b0p;
    float* Cd = C;
    __half* Chd = Ch;
    int csub = 0, Nw = N;
    if (EPI == EPI_QKV) {
        int sel = n0 >> 10;
        bias = (sel == 0) ? b0p : (sel == 1) ? b1p : b2p;
        Chd = Ch + (long)sel * BT * Dm;
        csub = sel << 10;
        Nw = Dm;
    }

    #pragma unroll
    for (int mi = 0; mi < 4; mi++) {
        int r0 = m0 + wm * 64 + mi * 16 + g;
        #pragma unroll
        for (int ni = 0; ni < 4; ni++) {
            int cc = n0 + wn * 32 + ni * 8 + 2 * t;
            float b0v = bias ? bias[cc - csub] : 0.f;
            float b1v = bias ? bias[cc - csub + 1] : 0.f;
            float v0 = acc[mi][ni][0] + b0v, v1 = acc[mi][ni][1] + b1v;
            float v2 = acc[mi][ni][2] + b0v, v3 = acc[mi][ni][3] + b1v;
            long i0 = (long)r0 * Nw + (cc - csub);
            long i1 = (long)(r0 + 8) * Nw + (cc - csub);
            if (EPI == EPI_ADD) {
                v0 += res[i0]; v1 += res[i0 + 1];
                v2 += res[i1]; v3 += res[i1 + 1];
            }
            if (EPI == EPI_GELU) {
                v0 = 0.5f * v0 * (1.f + erff(v0 * 0.70710678118654752f));
                v1 = 0.5f * v1 * (1.f + erff(v1 * 0.70710678118654752f));
                v2 = 0.5f * v2 * (1.f + erff(v2 * 0.70710678118654752f));
                v3 = 0.5f * v3 * (1.f + erff(v3 * 0.70710678118654752f));
            }
            if (EPI == EPI_GELU || EPI == EPI_QKV) {
                *(__half2*)(Chd + i0) = __halves2half2(__float2half_rn(v0), __float2half_rn(v1));
                *(__half2*)(Chd + i1) = __halves2half2(__float2half_rn(v2), __float2half_rn(v3));
            } else {
                *(float2*)(Cd + i0) = make_float2(v0, v1);
                *(float2*)(Cd + i1) = make_float2(v2, v3);
            }
        }
    }
}

// ---------------------------------------------------------------------------
// Flash attention (HMMA, causal), double-buffered K/V pipeline.
// ---------------------------------------------------------------------------
#define APD 72
#define ATT_SMEM ((128 + 4 * 64) * APD * 2)

__global__ __launch_bounds__(256, 2) void attn_hmma(
    const __half* __restrict__ Qg, const __half* __restrict__ Kg,
    const __half* __restrict__ Vg, __half* __restrict__ Y)
{
    extern __shared__ __align__(16) __half asmem[];
    const uint32_t sb = smem_u32(asmem);
    const uint32_t Qs  = sb;
    const uint32_t KVs = sb + 128 * APD * 2;

    const int qt = blockIdx.x, h = blockIdx.y, b = blockIdx.z;
    const int tid = threadIdx.x, lane = tid & 31, warp = tid >> 5;
    const int g = lane >> 2, c2 = (lane & 3) * 2;

    const long rowbase = (long)(b * Tq + qt * 128);
    const __half* qsrc = Qg + rowbase * Dm + h * HD;

    #pragma unroll
    for (int j = 0; j < 4; j++) {
        int c = tid + 256 * j;
        int r = c >> 3, col8 = (c & 7) * 8;
        cpa16(Qs + (uint32_t)(r * APD + col8) * 2u, qsrc + (long)r * Dm + col8);
    }
    asm volatile("cp.async.commit_group;" ::: "memory");

    auto issue_kv = [&](int kt, int buf) {
        const long krow = (long)(b * Tq + kt * 64);
        uint32_t Kb = KVs + (uint32_t)(buf * 128 * APD) * 2u;
        uint32_t Vb = Kb + (uint32_t)(64 * APD) * 2u;
        #pragma unroll
        for (int j = 0; j < 4; j++) {
            int c = tid + 256 * j;
            int tsel = c >> 9;
            int r = (c >> 3) & 63, col8 = (c & 7) * 8;
            const __half* src = (tsel ? Vg : Kg) + (krow + r) * (long)Dm + h * HD + col8;
            uint32_t dst = (tsel ? Vb : Kb) + (uint32_t)(r * APD + col8) * 2u;
            cpa16(dst, src);
        }
        asm volatile("cp.async.commit_group;" ::: "memory");
    };

    issue_kv(0, 0);

    asm volatile("cp.async.wait_group 1;" ::: "memory");
    __syncthreads();

    uint32_t qf[4][4];
    #pragma unroll
    for (int kf = 0; kf < 4; kf++) {
        uint32_t addr = Qs + (uint32_t)((warp * 16 + (lane & 15)) * APD
                                        + kf * 16 + ((lane >> 4) & 1) * 8) * 2u;
        ldm_x4(qf[kf][0], qf[kf][1], qf[kf][2], qf[kf][3], addr);
    }

    const int r0g = qt * 128 + warp * 16 + g;
    const int q_hi = qt * 128 + warp * 16 + 15;

    float O[8][4];
    #pragma unroll
    for (int nf = 0; nf < 8; nf++)
        #pragma unroll
        for (int j = 0; j < 4; j++) O[nf][j] = 0.f;
    float m0 = -1e30f, m1 = -1e30f, l0 = 0.f, l1 = 0.f;

    const int ktmax = qt * 2 + 1;
    for (int kt = 0; kt <= ktmax; kt++) {
        asm volatile("cp.async.wait_group 0;" ::: "memory");
        __syncthreads();
        if (kt + 1 <= ktmax) issue_kv(kt + 1, (kt + 1) & 1);

        uint32_t Kb = KVs + (uint32_t)((kt & 1) * 128 * APD) * 2u;
        uint32_t Vb = Kb + (uint32_t)(64 * APD) * 2u;

        if (kt * 64 <= q_hi) {
            float S[8][4];
            #pragma unroll
            for (int nf = 0; nf < 8; nf++)
                #pragma unroll
                for (int j = 0; j < 4; j++) S[nf][j] = 0.f;

            #pragma unroll
            for (int tg = 0; tg < 4; tg++) {
                #pragma unroll
                for (int kf = 0; kf < 4; kf++) {
                    uint32_t k0, k1, k2, k3;
                    uint32_t addr = Kb + (uint32_t)((tg * 16 + (lane & 15)) * APD
                                                    + kf * 16 + ((lane >> 4) & 1) * 8) * 2u;
                    ldm_x4(k0, k1, k2, k3, addr);
                    mma_f16(S[2*tg][0], S[2*tg][1], S[2*tg][2], S[2*tg][3],
                            qf[kf][0], qf[kf][1], qf[kf][2], qf[kf][3], k0, k2);
                    mma_f16(S[2*tg+1][0], S[2*tg+1][1], S[2*tg+1][2], S[2*tg+1][3],
                            qf[kf][0], qf[kf][1], qf[kf][2], qf[kf][3], k1, k3);
                }
            }

            const float scale = 0.125f;
            #pragma unroll
            for (int nf = 0; nf < 8; nf++)
                #pragma unroll
                for (int j = 0; j < 4; j++) S[nf][j] *= scale;

            if (kt * 64 + 63 > r0g) {
                #pragma unroll
                for (int nf = 0; nf < 8; nf++) {
                    int col = kt * 64 + nf * 8 + c2;
                    if (col     > r0g)     S[nf][0] = -1e30f;
                    if (col + 1 > r0g)     S[nf][1] = -1e30f;
                    if (col     > r0g + 8) S[nf][2] = -1e30f;
                    if (col + 1 > r0g + 8) S[nf][3] = -1e30f;
                }
            }

            float rmax0 = -1e30f, rmax1 = -1e30f;
            #pragma unroll
            for (int nf = 0; nf < 8; nf++) {
                rmax0 = fmaxf(rmax0, fmaxf(S[nf][0], S[nf][1]));
                rmax1 = fmaxf(rmax1, fmaxf(S[nf][2], S[nf][3]));
            }
            #pragma unroll
            for (int m = 1; m <= 2; m <<= 1) {
                rmax0 = fmaxf(rmax0, __shfl_xor_sync(0xffffffffu, rmax0, m));
                rmax1 = fmaxf(rmax1, __shfl_xor_sync(0xffffffffu, rmax1, m));
            }
            float mn0 = fmaxf(m0, rmax0), mn1 = fmaxf(m1, rmax1);
            float a0 = __expf(m0 - mn0), a1 = __expf(m1 - mn1);
            m0 = mn0; m1 = mn1;

            float rs0 = 0.f, rs1 = 0.f;
            uint32_t pa[4][4];
            #pragma unroll
            for (int nf = 0; nf < 8; nf++) {
                float p0 = __expf(S[nf][0] - mn0);
                float p1 = __expf(S[nf][1] - mn0);
                float p2 = __expf(S[nf][2] - mn1);
                float p3 = __expf(S[nf][3] - mn1);
                rs0 += p0 + p1; rs1 += p2 + p3;
                pa[nf >> 1][(nf & 1) * 2 + 0] = packh2(p0, p1);
                pa[nf >> 1][(nf & 1) * 2 + 1] = packh2(p2, p3);
            }
            #pragma unroll
            for (int m = 1; m <= 2; m <<= 1) {
                rs0 += __shfl_xor_sync(0xffffffffu, rs0, m);
                rs1 += __shfl_xor_sync(0xffffffffu, rs1, m);
            }
            l0 = l0 * a0 + rs0;
            l1 = l1 * a1 + rs1;
            #pragma unroll
            for (int nf = 0; nf < 8; nf++) {
                O[nf][0] *= a0; O[nf][1] *= a0;
                O[nf][2] *= a1; O[nf][3] *= a1;
            }

            #pragma unroll
            for (int kf = 0; kf < 4; kf++) {
                #pragma unroll
                for (int hg = 0; hg < 4; hg++) {
                    uint32_t v0, v1, v2, v3;
                    uint32_t addr = Vb + (uint32_t)((kf * 16 + (lane & 15)) * APD
                                                    + hg * 16 + ((lane >> 4) & 1) * 8) * 2u;
                    ldm_x4t(v0, v1, v2, v3, addr);
                    mma_f16(O[2*hg][0], O[2*hg][1], O[2*hg][2], O[2*hg][3],
                            pa[kf][0], pa[kf][1], pa[kf][2], pa[kf][3], v0, v1);
                    mma_f16(O[2*hg+1][0], O[2*hg+1][1], O[2*hg+1][2], O[2*hg+1][3],
                            pa[kf][0], pa[kf][1], pa[kf][2], pa[kf][3], v2, v3);
                }
            }
        }
    }

    float inv0 = 1.f / l0, inv1 = 1.f / l1;
    long ybase0 = (rowbase + warp * 16 + g) * (long)Dm + h * HD;
    long ybase1 = ybase0 + 8L * Dm;
    #pragma unroll
    for (int nf = 0; nf < 8; nf++) {
        int col = nf * 8 + c2;
        *(__half2*)(Y + ybase0 + col) =
            __halves2half2(__float2half_rn(O[nf][0] * inv0), __float2half_rn(O[nf][1] * inv0));
        *(__half2*)(Y + ybase1 + col) =
            __halves2half2(__float2half_rn(O[nf][2] * inv1), __float2half_rn(O[nf][3] * inv1));
    }
}

// ---------------------------------------------------------------------------
// Launcher
// ---------------------------------------------------------------------------
extern "C" void kernel_launch(void* const* d_in, const int* in_sizes, int n_in,
                              void* d_out, int out_size)
{
    const int*   idx  = (const int*)  d_in[0];
    const int*   ts   = (const int*)  d_in[1];
    const float* tok  = (const float*)d_in[2];
    const float* pos  = (const float*)d_in[3];
    const float* gpos = (const float*)d_in[4];
    const float* ln1w = (const float*)d_in[5];
    const float* ln1b = (const float*)d_in[6];
    const float* Wq   = (const float*)d_in[7];
    const float* bq   = (const float*)d_in[8];
    const float* Wk   = (const float*)d_in[9];
    const float* bk   = (const float*)d_in[10];
    const float* Wv   = (const float*)d_in[11];
    const float* bv   = (const float*)d_in[12];
    const float* Wo   = (const float*)d_in[13];
    const float* bo   = (const float*)d_in[14];
    const float* ln2w = (const float*)d_in[15];
    const float* ln2b = (const float*)d_in[16];
    const float* W1   = (const float*)d_in[17];
    const float* b1   = (const float*)d_in[18];
    const float* W2   = (const float*)d_in[19];
    const float* b2   = (const float*)d_in[20];
    const float* lnfw = (const float*)d_in[21];
    const float* lnfb = (const float*)d_in[22];
    const float* hw   = (const float*)d_in[23];
    float* out = (float*)d_out;

    float* x;
    __half *qkvh, *pa, *pb, *wh, *wl;
    cudaGetSymbolAddress((void**)&x,    g_x);
    cudaGetSymbolAddress((void**)&qkvh, g_qkvh);
    cudaGetSymbolAddress((void**)&pa,   g_pa);
    cudaGetSymbolAddress((void**)&pb,   g_pb);
    cudaGetSymbolAddress((void**)&wh,   g_wh);
    cudaGetSymbolAddress((void**)&wl,   g_wl);

    cudaFuncSetAttribute(attn_hmma, cudaFuncAttributeMaxDynamicSharedMemorySize, ATT_SMEM);
    cudaFuncSetAttribute((gemm_hmma<EPI_QKV, 1>),  cudaFuncAttributeMaxDynamicSharedMemorySize, GEMM_SMEM);
    cudaFuncSetAttribute((gemm_hmma<EPI_GELU, 1>), cudaFuncAttributeMaxDynamicSharedMemorySize, GEMM_SMEM);
    cudaFuncSetAttribute((gemm_hmma<EPI_ADD, 2>),  cudaFuncAttributeMaxDynamicSharedMemorySize, GEMM_SMEM);
    cudaFuncSetAttribute((gemm_hmma<EPI_ADD, 1>),  cudaFuncAttributeMaxDynamicSharedMemorySize, GEMM_SMEM);
    cudaFuncSetAttribute((gemm_hmma<EPI_NONE, 1>), cudaFuncAttributeMaxDynamicSharedMemorySize, GEMM_SMEM);

    auto cvt2 = [&](const float* src, long off, long n) {
        cvt_pair<<<(int)((n / 4 + 255) / 256), 256>>>(src, wh + off, wl + off, n);
    };
    auto cvt1 = [&](const float* src, long off, long n) {
        cvt_hi<<<(int)((n / 4 + 255) / 256), 256>>>(src, wh + off, n);
    };

    const dim3 gD(Dm / 128, BT / 128);
    const dim3 gQKV(3 * Dm / 128, BT / 128);
    const dim3 g2D(2 * Dm / 128, BT / 128);
    const dim3 gV(Vv / 128, BT / 128);

    __half* qb = qkvh;
    __half* kb = qkvh + (long)BT * Dm;
    __half* vb = qkvh + 2L * BT * Dm;

    cvt1(Wq, OFF_WQ, 8L * DD);
    cvt1(Wk, OFF_WK, 8L * DD);
    cvt1(Wv, OFF_WV, 8L * DD);
    embed_ln<<<BT, 256>>>(idx, ts, tok, pos, gpos, ln1w, ln1b, x, pa);

    bool cvted = false;

    for (int l = 0; l < Ll; l++) {
        if (l > 0)
            layernorm_f16<<<BT, 256>>>(x, ln1w + (long)l * Dm, ln1b + (long)l * Dm, pa);

        gemm_hmma<EPI_QKV, 1><<<gQKV, 256, GEMM_SMEM>>>(
            pa, wh + OFF_WQ + (long)l * DD, nullptr,
            8L * DD,
            bq + (long)l * Dm, bk + (long)l * Dm, bv + (long)l * Dm,
            nullptr, nullptr, qkvh, BT, 3 * Dm, Dm);

        attn_hmma<<<dim3(Tq / 128, Hh, Bq), 256, ATT_SMEM>>>(qb, kb, vb, pa);

        if (!cvted) cvt2(Wo, OFF_WO, 8L * DD);

        gemm_hmma<EPI_ADD, 2><<<gD, 256, GEMM_SMEM>>>(
            pa, wh + OFF_WO + (long)l * DD, wl + OFF_WO + (long)l * DD, 0,
            bo + (long)l * Dm, nullptr, nullptr, x, x, nullptr, BT, Dm, Dm);

        layernorm_f16<<<BT, 256>>>(x, ln2w + (long)l * Dm, ln2b + (long)l * Dm, pa);

        if (!cvted) cvt1(W1, OFF_W1, 16L * DD);

        gemm_hmma<EPI_GELU, 1><<<g2D, 256, GEMM_SMEM>>>(
            pa, wh + OFF_W1 + (long)l * 2 * DD, nullptr, 0,
            b1 + (long)l * 2 * Dm, nullptr, nullptr, nullptr,
            nullptr, pb, BT, 2 * Dm, Dm);

        if (!cvted) { cvt1(W2, OFF_W2, 16L * DD); cvted = true; }

        gemm_hmma<EPI_ADD, 1><<<gD, 256, GEMM_SMEM>>>(
            pb, wh + OFF_W2 + (long)l * 2 * DD, nullptr, 0,
            b2 + (long)l * Dm, nullptr, nullptr, x, x, nullptr, BT, Dm, 2 * Dm);
    }

    layernorm_f16<<<BT, 256>>>(x, lnfw, lnfb, pa);
    cvt1(hw, OFF_HW, 8L * DD);
    gemm_hmma<EPI_NONE, 1><<<gV, 256, GEMM_SMEM>>>(
        pa, wh + OFF_HW, nullptr, 0,
        nullptr, nullptr, nullptr, nullptr, out, nullptr, BT, Vv, Dm);
}

// round 16
// speedup vs baseline: 5.7563x; 1.0514x over previous
#include <cuda_runtime.h>
#include <cuda_fp16.h>
#include <math.h>
#include <stdint.h>

// ---------------------------------------------------------------------------
// Problem constants
// ---------------------------------------------------------------------------
#define Bq   8
#define Tq   1024
#define Dm   1024
#define Hh   16
#define Ll   8
#define Vv   8192
#define HD   64
#define BT   (Bq*Tq)

// ---------------------------------------------------------------------------
// Scratch (static device globals)
// ---------------------------------------------------------------------------
__device__ float  g_x[BT * Dm];          // residual stream (f32)
__device__ __half g_qkvh[3L * BT * Dm];  // q | k | v  (f16)

__device__ __half g_pa[BT * Dm];         // act buf A: LN out / attn out
__device__ __half g_pb[BT * 2 * Dm];     // act buf B: MLP hidden

#define DD      (Dm*Dm)
#define OFF_WQ  0L
#define OFF_WK  (8L*DD)
#define OFF_WV  (16L*DD)
#define OFF_WO  (24L*DD)
#define OFF_W1  (32L*DD)
#define OFF_W2  (48L*DD)
#define OFF_HW  (64L*DD)
#define WTOT    (72L*DD)
__device__ __half g_wh[WTOT];            // all weights, hi slice only (1-term)

// ---------------------------------------------------------------------------
// Helpers
// ---------------------------------------------------------------------------
__device__ __forceinline__ uint32_t smem_u32(const void* p) {
    uint32_t a;
    asm("{ .reg .u64 t; cvta.to.shared.u64 t, %1; cvt.u32.u64 %0, t; }"
        : "=r"(a) : "l"(p));
    return a;
}
__device__ __forceinline__ void cpa16(uint32_t dst, const void* src) {
    asm volatile("cp.async.cg.shared.global [%0], [%1], 16;" :: "r"(dst), "l"(src));
}
__device__ __forceinline__ void ldm_x4(uint32_t& r0, uint32_t& r1,
                                       uint32_t& r2, uint32_t& r3, uint32_t addr) {
    asm volatile("ldmatrix.sync.aligned.m8n8.x4.shared.b16 {%0,%1,%2,%3}, [%4];"
                 : "=r"(r0), "=r"(r1), "=r"(r2), "=r"(r3) : "r"(addr));
}
__device__ __forceinline__ void ldm_x4t(uint32_t& r0, uint32_t& r1,
                                        uint32_t& r2, uint32_t& r3, uint32_t addr) {
    asm volatile("ldmatrix.sync.aligned.m8n8.x4.trans.shared.b16 {%0,%1,%2,%3}, [%4];"
                 : "=r"(r0), "=r"(r1), "=r"(r2), "=r"(r3) : "r"(addr));
}
__device__ __forceinline__ void mma_f16(float& d0, float& d1, float& d2, float& d3,
                                        uint32_t a0, uint32_t a1, uint32_t a2, uint32_t a3,
                                        uint32_t b0, uint32_t b1) {
    asm volatile(
        "mma.sync.aligned.m16n8k16.row.col.f32.f16.f16.f32 "
        "{%0,%1,%2,%3}, {%4,%5,%6,%7}, {%8,%9}, {%0,%1,%2,%3};"
        : "+f"(d0), "+f"(d1), "+f"(d2), "+f"(d3)
        : "r"(a0), "r"(a1), "r"(a2), "r"(a3), "r"(b0), "r"(b1));
}
__device__ __forceinline__ uint32_t packh2(float a, float b) {
    __half2 h = __halves2half2(__float2half_rn(a), __float2half_rn(b));
    return *(uint32_t*)&h;
}

// ---------------------------------------------------------------------------
// Weight conversion (hi slice only)
// ---------------------------------------------------------------------------
__global__ __launch_bounds__(256) void cvt_hi(
    const float* __restrict__ s, __half* __restrict__ h, long n)
{
    long i = ((long)blockIdx.x * 256 + threadIdx.x) * 4;
    if (i >= n) return;
    float4 v = *(const float4*)(s + i);
    *(__half2*)(h + i)     = __halves2half2(__float2half_rn(v.x), __float2half_rn(v.y));
    *(__half2*)(h + i + 2) = __halves2half2(__float2half_rn(v.z), __float2half_rn(v.w));
}

// ---------------------------------------------------------------------------
// Fused embedding + LayerNorm(layer0 ln1) -> x and f16 output
// ---------------------------------------------------------------------------
__global__ __launch_bounds__(256) void embed_ln(
    const int* __restrict__ idx, const int* __restrict__ ts,
    const float* __restrict__ tok, const float* __restrict__ pos,
    const float* __restrict__ gpos,
    const float* __restrict__ w, const float* __restrict__ b,
    float* __restrict__ X, __half* __restrict__ Y)
{
    int row = blockIdx.x;
    int t = row & (Tq - 1);
    int bb = row >> 10;
    int tid = threadIdx.x;
    int i = tid * 4;

    float4 tv = *(const float4*)(tok + (long)idx[row] * Dm + i);
    float4 gv = *(const float4*)(gpos + (long)ts[bb] * Dm + i);
    float4 pv = *(const float4*)(pos + (long)t * Dm + i);
    float4 v;
    v.x = tv.x + gv.x + pv.x;
    v.y = tv.y + gv.y + pv.y;
    v.z = tv.z + gv.z + pv.z;
    v.w = tv.w + gv.w + pv.w;

    long base = (long)row * Dm + i;
    *(float4*)(X + base) = v;

    float s  = v.x + v.y + v.z + v.w;
    float ss = v.x*v.x + v.y*v.y + v.z*v.z + v.w*v.w;

    __shared__ float rs[8], rss[8];
    #pragma unroll
    for (int m = 16; m; m >>= 1) {
        s  += __shfl_xor_sync(0xffffffffu, s,  m);
        ss += __shfl_xor_sync(0xffffffffu, ss, m);
    }
    int wid = tid >> 5, lane = tid & 31;
    if (lane == 0) { rs[wid] = s; rss[wid] = ss; }
    __syncthreads();
    if (wid == 0) {
        s  = (lane < 8) ? rs[lane]  : 0.f;
        ss = (lane < 8) ? rss[lane] : 0.f;
        #pragma unroll
        for (int m = 4; m; m >>= 1) {
            s  += __shfl_xor_sync(0xffffffffu, s,  m);
            ss += __shfl_xor_sync(0xffffffffu, ss, m);
        }
        if (lane == 0) { rs[0] = s; rss[0] = ss; }
    }
    __syncthreads();
    float mean = rs[0] * (1.0f / Dm);
    float var  = rss[0] * (1.0f / Dm) - mean * mean;
    float rstd = rsqrtf(var + 1e-5f);

    float4 wv = *(const float4*)(w + i);
    float4 bv = *(const float4*)(b + i);
    float o0 = (v.x - mean) * rstd * wv.x + bv.x;
    float o1 = (v.y - mean) * rstd * wv.y + bv.y;
    float o2 = (v.z - mean) * rstd * wv.z + bv.z;
    float o3 = (v.w - mean) * rstd * wv.w + bv.w;

    *(__half2*)(Y + base)     = __halves2half2(__float2half_rn(o0), __float2half_rn(o1));
    *(__half2*)(Y + base + 2) = __halves2half2(__float2half_rn(o2), __float2half_rn(o3));
}

// ---------------------------------------------------------------------------
// LayerNorm -> f16 output
// ---------------------------------------------------------------------------
__global__ __launch_bounds__(256) void layernorm_f16(
    const float* __restrict__ X, const float* __restrict__ w,
    const float* __restrict__ b, __half* __restrict__ Y)
{
    int row = blockIdx.x;
    const float* x = X + (long)row * Dm;
    int tid = threadIdx.x;

    int i = tid * 4;
    float4 v = *(const float4*)(x + i);
    float s  = v.x + v.y + v.z + v.w;
    float ss = v.x*v.x + v.y*v.y + v.z*v.z + v.w*v.w;

    __shared__ float rs[8], rss[8];
    #pragma unroll
    for (int m = 16; m; m >>= 1) {
        s  += __shfl_xor_sync(0xffffffffu, s,  m);
        ss += __shfl_xor_sync(0xffffffffu, ss, m);
    }
    int wid = tid >> 5, lane = tid & 31;
    if (lane == 0) { rs[wid] = s; rss[wid] = ss; }
    __syncthreads();
    if (wid == 0) {
        s  = (lane < 8) ? rs[lane]  : 0.f;
        ss = (lane < 8) ? rss[lane] : 0.f;
        #pragma unroll
        for (int m = 4; m; m >>= 1) {
            s  += __shfl_xor_sync(0xffffffffu, s,  m);
            ss += __shfl_xor_sync(0xffffffffu, ss, m);
        }
        if (lane == 0) { rs[0] = s; rss[0] = ss; }
    }
    __syncthreads();
    float mean = rs[0] * (1.0f / Dm);
    float var  = rss[0] * (1.0f / Dm) - mean * mean;
    float rstd = rsqrtf(var + 1e-5f);

    float4 wv = *(const float4*)(w + i);
    float4 bv = *(const float4*)(b + i);
    float o0 = (v.x - mean) * rstd * wv.x + bv.x;
    float o1 = (v.y - mean) * rstd * wv.y + bv.y;
    float o2 = (v.z - mean) * rstd * wv.z + bv.z;
    float o3 = (v.w - mean) * rstd * wv.w + bv.w;

    long base = (long)row * Dm + i;
    *(__half2*)(Y + base)     = __halves2half2(__float2half_rn(o0), __float2half_rn(o1));
    *(__half2*)(Y + base + 2) = __halves2half2(__float2half_rn(o2), __float2half_rn(o3));
}

// ---------------------------------------------------------------------------
// HMMA GEMM (1-term: C = Ah·Bh). CTA 128x128, k-step 32, cp.async double
// buffer, 8 warps of 64x32. Epilogues: NONE / ADD / GELU->f16 / QKV->f16.
// ---------------------------------------------------------------------------
#define EPI_NONE 0
#define EPI_ADD  1
#define EPI_GELU 2
#define EPI_QKV  3

#define PK      40
#define TILE_H  (128*PK)
#define STG_H   (2*TILE_H)
#define GEMM_SMEM (2*STG_H*2)

template<int EPI>
__global__ __launch_bounds__(256, 2) void gemm_hmma(
    const __half* __restrict__ Ah,
    const __half* __restrict__ Bh,
    long bStride,
    const float* __restrict__ b0p, const float* __restrict__ b1p,
    const float* __restrict__ b2p, const float* __restrict__ res,
    float* __restrict__ C, __half* __restrict__ Ch,
    int M, int N, int K)
{
    extern __shared__ __align__(16) __half gsm[];
    const uint32_t sbase = smem_u32(gsm);

    const int tid = threadIdx.x, lane = tid & 31, warp = tid >> 5;
    const int g = lane >> 2, t = lane & 3, l7 = lane & 7;
    const int wm = warp & 1, wn = warp >> 1;
    const int m0 = blockIdx.y * 128, n0 = blockIdx.x * 128;

    float acc[4][4][4];
    #pragma unroll
    for (int a = 0; a < 4; a++)
        #pragma unroll
        for (int b = 0; b < 4; b++)
            #pragma unroll
            for (int c = 0; c < 4; c++) acc[a][b][c] = 0.f;

    const int S = K >> 5;

    auto issue = [&](int k0, int buf) {
        #pragma unroll
        for (int j = 0; j < 4; j++) {
            int c = tid + 256 * j;
            int tile = c >> 9;
            int r = (c >> 2) & 127;
            int q = c & 3;
            const __half* src;
            if (tile == 0) src = Ah + (long)(m0 + r) * K + k0 + q * 8;
            else {
                long roff;
                if (EPI == EPI_QKV) {
                    int rg = n0 + r;
                    roff = (long)(rg >> 10) * bStride + (long)(rg & 1023) * K;
                } else {
                    roff = (long)(n0 + r) * K;
                }
                src = Bh + roff + k0 + q * 8;
            }
            uint32_t dst = sbase + (uint32_t)(buf * STG_H + tile * TILE_H + r * PK + q * 8) * 2u;
            cpa16(dst, src);
        }
        asm volatile("cp.async.commit_group;" ::: "memory");
    };

    issue(0, 0);

    for (int s = 0; s < S; s++) {
        asm volatile("cp.async.wait_group 0;" ::: "memory");
        __syncthreads();
        if (s + 1 < S) issue((s + 1) << 5, (s + 1) & 1);

        uint32_t sb  = sbase + (uint32_t)((s & 1) * STG_H) * 2u;
        uint32_t A_h = sb;
        uint32_t B_h = sb + TILE_H * 2u;

        #pragma unroll
        for (int kk = 0; kk < 32; kk += 16) {
            uint32_t bh[4][2];
            #pragma unroll
            for (int p = 0; p < 2; p++) {
                int row = wn * 32 + p * 16 + l7 + ((lane & 16) >> 1);
                int kc  = kk + (lane & 8);
                uint32_t off = (uint32_t)(row * PK + kc) * 2u;
                ldm_x4(bh[2*p][0], bh[2*p][1], bh[2*p+1][0], bh[2*p+1][1], B_h + off);
            }
            #pragma unroll
            for (int mi = 0; mi < 4; mi++) {
                int row = wm * 64 + mi * 16 + l7 + (lane & 8);
                int kc  = kk + ((lane & 16) >> 1);
                uint32_t off = (uint32_t)(row * PK + kc) * 2u;
                uint32_t ah0, ah1, ah2, ah3;
                ldm_x4(ah0, ah1, ah2, ah3, A_h + off);
                #pragma unroll
                for (int ni = 0; ni < 4; ni++) {
                    float* d = acc[mi][ni];
                    mma_f16(d[0], d[1], d[2], d[3], ah0, ah1, ah2, ah3, bh[ni][0], bh[ni][1]);
                }
            }
        }
    }

    // --- epilogue ---
    const float* bias = b0p;
    float* Cd = C;
    __half* Chd = Ch;
    int csub = 0, Nw = N;
    if (EPI == EPI_QKV) {
        int sel = n0 >> 10;
        bias = (sel == 0) ? b0p : (sel == 1) ? b1p : b2p;
        Chd = Ch + (long)sel * BT * Dm;
        csub = sel << 10;
        Nw = Dm;
    }

    #pragma unroll
    for (int mi = 0; mi < 4; mi++) {
        int r0 = m0 + wm * 64 + mi * 16 + g;
        #pragma unroll
        for (int ni = 0; ni < 4; ni++) {
            int cc = n0 + wn * 32 + ni * 8 + 2 * t;
            float b0v = bias ? bias[cc - csub] : 0.f;
            float b1v = bias ? bias[cc - csub + 1] : 0.f;
            float v0 = acc[mi][ni][0] + b0v, v1 = acc[mi][ni][1] + b1v;
            float v2 = acc[mi][ni][2] + b0v, v3 = acc[mi][ni][3] + b1v;
            long i0 = (long)r0 * Nw + (cc - csub);
            long i1 = (long)(r0 + 8) * Nw + (cc - csub);
            if (EPI == EPI_ADD) {
                v0 += res[i0]; v1 += res[i0 + 1];
                v2 += res[i1]; v3 += res[i1 + 1];
            }
            if (EPI == EPI_GELU) {
                v0 = 0.5f * v0 * (1.f + erff(v0 * 0.70710678118654752f));
                v1 = 0.5f * v1 * (1.f + erff(v1 * 0.70710678118654752f));
                v2 = 0.5f * v2 * (1.f + erff(v2 * 0.70710678118654752f));
                v3 = 0.5f * v3 * (1.f + erff(v3 * 0.70710678118654752f));
            }
            if (EPI == EPI_GELU || EPI == EPI_QKV) {
                *(__half2*)(Chd + i0) = __halves2half2(__float2half_rn(v0), __float2half_rn(v1));
                *(__half2*)(Chd + i1) = __halves2half2(__float2half_rn(v2), __float2half_rn(v3));
            } else {
                *(float2*)(Cd + i0) = make_float2(v0, v1);
                *(float2*)(Cd + i1) = make_float2(v2, v3);
            }
        }
    }
}

// ---------------------------------------------------------------------------
// Flash attention (HMMA, causal), double-buffered K/V pipeline.
// ---------------------------------------------------------------------------
#define APD 72
#define ATT_SMEM ((128 + 4 * 64) * APD * 2)

__global__ __launch_bounds__(256, 2) void attn_hmma(
    const __half* __restrict__ Qg, const __half* __restrict__ Kg,
    const __half* __restrict__ Vg, __half* __restrict__ Y)
{
    extern __shared__ __align__(16) __half asmem[];
    const uint32_t sb = smem_u32(asmem);
    const uint32_t Qs  = sb;
    const uint32_t KVs = sb + 128 * APD * 2;

    const int qt = blockIdx.x, h = blockIdx.y, b = blockIdx.z;
    const int tid = threadIdx.x, lane = tid & 31, warp = tid >> 5;
    const int g = lane >> 2, c2 = (lane & 3) * 2;

    const long rowbase = (long)(b * Tq + qt * 128);
    const __half* qsrc = Qg + rowbase * Dm + h * HD;

    #pragma unroll
    for (int j = 0; j < 4; j++) {
        int c = tid + 256 * j;
        int r = c >> 3, col8 = (c & 7) * 8;
        cpa16(Qs + (uint32_t)(r * APD + col8) * 2u, qsrc + (long)r * Dm + col8);
    }
    asm volatile("cp.async.commit_group;" ::: "memory");

    auto issue_kv = [&](int kt, int buf) {
        const long krow = (long)(b * Tq + kt * 64);
        uint32_t Kb = KVs + (uint32_t)(buf * 128 * APD) * 2u;
        uint32_t Vb = Kb + (uint32_t)(64 * APD) * 2u;
        #pragma unroll
        for (int j = 0; j < 4; j++) {
            int c = tid + 256 * j;
            int tsel = c >> 9;
            int r = (c >> 3) & 63, col8 = (c & 7) * 8;
            const __half* src = (tsel ? Vg : Kg) + (krow + r) * (long)Dm + h * HD + col8;
            uint32_t dst = (tsel ? Vb : Kb) + (uint32_t)(r * APD + col8) * 2u;
            cpa16(dst, src);
        }
        asm volatile("cp.async.commit_group;" ::: "memory");
    };

    issue_kv(0, 0);

    asm volatile("cp.async.wait_group 1;" ::: "memory");
    __syncthreads();

    uint32_t qf[4][4];
    #pragma unroll
    for (int kf = 0; kf < 4; kf++) {
        uint32_t addr = Qs + (uint32_t)((warp * 16 + (lane & 15)) * APD
                                        + kf * 16 + ((lane >> 4) & 1) * 8) * 2u;
        ldm_x4(qf[kf][0], qf[kf][1], qf[kf][2], qf[kf][3], addr);
    }

    const int r0g = qt * 128 + warp * 16 + g;
    const int q_hi = qt * 128 + warp * 16 + 15;

    float O[8][4];
    #pragma unroll
    for (int nf = 0; nf < 8; nf++)
        #pragma unroll
        for (int j = 0; j < 4; j++) O[nf][j] = 0.f;
    float m0 = -1e30f, m1 = -1e30f, l0 = 0.f, l1 = 0.f;

    const int ktmax = qt * 2 + 1;
    for (int kt = 0; kt <= ktmax; kt++) {
        asm volatile("cp.async.wait_group 0;" ::: "memory");
        __syncthreads();
        if (kt + 1 <= ktmax) issue_kv(kt + 1, (kt + 1) & 1);

        uint32_t Kb = KVs + (uint32_t)((kt & 1) * 128 * APD) * 2u;
        uint32_t Vb = Kb + (uint32_t)(64 * APD) * 2u;

        if (kt * 64 <= q_hi) {
            float S[8][4];
            #pragma unroll
            for (int nf = 0; nf < 8; nf++)
                #pragma unroll
                for (int j = 0; j < 4; j++) S[nf][j] = 0.f;

            #pragma unroll
            for (int tg = 0; tg < 4; tg++) {
                #pragma unroll
                for (int kf = 0; kf < 4; kf++) {
                    uint32_t k0, k1, k2, k3;
                    uint32_t addr = Kb + (uint32_t)((tg * 16 + (lane & 15)) * APD
                                                    + kf * 16 + ((lane >> 4) & 1) * 8) * 2u;
                    ldm_x4(k0, k1, k2, k3, addr);
                    mma_f16(S[2*tg][0], S[2*tg][1], S[2*tg][2], S[2*tg][3],
                            qf[kf][0], qf[kf][1], qf[kf][2], qf[kf][3], k0, k2);
                    mma_f16(S[2*tg+1][0], S[2*tg+1][1], S[2*tg+1][2], S[2*tg+1][3],
                            qf[kf][0], qf[kf][1], qf[kf][2], qf[kf][3], k1, k3);
                }
            }

            const float scale = 0.125f;
            #pragma unroll
            for (int nf = 0; nf < 8; nf++)
                #pragma unroll
                for (int j = 0; j < 4; j++) S[nf][j] *= scale;

            if (kt * 64 + 63 > r0g) {
                #pragma unroll
                for (int nf = 0; nf < 8; nf++) {
                    int col = kt * 64 + nf * 8 + c2;
                    if (col     > r0g)     S[nf][0] = -1e30f;
                    if (col + 1 > r0g)     S[nf][1] = -1e30f;
                    if (col     > r0g + 8) S[nf][2] = -1e30f;
                    if (col + 1 > r0g + 8) S[nf][3] = -1e30f;
                }
            }

            float rmax0 = -1e30f, rmax1 = -1e30f;
            #pragma unroll
            for (int nf = 0; nf < 8; nf++) {
                rmax0 = fmaxf(rmax0, fmaxf(S[nf][0], S[nf][1]));
                rmax1 = fmaxf(rmax1, fmaxf(S[nf][2], S[nf][3]));
            }
            #pragma unroll
            for (int m = 1; m <= 2; m <<= 1) {
                rmax0 = fmaxf(rmax0, __shfl_xor_sync(0xffffffffu, rmax0, m));
                rmax1 = fmaxf(rmax1, __shfl_xor_sync(0xffffffffu, rmax1, m));
            }
            float mn0 = fmaxf(m0, rmax0), mn1 = fmaxf(m1, rmax1);
            float a0 = __expf(m0 - mn0), a1 = __expf(m1 - mn1);
            m0 = mn0; m1 = mn1;

            float rs0 = 0.f, rs1 = 0.f;
            uint32_t pa[4][4];
            #pragma unroll
            for (int nf = 0; nf < 8; nf++) {
                float p0 = __expf(S[nf][0] - mn0);
                float p1 = __expf(S[nf][1] - mn0);
                float p2 = __expf(S[nf][2] - mn1);
                float p3 = __expf(S[nf][3] - mn1);
                rs0 += p0 + p1; rs1 += p2 + p3;
                pa[nf >> 1][(nf & 1) * 2 + 0] = packh2(p0, p1);
                pa[nf >> 1][(nf & 1) * 2 + 1] = packh2(p2, p3);
            }
            #pragma unroll
            for (int m = 1; m <= 2; m <<= 1) {
                rs0 += __shfl_xor_sync(0xffffffffu, rs0, m);
                rs1 += __shfl_xor_sync(0xffffffffu, rs1, m);
            }
            l0 = l0 * a0 + rs0;
            l1 = l1 * a1 + rs1;
            #pragma unroll
            for (int nf = 0; nf < 8; nf++) {
                O[nf][0] *= a0; O[nf][1] *= a0;
                O[nf][2] *= a1; O[nf][3] *= a1;
            }

            #pragma unroll
            for (int kf = 0; kf < 4; kf++) {
                #pragma unroll
                for (int hg = 0; hg < 4; hg++) {
                    uint32_t v0, v1, v2, v3;
                    uint32_t addr = Vb + (uint32_t)((kf * 16 + (lane & 15)) * APD
                                                    + hg * 16 + ((lane >> 4) & 1) * 8) * 2u;
                    ldm_x4t(v0, v1, v2, v3, addr);
                    mma_f16(O[2*hg][0], O[2*hg][1], O[2*hg][2], O[2*hg][3],
                            pa[kf][0], pa[kf][1], pa[kf][2], pa[kf][3], v0, v1);
                    mma_f16(O[2*hg+1][0], O[2*hg+1][1], O[2*hg+1][2], O[2*hg+1][3],
                            pa[kf][0], pa[kf][1], pa[kf][2], pa[kf][3], v2, v3);
                }
            }
        }
    }

    float inv0 = 1.f / l0, inv1 = 1.f / l1;
    long ybase0 = (rowbase + warp * 16 + g) * (long)Dm + h * HD;
    long ybase1 = ybase0 + 8L * Dm;
    #pragma unroll
    for (int nf = 0; nf < 8; nf++) {
        int col = nf * 8 + c2;
        *(__half2*)(Y + ybase0 + col) =
            __halves2half2(__float2half_rn(O[nf][0] * inv0), __float2half_rn(O[nf][1] * inv0));
        *(__half2*)(Y + ybase1 + col) =
            __halves2half2(__float2half_rn(O[nf][2] * inv1), __float2half_rn(O[nf][3] * inv1));
    }
}

// ---------------------------------------------------------------------------
// Launcher
// ---------------------------------------------------------------------------
extern "C" void kernel_launch(void* const* d_in, const int* in_sizes, int n_in,
                              void* d_out, int out_size)
{
    const int*   idx  = (const int*)  d_in[0];
    const int*   ts   = (const int*)  d_in[1];
    const float* tok  = (const float*)d_in[2];
    const float* pos  = (const float*)d_in[3];
    const float* gpos = (const float*)d_in[4];
    const float* ln1w = (const float*)d_in[5];
    const float* ln1b = (const float*)d_in[6];
    const float* Wq   = (const float*)d_in[7];
    const float* bq   = (const float*)d_in[8];
    const float* Wk   = (const float*)d_in[9];
    const float* bk   = (const float*)d_in[10];
    const float* Wv   = (const float*)d_in[11];
    const float* bv   = (const float*)d_in[12];
    const float* Wo   = (const float*)d_in[13];
    const float* bo   = (const float*)d_in[14];
    const float* ln2w = (const float*)d_in[15];
    const float* ln2b = (const float*)d_in[16];
    const float* W1   = (const float*)d_in[17];
    const float* b1   = (const float*)d_in[18];
    const float* W2   = (const float*)d_in[19];
    const float* b2   = (const float*)d_in[20];
    const float* lnfw = (const float*)d_in[21];
    const float* lnfb = (const float*)d_in[22];
    const float* hw   = (const float*)d_in[23];
    float* out = (float*)d_out;

    float* x;
    __half *qkvh, *pa, *pb, *wh;
    cudaGetSymbolAddress((void**)&x,    g_x);
    cudaGetSymbolAddress((void**)&qkvh, g_qkvh);
    cudaGetSymbolAddress((void**)&pa,   g_pa);
    cudaGetSymbolAddress((void**)&pb,   g_pb);
    cudaGetSymbolAddress((void**)&wh,   g_wh);

    cudaFuncSetAttribute(attn_hmma, cudaFuncAttributeMaxDynamicSharedMemorySize, ATT_SMEM);
    cudaFuncSetAttribute(gemm_hmma<EPI_QKV>,  cudaFuncAttributeMaxDynamicSharedMemorySize, GEMM_SMEM);
    cudaFuncSetAttribute(gemm_hmma<EPI_GELU>, cudaFuncAttributeMaxDynamicSharedMemorySize, GEMM_SMEM);
    cudaFuncSetAttribute(gemm_hmma<EPI_ADD>,  cudaFuncAttributeMaxDynamicSharedMemorySize, GEMM_SMEM);
    cudaFuncSetAttribute(gemm_hmma<EPI_NONE>, cudaFuncAttributeMaxDynamicSharedMemorySize, GEMM_SMEM);

    auto cvt1 = [&](const float* src, long off, long n) {
        cvt_hi<<<(int)((n / 4 + 255) / 256), 256>>>(src, wh + off, n);
    };

    const dim3 gD(Dm / 128, BT / 128);
    const dim3 gQKV(3 * Dm / 128, BT / 128);
    const dim3 g2D(2 * Dm / 128, BT / 128);
    const dim3 gV(Vv / 128, BT / 128);

    __half* qb = qkvh;
    __half* kb = qkvh + (long)BT * Dm;
    __half* vb = qkvh + 2L * BT * Dm;

    cvt1(Wq, OFF_WQ, 8L * DD);
    cvt1(Wk, OFF_WK, 8L * DD);
    cvt1(Wv, OFF_WV, 8L * DD);
    embed_ln<<<BT, 256>>>(idx, ts, tok, pos, gpos, ln1w, ln1b, x, pa);

    bool cvted = false;

    for (int l = 0; l < Ll; l++) {
        if (l > 0)
            layernorm_f16<<<BT, 256>>>(x, ln1w + (long)l * Dm, ln1b + (long)l * Dm, pa);

        gemm_hmma<EPI_QKV><<<gQKV, 256, GEMM_SMEM>>>(
            pa, wh + OFF_WQ + (long)l * DD,
            8L * DD,
            bq + (long)l * Dm, bk + (long)l * Dm, bv + (long)l * Dm,
            nullptr, nullptr, qkvh, BT, 3 * Dm, Dm);

        attn_hmma<<<dim3(Tq / 128, Hh, Bq), 256, ATT_SMEM>>>(qb, kb, vb, pa);

        if (!cvted) cvt1(Wo, OFF_WO, 8L * DD);

        gemm_hmma<EPI_ADD><<<gD, 256, GEMM_SMEM>>>(
            pa, wh + OFF_WO + (long)l * DD, 0,
            bo + (long)l * Dm, nullptr, nullptr, x, x, nullptr, BT, Dm, Dm);

        layernorm_f16<<<BT, 256>>>(x, ln2w + (long)l * Dm, ln2b + (long)l * Dm, pa);

        if (!cvted) cvt1(W1, OFF_W1, 16L * DD);

        gemm_hmma<EPI_GELU><<<g2D, 256, GEMM_SMEM>>>(
            pa, wh + OFF_W1 + (long)l * 2 * DD, 0,
            b1 + (long)l * 2 * Dm, nullptr, nullptr, nullptr,
            nullptr, pb, BT, 2 * Dm, Dm);

        if (!cvted) { cvt1(W2, OFF_W2, 16L * DD); cvted = true; }

        gemm_hmma<EPI_ADD><<<gD, 256, GEMM_SMEM>>>(
            pb, wh + OFF_W2 + (long)l * 2 * DD, 0,
            b2 + (long)l * Dm, nullptr, nullptr, x, x, nullptr, BT, Dm, 2 * Dm);
    }

    layernorm_f16<<<BT, 256>>>(x, lnfw, lnfb, pa);
    cvt1(hw, OFF_HW, 8L * DD);
    gemm_hmma<EPI_NONE><<<gV, 256, GEMM_SMEM>>>(
        pa, wh + OFF_HW, 0,
        nullptr, nullptr, nullptr, nullptr, out, nullptr, BT, Vv, Dm);
}

// round 17
// speedup vs baseline: 6.1990x; 1.0769x over previous
#include <cuda_runtime.h>
#include <cuda_fp16.h>
#include <math.h>
#include <stdint.h>

// ---------------------------------------------------------------------------
// Problem constants
// ---------------------------------------------------------------------------
#define Bq   8
#define Tq   1024
#define Dm   1024
#define Hh   16
#define Ll   8
#define Vv   8192
#define HD   64
#define BT   (Bq*Tq)

// ---------------------------------------------------------------------------
// Scratch (static device globals)
// ---------------------------------------------------------------------------
__device__ float  g_x[BT * Dm];          // residual stream (f32)
__device__ __half g_qkvh[3L * BT * Dm];  // q | k | v  (f16)

__device__ __half g_pa[BT * Dm];         // act buf A: LN out / attn out
__device__ __half g_pb[BT * 2 * Dm];     // act buf B: MLP hidden

#define DD      (Dm*Dm)
#define OFF_WQ  0L
#define OFF_WK  (8L*DD)
#define OFF_WV  (16L*DD)
#define OFF_WO  (24L*DD)
#define OFF_W1  (32L*DD)
#define OFF_W2  (48L*DD)
#define OFF_HW  (64L*DD)
#define WTOT    (72L*DD)
__device__ __half g_wh[WTOT];            // all weights, f16 (1-term)

// ---------------------------------------------------------------------------
// Helpers
// ---------------------------------------------------------------------------
__device__ __forceinline__ uint32_t smem_u32(const void* p) {
    uint32_t a;
    asm("{ .reg .u64 t; cvta.to.shared.u64 t, %1; cvt.u32.u64 %0, t; }"
        : "=r"(a) : "l"(p));
    return a;
}
__device__ __forceinline__ void cpa16(uint32_t dst, const void* src) {
    asm volatile("cp.async.cg.shared.global [%0], [%1], 16;" :: "r"(dst), "l"(src));
}
__device__ __forceinline__ void ldm_x4(uint32_t& r0, uint32_t& r1,
                                       uint32_t& r2, uint32_t& r3, uint32_t addr) {
    asm volatile("ldmatrix.sync.aligned.m8n8.x4.shared.b16 {%0,%1,%2,%3}, [%4];"
                 : "=r"(r0), "=r"(r1), "=r"(r2), "=r"(r3) : "r"(addr));
}
__device__ __forceinline__ void ldm_x4t(uint32_t& r0, uint32_t& r1,
                                        uint32_t& r2, uint32_t& r3, uint32_t addr) {
    asm volatile("ldmatrix.sync.aligned.m8n8.x4.trans.shared.b16 {%0,%1,%2,%3}, [%4];"
                 : "=r"(r0), "=r"(r1), "=r"(r2), "=r"(r3) : "r"(addr));
}
__device__ __forceinline__ void mma_f16(float& d0, float& d1, float& d2, float& d3,
                                        uint32_t a0, uint32_t a1, uint32_t a2, uint32_t a3,
                                        uint32_t b0, uint32_t b1) {
    asm volatile(
        "mma.sync.aligned.m16n8k16.row.col.f32.f16.f16.f32 "
        "{%0,%1,%2,%3}, {%4,%5,%6,%7}, {%8,%9}, {%0,%1,%2,%3};"
        : "+f"(d0), "+f"(d1), "+f"(d2), "+f"(d3)
        : "r"(a0), "r"(a1), "r"(a2), "r"(a3), "r"(b0), "r"(b1));
}
__device__ __forceinline__ uint32_t packh2(float a, float b) {
    __half2 h = __halves2half2(__float2half_rn(a), __float2half_rn(b));
    return *(uint32_t*)&h;
}

// ---------------------------------------------------------------------------
// Weight conversion (f16)
// ---------------------------------------------------------------------------
__global__ __launch_bounds__(256) void cvt_hi(
    const float* __restrict__ s, __half* __restrict__ h, long n)
{
    long i = ((long)blockIdx.x * 256 + threadIdx.x) * 4;
    if (i >= n) return;
    float4 v = *(const float4*)(s + i);
    *(__half2*)(h + i)     = __halves2half2(__float2half_rn(v.x), __float2half_rn(v.y));
    *(__half2*)(h + i + 2) = __halves2half2(__float2half_rn(v.z), __float2half_rn(v.w));
}

// ---------------------------------------------------------------------------
// Fused embedding + LayerNorm(layer0 ln1) -> x and f16 output
// ---------------------------------------------------------------------------
__global__ __launch_bounds__(256) void embed_ln(
    const int* __restrict__ idx, const int* __restrict__ ts,
    const float* __restrict__ tok, const float* __restrict__ pos,
    const float* __restrict__ gpos,
    const float* __restrict__ w, const float* __restrict__ b,
    float* __restrict__ X, __half* __restrict__ Y)
{
    int row = blockIdx.x;
    int t = row & (Tq - 1);
    int bb = row >> 10;
    int tid = threadIdx.x;
    int i = tid * 4;

    float4 tv = *(const float4*)(tok + (long)idx[row] * Dm + i);
    float4 gv = *(const float4*)(gpos + (long)ts[bb] * Dm + i);
    float4 pv = *(const float4*)(pos + (long)t * Dm + i);
    float4 v;
    v.x = tv.x + gv.x + pv.x;
    v.y = tv.y + gv.y + pv.y;
    v.z = tv.z + gv.z + pv.z;
    v.w = tv.w + gv.w + pv.w;

    long base = (long)row * Dm + i;
    *(float4*)(X + base) = v;

    float s  = v.x + v.y + v.z + v.w;
    float ss = v.x*v.x + v.y*v.y + v.z*v.z + v.w*v.w;

    __shared__ float rs[8], rss[8];
    #pragma unroll
    for (int m = 16; m; m >>= 1) {
        s  += __shfl_xor_sync(0xffffffffu, s,  m);
        ss += __shfl_xor_sync(0xffffffffu, ss, m);
    }
    int wid = tid >> 5, lane = tid & 31;
    if (lane == 0) { rs[wid] = s; rss[wid] = ss; }
    __syncthreads();
    if (wid == 0) {
        s  = (lane < 8) ? rs[lane]  : 0.f;
        ss = (lane < 8) ? rss[lane] : 0.f;
        #pragma unroll
        for (int m = 4; m; m >>= 1) {
            s  += __shfl_xor_sync(0xffffffffu, s,  m);
            ss += __shfl_xor_sync(0xffffffffu, ss, m);
        }
        if (lane == 0) { rs[0] = s; rss[0] = ss; }
    }
    __syncthreads();
    float mean = rs[0] * (1.0f / Dm);
    float var  = rss[0] * (1.0f / Dm) - mean * mean;
    float rstd = rsqrtf(var + 1e-5f);

    float4 wv = *(const float4*)(w + i);
    float4 bv = *(const float4*)(b + i);
    float o0 = (v.x - mean) * rstd * wv.x + bv.x;
    float o1 = (v.y - mean) * rstd * wv.y + bv.y;
    float o2 = (v.z - mean) * rstd * wv.z + bv.z;
    float o3 = (v.w - mean) * rstd * wv.w + bv.w;

    *(__half2*)(Y + base)     = __halves2half2(__float2half_rn(o0), __float2half_rn(o1));
    *(__half2*)(Y + base + 2) = __halves2half2(__float2half_rn(o2), __float2half_rn(o3));
}

// ---------------------------------------------------------------------------
// LayerNorm -> f16. 2 rows per 256-thread block (128 thr/row, 8 elems/thr),
// single barrier (warp partials + broadcast read).
// ---------------------------------------------------------------------------
__global__ __launch_bounds__(256) void layernorm_f16(
    const float* __restrict__ X, const float* __restrict__ w,
    const float* __restrict__ b, __half* __restrict__ Y)
{
    const int half_id = threadIdx.x >> 7;          // 0 or 1: which row
    const int tid = threadIdx.x & 127;
    const long row = (long)blockIdx.x * 2 + half_id;
    const float* x = X + row * Dm;
    const int i = tid * 8;

    float4 v0 = *(const float4*)(x + i);
    float4 v1 = *(const float4*)(x + i + 4);
    float s  = v0.x + v0.y + v0.z + v0.w + v1.x + v1.y + v1.z + v1.w;
    float ss = v0.x*v0.x + v0.y*v0.y + v0.z*v0.z + v0.w*v0.w
             + v1.x*v1.x + v1.y*v1.y + v1.z*v1.z + v1.w*v1.w;

    __shared__ float rs[8], rss[8];
    #pragma unroll
    for (int m = 16; m; m >>= 1) {
        s  += __shfl_xor_sync(0xffffffffu, s,  m);
        ss += __shfl_xor_sync(0xffffffffu, ss, m);
    }
    int wid = threadIdx.x >> 5;
    if ((threadIdx.x & 31) == 0) { rs[wid] = s; rss[wid] = ss; }
    __syncthreads();
    int base4 = half_id * 4;
    float S  = rs[base4]  + rs[base4+1]  + rs[base4+2]  + rs[base4+3];
    float SS = rss[base4] + rss[base4+1] + rss[base4+2] + rss[base4+3];

    float mean = S * (1.0f / Dm);
    float var  = SS * (1.0f / Dm) - mean * mean;
    float rstd = rsqrtf(var + 1e-5f);

    float4 wv0 = *(const float4*)(w + i);
    float4 wv1 = *(const float4*)(w + i + 4);
    float4 bv0 = *(const float4*)(b + i);
    float4 bv1 = *(const float4*)(b + i + 4);

    long obase = row * Dm + i;
    *(__half2*)(Y + obase) = __halves2half2(
        __float2half_rn((v0.x - mean) * rstd * wv0.x + bv0.x),
        __float2half_rn((v0.y - mean) * rstd * wv0.y + bv0.y));
    *(__half2*)(Y + obase + 2) = __halves2half2(
        __float2half_rn((v0.z - mean) * rstd * wv0.z + bv0.z),
        __float2half_rn((v0.w - mean) * rstd * wv0.w + bv0.w));
    *(__half2*)(Y + obase + 4) = __halves2half2(
        __float2half_rn((v1.x - mean) * rstd * wv1.x + bv1.x),
        __float2half_rn((v1.y - mean) * rstd * wv1.y + bv1.y));
    *(__half2*)(Y + obase + 6) = __halves2half2(
        __float2half_rn((v1.z - mean) * rstd * wv1.z + bv1.z),
        __float2half_rn((v1.w - mean) * rstd * wv1.w + bv1.w));
}

// ---------------------------------------------------------------------------
// HMMA GEMM (1-term: C = Ah·Bh). CTA 128x128, k-step 64, cp.async double
// buffer, 8 warps of 64x32. Epilogues: NONE / ADD / GELU->f16 / QKV->f16.
// smem: 2 stages x 2 tiles x (128 rows x 72 halfs) = 73728 B.
// ---------------------------------------------------------------------------
#define EPI_NONE 0
#define EPI_ADD  1
#define EPI_GELU 2
#define EPI_QKV  3

#define PK      72
#define TILE_H  (128*PK)
#define STG_H   (2*TILE_H)
#define GEMM_SMEM (2*STG_H*2)

template<int EPI>
__global__ __launch_bounds__(256, 2) void gemm_hmma(
    const __half* __restrict__ Ah,
    const __half* __restrict__ Bh,
    long bStride,
    const float* __restrict__ b0p, const float* __restrict__ b1p,
    const float* __restrict__ b2p, const float* __restrict__ res,
    float* __restrict__ C, __half* __restrict__ Ch,
    int M, int N, int K)
{
    extern __shared__ __align__(16) __half gsm[];
    const uint32_t sbase = smem_u32(gsm);

    const int tid = threadIdx.x, lane = tid & 31, warp = tid >> 5;
    const int g = lane >> 2, t = lane & 3, l7 = lane & 7;
    const int wm = warp & 1, wn = warp >> 1;
    const int m0 = blockIdx.y * 128, n0 = blockIdx.x * 128;

    float acc[4][4][4];
    #pragma unroll
    for (int a = 0; a < 4; a++)
        #pragma unroll
        for (int b = 0; b < 4; b++)
            #pragma unroll
            for (int c = 0; c < 4; c++) acc[a][b][c] = 0.f;

    const int S = K >> 6;

    // 2048 16B-chunks per stage: A[0,1024) B[1024,2048); 8 chunks (=64 halfs) per row
    auto issue = [&](int k0, int buf) {
        #pragma unroll
        for (int j = 0; j < 8; j++) {
            int c = tid + 256 * j;
            int tile = c >> 10;
            int r = (c >> 3) & 127;
            int q = c & 7;
            const __half* src;
            if (tile == 0) src = Ah + (long)(m0 + r) * K + k0 + q * 8;
            else {
                long roff;
                if (EPI == EPI_QKV) {
                    int rg = n0 + r;
                    roff = (long)(rg >> 10) * bStride + (long)(rg & 1023) * K;
                } else {
                    roff = (long)(n0 + r) * K;
                }
                src = Bh + roff + k0 + q * 8;
            }
            uint32_t dst = sbase + (uint32_t)(buf * STG_H + tile * TILE_H + r * PK + q * 8) * 2u;
            cpa16(dst, src);
        }
        asm volatile("cp.async.commit_group;" ::: "memory");
    };

    issue(0, 0);

    for (int s = 0; s < S; s++) {
        asm volatile("cp.async.wait_group 0;" ::: "memory");
        __syncthreads();
        if (s + 1 < S) issue((s + 1) << 6, (s + 1) & 1);

        uint32_t sb  = sbase + (uint32_t)((s & 1) * STG_H) * 2u;
        uint32_t A_h = sb;
        uint32_t B_h = sb + TILE_H * 2u;

        #pragma unroll
        for (int kk = 0; kk < 64; kk += 16) {
            uint32_t bh[4][2];
            #pragma unroll
            for (int p = 0; p < 2; p++) {
                int row = wn * 32 + p * 16 + l7 + ((lane & 16) >> 1);
                int kc  = kk + (lane & 8);
                uint32_t off = (uint32_t)(row * PK + kc) * 2u;
                ldm_x4(bh[2*p][0], bh[2*p][1], bh[2*p+1][0], bh[2*p+1][1], B_h + off);
            }
            #pragma unroll
            for (int mi = 0; mi < 4; mi++) {
                int row = wm * 64 + mi * 16 + l7 + (lane & 8);
                int kc  = kk + ((lane & 16) >> 1);
                uint32_t off = (uint32_t)(row * PK + kc) * 2u;
                uint32_t ah0, ah1, ah2, ah3;
                ldm_x4(ah0, ah1, ah2, ah3, A_h + off);
                #pragma unroll
                for (int ni = 0; ni < 4; ni++) {
                    float* d = acc[mi][ni];
                    mma_f16(d[0], d[1], d[2], d[3], ah0, ah1, ah2, ah3, bh[ni][0], bh[ni][1]);
                }
            }
        }
    }

    // --- epilogue ---
    const float* bias = b0p;
    float* Cd = C;
    __half* Chd = Ch;
    int csub = 0, Nw = N;
    if (EPI == EPI_QKV) {
        int sel = n0 >> 10;
        bias = (sel == 0) ? b0p : (sel == 1) ? b1p : b2p;
        Chd = Ch + (long)sel * BT * Dm;
        csub = sel << 10;
        Nw = Dm;
    }

    #pragma unroll
    for (int mi = 0; mi < 4; mi++) {
        int r0 = m0 + wm * 64 + mi * 16 + g;
        #pragma unroll
        for (int ni = 0; ni < 4; ni++) {
            int cc = n0 + wn * 32 + ni * 8 + 2 * t;
            float b0v = bias ? bias[cc - csub] : 0.f;
            float b1v = bias ? bias[cc - csub + 1] : 0.f;
            float v0 = acc[mi][ni][0] + b0v, v1 = acc[mi][ni][1] + b1v;
            float v2 = acc[mi][ni][2] + b0v, v3 = acc[mi][ni][3] + b1v;
            long i0 = (long)r0 * Nw + (cc - csub);
            long i1 = (long)(r0 + 8) * Nw + (cc - csub);
            if (EPI == EPI_ADD) {
                v0 += res[i0]; v1 += res[i0 + 1];
                v2 += res[i1]; v3 += res[i1 + 1];
            }
            if (EPI == EPI_GELU) {
                v0 = 0.5f * v0 * (1.f + erff(v0 * 0.70710678118654752f));
                v1 = 0.5f * v1 * (1.f + erff(v1 * 0.70710678118654752f));
                v2 = 0.5f * v2 * (1.f + erff(v2 * 0.70710678118654752f));
                v3 = 0.5f * v3 * (1.f + erff(v3 * 0.70710678118654752f));
            }
            if (EPI == EPI_GELU || EPI == EPI_QKV) {
                *(__half2*)(Chd + i0) = __halves2half2(__float2half_rn(v0), __float2half_rn(v1));
                *(__half2*)(Chd + i1) = __halves2half2(__float2half_rn(v2), __float2half_rn(v3));
            } else {
                *(float2*)(Cd + i0) = make_float2(v0, v1);
                *(float2*)(Cd + i1) = make_float2(v2, v3);
            }
        }
    }
}

// ---------------------------------------------------------------------------
// Flash attention (HMMA, causal), double-buffered K/V pipeline.
// ---------------------------------------------------------------------------
#define APD 72
#define ATT_SMEM ((128 + 4 * 64) * APD * 2)

__global__ __launch_bounds__(256, 2) void attn_hmma(
    const __half* __restrict__ Qg, const __half* __restrict__ Kg,
    const __half* __restrict__ Vg, __half* __restrict__ Y)
{
    extern __shared__ __align__(16) __half asmem[];
    const uint32_t sb = smem_u32(asmem);
    const uint32_t Qs  = sb;
    const uint32_t KVs = sb + 128 * APD * 2;

    const int qt = blockIdx.x, h = blockIdx.y, b = blockIdx.z;
    const int tid = threadIdx.x, lane = tid & 31, warp = tid >> 5;
    const int g = lane >> 2, c2 = (lane & 3) * 2;

    const long rowbase = (long)(b * Tq + qt * 128);
    const __half* qsrc = Qg + rowbase * Dm + h * HD;

    #pragma unroll
    for (int j = 0; j < 4; j++) {
        int c = tid + 256 * j;
        int r = c >> 3, col8 = (c & 7) * 8;
        cpa16(Qs + (uint32_t)(r * APD + col8) * 2u, qsrc + (long)r * Dm + col8);
    }
    asm volatile("cp.async.commit_group;" ::: "memory");

    auto issue_kv = [&](int kt, int buf) {
        const long krow = (long)(b * Tq + kt * 64);
        uint32_t Kb = KVs + (uint32_t)(buf * 128 * APD) * 2u;
        uint32_t Vb = Kb + (uint32_t)(64 * APD) * 2u;
        #pragma unroll
        for (int j = 0; j < 4; j++) {
            int c = tid + 256 * j;
            int tsel = c >> 9;
            int r = (c >> 3) & 63, col8 = (c & 7) * 8;
            const __half* src = (tsel ? Vg : Kg) + (krow + r) * (long)Dm + h * HD + col8;
            uint32_t dst = (tsel ? Vb : Kb) + (uint32_t)(r * APD + col8) * 2u;
            cpa16(dst, src);
        }
        asm volatile("cp.async.commit_group;" ::: "memory");
    };

    issue_kv(0, 0);

    asm volatile("cp.async.wait_group 1;" ::: "memory");
    __syncthreads();

    uint32_t qf[4][4];
    #pragma unroll
    for (int kf = 0; kf < 4; kf++) {
        uint32_t addr = Qs + (uint32_t)((warp * 16 + (lane & 15)) * APD
                                        + kf * 16 + ((lane >> 4) & 1) * 8) * 2u;
        ldm_x4(qf[kf][0], qf[kf][1], qf[kf][2], qf[kf][3], addr);
    }

    const int r0g = qt * 128 + warp * 16 + g;
    const int q_hi = qt * 128 + warp * 16 + 15;

    float O[8][4];
    #pragma unroll
    for (int nf = 0; nf < 8; nf++)
        #pragma unroll
        for (int j = 0; j < 4; j++) O[nf][j] = 0.f;
    float m0 = -1e30f, m1 = -1e30f, l0 = 0.f, l1 = 0.f;

    const int ktmax = qt * 2 + 1;
    for (int kt = 0; kt <= ktmax; kt++) {
        asm volatile("cp.async.wait_group 0;" ::: "memory");
        __syncthreads();
        if (kt + 1 <= ktmax) issue_kv(kt + 1, (kt + 1) & 1);

        uint32_t Kb = KVs + (uint32_t)((kt & 1) * 128 * APD) * 2u;
        uint32_t Vb = Kb + (uint32_t)(64 * APD) * 2u;

        if (kt * 64 <= q_hi) {
            float S[8][4];
            #pragma unroll
            for (int nf = 0; nf < 8; nf++)
                #pragma unroll
                for (int j = 0; j < 4; j++) S[nf][j] = 0.f;

            #pragma unroll
            for (int tg = 0; tg < 4; tg++) {
                #pragma unroll
                for (int kf = 0; kf < 4; kf++) {
                    uint32_t k0, k1, k2, k3;
                    uint32_t addr = Kb + (uint32_t)((tg * 16 + (lane & 15)) * APD
                                                    + kf * 16 + ((lane >> 4) & 1) * 8) * 2u;
                    ldm_x4(k0, k1, k2, k3, addr);
                    mma_f16(S[2*tg][0], S[2*tg][1], S[2*tg][2], S[2*tg][3],
                            qf[kf][0], qf[kf][1], qf[kf][2], qf[kf][3], k0, k2);
                    mma_f16(S[2*tg+1][0], S[2*tg+1][1], S[2*tg+1][2], S[2*tg+1][3],
                            qf[kf][0], qf[kf][1], qf[kf][2], qf[kf][3], k1, k3);
                }
            }

            const float scale = 0.125f;
            #pragma unroll
            for (int nf = 0; nf < 8; nf++)
                #pragma unroll
                for (int j = 0; j < 4; j++) S[nf][j] *= scale;

            if (kt * 64 + 63 > r0g) {
                #pragma unroll
                for (int nf = 0; nf < 8; nf++) {
                    int col = kt * 64 + nf * 8 + c2;
                    if (col     > r0g)     S[nf][0] = -1e30f;
                    if (col + 1 > r0g)     S[nf][1] = -1e30f;
                    if (col     > r0g + 8) S[nf][2] = -1e30f;
                    if (col + 1 > r0g + 8) S[nf][3] = -1e30f;
                }
            }

            float rmax0 = -1e30f, rmax1 = -1e30f;
            #pragma unroll
            for (int nf = 0; nf < 8; nf++) {
                rmax0 = fmaxf(rmax0, fmaxf(S[nf][0], S[nf][1]));
                rmax1 = fmaxf(rmax1, fmaxf(S[nf][2], S[nf][3]));
            }
            #pragma unroll
            for (int m = 1; m <= 2; m <<= 1) {
                rmax0 = fmaxf(rmax0, __shfl_xor_sync(0xffffffffu, rmax0, m));
                rmax1 = fmaxf(rmax1, __shfl_xor_sync(0xffffffffu, rmax1, m));
            }
            float mn0 = fmaxf(m0, rmax0), mn1 = fmaxf(m1, rmax1);
            float a0 = __expf(m0 - mn0), a1 = __expf(m1 - mn1);
            m0 = mn0; m1 = mn1;

            float rs0 = 0.f, rs1 = 0.f;
            uint32_t pa[4][4];
            #pragma unroll
            for (int nf = 0; nf < 8; nf++) {
                float p0 = __expf(S[nf][0] - mn0);
                float p1 = __expf(S[nf][1] - mn0);
                float p2 = __expf(S[nf][2] - mn1);
                float p3 = __expf(S[nf][3] - mn1);
                rs0 += p0 + p1; rs1 += p2 + p3;
                pa[nf >> 1][(nf & 1) * 2 + 0] = packh2(p0, p1);
                pa[nf >> 1][(nf & 1) * 2 + 1] = packh2(p2, p3);
            }
            #pragma unroll
            for (int m = 1; m <= 2; m <<= 1) {
                rs0 += __shfl_xor_sync(0xffffffffu, rs0, m);
                rs1 += __shfl_xor_sync(0xffffffffu, rs1, m);
            }
            l0 = l0 * a0 + rs0;
            l1 = l1 * a1 + rs1;
            #pragma unroll
            for (int nf = 0; nf < 8; nf++) {
                O[nf][0] *= a0; O[nf][1] *= a0;
                O[nf][2] *= a1; O[nf][3] *= a1;
            }

            #pragma unroll
            for (int kf = 0; kf < 4; kf++) {
                #pragma unroll
                for (int hg = 0; hg < 4; hg++) {
                    uint32_t v0, v1, v2, v3;
                    uint32_t addr = Vb + (uint32_t)((kf * 16 + (lane & 15)) * APD
                                                    + hg * 16 + ((lane >> 4) & 1) * 8) * 2u;
                    ldm_x4t(v0, v1, v2, v3, addr);
                    mma_f16(O[2*hg][0], O[2*hg][1], O[2*hg][2], O[2*hg][3],
                            pa[kf][0], pa[kf][1], pa[kf][2], pa[kf][3], v0, v1);
                    mma_f16(O[2*hg+1][0], O[2*hg+1][1], O[2*hg+1][2], O[2*hg+1][3],
                            pa[kf][0], pa[kf][1], pa[kf][2], pa[kf][3], v2, v3);
                }
            }
        }
    }

    float inv0 = 1.f / l0, inv1 = 1.f / l1;
    long ybase0 = (rowbase + warp * 16 + g) * (long)Dm + h * HD;
    long ybase1 = ybase0 + 8L * Dm;
    #pragma unroll
    for (int nf = 0; nf < 8; nf++) {
        int col = nf * 8 + c2;
        *(__half2*)(Y + ybase0 + col) =
            __halves2half2(__float2half_rn(O[nf][0] * inv0), __float2half_rn(O[nf][1] * inv0));
        *(__half2*)(Y + ybase1 + col) =
            __halves2half2(__float2half_rn(O[nf][2] * inv1), __float2half_rn(O[nf][3] * inv1));
    }
}

// ---------------------------------------------------------------------------
// Launcher
// ---------------------------------------------------------------------------
extern "C" void kernel_launch(void* const* d_in, const int* in_sizes, int n_in,
                              void* d_out, int out_size)
{
    const int*   idx  = (const int*)  d_in[0];
    const int*   ts   = (const int*)  d_in[1];
    const float* tok  = (const float*)d_in[2];
    const float* pos  = (const float*)d_in[3];
    const float* gpos = (const float*)d_in[4];
    const float* ln1w = (const float*)d_in[5];
    const float* ln1b = (const float*)d_in[6];
    const float* Wq   = (const float*)d_in[7];
    const float* bq   = (const float*)d_in[8];
    const float* Wk   = (const float*)d_in[9];
    const float* bk   = (const float*)d_in[10];
    const float* Wv   = (const float*)d_in[11];
    const float* bv   = (const float*)d_in[12];
    const float* Wo   = (const float*)d_in[13];
    const float* bo   = (const float*)d_in[14];
    const float* ln2w = (const float*)d_in[15];
    const float* ln2b = (const float*)d_in[16];
    const float* W1   = (const float*)d_in[17];
    const float* b1   = (const float*)d_in[18];
    const float* W2   = (const float*)d_in[19];
    const float* b2   = (const float*)d_in[20];
    const float* lnfw = (const float*)d_in[21];
    const float* lnfb = (const float*)d_in[22];
    const float* hw   = (const float*)d_in[23];
    float* out = (float*)d_out;

    float* x;
    __half *qkvh, *pa, *pb, *wh;
    cudaGetSymbolAddress((void**)&x,    g_x);
    cudaGetSymbolAddress((void**)&qkvh, g_qkvh);
    cudaGetSymbolAddress((void**)&pa,   g_pa);
    cudaGetSymbolAddress((void**)&pb,   g_pb);
    cudaGetSymbolAddress((void**)&wh,   g_wh);

    cudaFuncSetAttribute(attn_hmma, cudaFuncAttributeMaxDynamicSharedMemorySize, ATT_SMEM);
    cudaFuncSetAttribute(gemm_hmma<EPI_QKV>,  cudaFuncAttributeMaxDynamicSharedMemorySize, GEMM_SMEM);
    cudaFuncSetAttribute(gemm_hmma<EPI_GELU>, cudaFuncAttributeMaxDynamicSharedMemorySize, GEMM_SMEM);
    cudaFuncSetAttribute(gemm_hmma<EPI_ADD>,  cudaFuncAttributeMaxDynamicSharedMemorySize, GEMM_SMEM);
    cudaFuncSetAttribute(gemm_hmma<EPI_NONE>, cudaFuncAttributeMaxDynamicSharedMemorySize, GEMM_SMEM);

    auto cvt1 = [&](const float* src, long off, long n) {
        cvt_hi<<<(int)((n / 4 + 255) / 256), 256>>>(src, wh + off, n);
    };

    const dim3 gD(Dm / 128, BT / 128);
    const dim3 gQKV(3 * Dm / 128, BT / 128);
    const dim3 g2D(2 * Dm / 128, BT / 128);
    const dim3 gV(Vv / 128, BT / 128);

    __half* qb = qkvh;
    __half* kb = qkvh + (long)BT * Dm;
    __half* vb = qkvh + 2L * BT * Dm;

    cvt1(Wq, OFF_WQ, 8L * DD);
    cvt1(Wk, OFF_WK, 8L * DD);
    cvt1(Wv, OFF_WV, 8L * DD);
    embed_ln<<<BT, 256>>>(idx, ts, tok, pos, gpos, ln1w, ln1b, x, pa);

    bool cvted = false;

    for (int l = 0; l < Ll; l++) {
        if (l > 0)
            layernorm_f16<<<BT / 2, 256>>>(x, ln1w + (long)l * Dm, ln1b + (long)l * Dm, pa);

        gemm_hmma<EPI_QKV><<<gQKV, 256, GEMM_SMEM>>>(
            pa, wh + OFF_WQ + (long)l * DD,
            8L * DD,
            bq + (long)l * Dm, bk + (long)l * Dm, bv + (long)l * Dm,
            nullptr, nullptr, qkvh, BT, 3 * Dm, Dm);

        attn_hmma<<<dim3(Tq / 128, Hh, Bq), 256, ATT_SMEM>>>(qb, kb, vb, pa);

        if (!cvted) cvt1(Wo, OFF_WO, 8L * DD);

        gemm_hmma<EPI_ADD><<<gD, 256, GEMM_SMEM>>>(
            pa, wh + OFF_WO + (long)l * DD, 0,
            bo + (long)l * Dm, nullptr, nullptr, x, x, nullptr, BT, Dm, Dm);

        layernorm_f16<<<BT / 2, 256>>>(x, ln2w + (long)l * Dm, ln2b + (long)l * Dm, pa);

        if (!cvted) cvt1(W1, OFF_W1, 16L * DD);

        gemm_hmma<EPI_GELU><<<g2D, 256, GEMM_SMEM>>>(
            pa, wh + OFF_W1 + (long)l * 2 * DD, 0,
            b1 + (long)l * 2 * Dm, nullptr, nullptr, nullptr,
            nullptr, pb, BT, 2 * Dm, Dm);

        if (!cvted) { cvt1(W2, OFF_W2, 16L * DD); cvted = true; }

        gemm_hmma<EPI_ADD><<<gD, 256, GEMM_SMEM>>>(
            pb, wh + OFF_W2 + (long)l * 2 * DD, 0,
            b2 + (long)l * Dm, nullptr, nullptr, x, x, nullptr, BT, Dm, 2 * Dm);
    }

    layernorm_f16<<<BT / 2, 256>>>(x, lnfw, lnfb, pa);
    cvt1(hw, OFF_HW, 8L * DD);
    gemm_hmma<EPI_NONE><<<gV, 256, GEMM_SMEM>>>(
        pa, wh + OFF_HW, 0,
        nullptr, nullptr, nullptr, nullptr, out, nullptr, BT, Vv, Dm);
}